// round 9
// baseline (speedup 1.0000x reference)
#include <cuda_runtime.h>
#include <cuda_bf16.h>
#include <math.h>
#include <stdint.h>

// ---------------- problem constants ----------------
#define NVB   6
#define VV    3
#define BB    2
#define CC    256
#define LTOK  1024
#define TKX   2048
#define NH    4
#define HD    64
#define FFNI  512
#define FFNH  2048

#define ROWS_ (NVB*LTOK)          // 6144
#define XW    (NVB*LTOK*CC/2)     // words in x hi/lo

// ---------------- device scratch ----------------
__device__ float g_x   [ROWS_*CC];
__device__ float g_qkv [ROWS_*768];           // fused Q|K|V outputs (self & cross)
__device__ float g_qp  [NVB*NH*LTOK*HD];
__device__ float g_kp  [NVB*NH*TKX*HD];
__device__ float g_vp  [NVB*NH*TKX*HD];       // TRANSPOSED: [n][h][HD][Tk]
__device__ float g_O   [NVB*NH*LTOK*HD];
__device__ float g_msg [ROWS_*CC];
__device__ float g_h2  [ROWS_*CC];
__device__ float g_Mq  [NVB*LTOK*16];
__device__ float g_Mqi [NVB*LTOK*16];
__device__ float g_Mkv [NVB*TKX*16];

// packed bf16 hi/lo operand buffers
__device__ uint32_t g_xh   [XW],  g_xl   [XW];
__device__ uint32_t g_xpreh[XW],  g_xprel[XW];
__device__ uint32_t g_omh  [XW],  g_oml  [XW];
__device__ uint32_t g_cath [ROWS_*FFNI/2], g_catl[ROWS_*FFNI/2];
__device__ uint32_t g_hh   [ROWS_*FFNH/2], g_hl  [ROWS_*FFNH/2];
// weights (words): qkv blocks [4 x 98304: selfL0,crossL0,selfL1,crossL1] | wm 4x32768 | w1 | w2
#define WQKV0 0
#define WMO   393216
#define W1O   524288
#define W2O   1572864
#define WTOT  2097152
__device__ uint32_t g_wh[WTOT], g_wl[WTOT];

// ---------------- helpers ----------------
__device__ __forceinline__ void cvt_hl(float x, float y, uint32_t& hi, uint32_t& lo) {
    __nv_bfloat162 h = __floats2bfloat162_rn(x, y);
    float rx = x - __bfloat162float(h.x);
    float ry = y - __bfloat162float(h.y);
    __nv_bfloat162 l = __floats2bfloat162_rn(rx, ry);
    hi = *reinterpret_cast<uint32_t*>(&h);
    lo = *reinterpret_cast<uint32_t*>(&l);
}

__device__ __forceinline__ void mma_bf16(float* c, const uint32_t* a, const uint32_t* b) {
    asm volatile(
        "mma.sync.aligned.m16n8k16.row.col.f32.bf16.bf16.f32 "
        "{%0,%1,%2,%3}, {%4,%5,%6,%7}, {%8,%9}, {%0,%1,%2,%3};"
        : "+f"(c[0]), "+f"(c[1]), "+f"(c[2]), "+f"(c[3])
        : "r"(a[0]), "r"(a[1]), "r"(a[2]), "r"(a[3]), "r"(b[0]), "r"(b[1]));
}

__device__ __forceinline__ void ldsm4(uint32_t* r, uint32_t addr) {
    asm volatile("ldmatrix.sync.aligned.m8n8.x4.shared.b16 {%0,%1,%2,%3}, [%4];"
        : "=r"(r[0]), "=r"(r[1]), "=r"(r[2]), "=r"(r[3]) : "r"(addr));
}

__device__ __forceinline__ uint32_t smem_u32(const void* p) {
    uint32_t a;
    asm("{ .reg .u64 t; cvta.to.shared.u64 t, %1; cvt.u32.u64 %0, t; }" : "=r"(a) : "l"(p));
    return a;
}

__device__ __forceinline__ void cp16(uint32_t smem, const void* g) {
    asm volatile("cp.async.cg.shared.global [%0], [%1], 16;" :: "r"(smem), "l"(g));
}
#define CP_COMMIT() asm volatile("cp.async.commit_group;")
#define CP_WAIT(N)  asm volatile("cp.async.wait_group %0;" :: "n"(N))

// ---------------- all-weight conversion + QKV repack, ONE launch ----------------
__global__ void k_cvt_all(const float* __restrict__ Wq, const float* __restrict__ Wk,
                          const float* __restrict__ Wv, const float* __restrict__ Wm,
                          const float* __restrict__ W1, const float* __restrict__ W2,
                          uint32_t* __restrict__ wh, uint32_t* __restrict__ wl) {
    int i = blockIdx.x * blockDim.x + threadIdx.x;
    if (i >= WTOT) return;
    const float* src;
    if (i < WMO) {
        int lyp  = i / 98304;            // (ly*2+half) block index
        int sub  = i % 98304;
        int which = sub / 32768;         // 0=q 1=k 2=v
        int woff  = sub % 32768;
        const float* base = (which == 0) ? Wq : (which == 1) ? Wk : Wv;
        src = base + (size_t)lyp * 65536 + (size_t)woff * 2;
    } else if (i < W1O) {
        src = Wm + (size_t)(i - WMO) * 2;
    } else if (i < W2O) {
        src = W1 + (size_t)(i - W1O) * 2;
    } else {
        src = W2 + (size_t)(i - W2O) * 2;
    }
    float2 v = *reinterpret_cast<const float2*>(src);
    uint32_t h, l;
    cvt_hl(v.x, v.y, h, l);
    wh[i] = h; wl[i] = l;
}

// ---------------- float -> bf16 hi/lo conversion ----------------
__global__ void k_cvt(const float* __restrict__ src, uint32_t* __restrict__ hi,
                      uint32_t* __restrict__ lo, int nw) {
    int i = blockIdx.x * blockDim.x + threadIdx.x;
    if (i >= nw) return;
    float2 v = reinterpret_cast<const float2*>(src)[i];
    uint32_t h, l;
    cvt_hl(v.x, v.y, h, l);
    hi[i] = h; lo[i] = l;
}

// ---------------- tensor-core bf16x3 GEMM v4 (BK=32, 3-stage cp.async) ----------
// C = act(A @ B^T). Per-block A select: n0 >= nsplit uses A2 (for fused cross QKV).
// A/B hi/lo [rows, K/2 words]. M%128==0, N%128==0, K%32==0. 256 thr, warp 64x32.
template<int OUT>
__global__ __launch_bounds__(256)
void tc_gemm4(const uint32_t* __restrict__ Ah, const uint32_t* __restrict__ Al,
              const uint32_t* __restrict__ A2h, const uint32_t* __restrict__ A2l,
              int nsplit,
              const uint32_t* __restrict__ Bh, const uint32_t* __restrict__ Bl,
              float* __restrict__ C, uint32_t* __restrict__ Oh, uint32_t* __restrict__ Ol,
              int M, int N, int K)
{
    extern __shared__ uint32_t smem[];
    const uint32_t sb0 = smem_u32(smem);

    const int m0 = blockIdx.y * 128;
    const int n0 = blockIdx.x * 128;
    const int tid = threadIdx.x;
    const int wid = tid >> 5, lane = tid & 31;
    const int g = lane >> 2, tg = lane & 3;
    const int warp_m = wid >> 2, warp_n = wid & 3;
    const int wm0 = warp_m * 64, wn0 = warp_n * 32;
    const int K2 = K >> 1;

    const int rowa = tid >> 1, hw = (tid & 1) * 4;

    const int a_lrow = lane & 15;
    const int a_lcol = (lane >> 4) * 4;
    const int b_lrow = (lane & 7) + ((lane >> 4) << 3);
    const int b_lcol = ((lane >> 3) & 1) * 4;

    float acc[4][4][4];
    #pragma unroll
    for (int i = 0; i < 4; i++)
        #pragma unroll
        for (int j = 0; j < 4; j++)
            #pragma unroll
            for (int r = 0; r < 4; r++) acc[i][j][r] = 0.f;

    const bool useA2 = (n0 >= nsplit);
    const uint32_t* Ab  = (useA2 ? A2h : Ah) + (size_t)(m0 + rowa) * K2 + hw;
    const uint32_t* Alb = (useA2 ? A2l : Al) + (size_t)(m0 + rowa) * K2 + hw;
    const uint32_t* Bb  = Bh + (size_t)(n0 + rowa) * K2 + hw;
    const uint32_t* Blb = Bl + (size_t)(n0 + rowa) * K2 + hw;

    const uint32_t dst_off = (uint32_t)(rowa * 12 + hw) * 4;
    const int nk2 = K >> 5;   // BK=32 tiles (>= 8 for all our shapes)

    // stage = 49152 B = 2 sub-tiles x 24576 (ash 0 | asl 6144 | bsh 12288 | bsl 18432)
    #define ISSUE(tile, stage) do {                                         \
        _Pragma("unroll")                                                   \
        for (int t = 0; t < 2; t++) {                                       \
            uint32_t sb = sb0 + (stage) * 49152u + t * 24576u + dst_off;    \
            int ko = (tile) * 16 + t * 8;                                   \
            cp16(sb,         Ab + ko);                                      \
            cp16(sb + 6144,  Alb + ko);                                     \
            cp16(sb + 12288, Bb + ko);                                      \
            cp16(sb + 18432, Blb + ko);                                     \
        }                                                                   \
    } while (0)

    ISSUE(0, 0); CP_COMMIT();
    ISSUE(1, 1); CP_COMMIT();

    int st = 0, sti = 2;
    for (int kt2 = 0; kt2 < nk2; kt2++) {
        if (kt2 + 2 < nk2) ISSUE(kt2 + 2, sti);
        CP_COMMIT();
        CP_WAIT(2);
        __syncthreads();

        #pragma unroll
        for (int t = 0; t < 2; t++) {
            const uint32_t sb = sb0 + st * 49152u + t * 24576u;
            uint32_t ah[4][4], al[4][4], bh2[4][2], bl2[4][2];
            #pragma unroll
            for (int mi = 0; mi < 4; mi++) {
                uint32_t woff = (uint32_t)((wm0 + mi*16 + a_lrow) * 12 + a_lcol) * 4;
                ldsm4(ah[mi], sb + woff);
                ldsm4(al[mi], sb + 6144 + woff);
            }
            #pragma unroll
            for (int p = 0; p < 2; p++) {
                uint32_t woff = (uint32_t)((wn0 + p*16 + b_lrow) * 12 + b_lcol) * 4;
                uint32_t r[4];
                ldsm4(r, sb + 12288 + woff);
                bh2[2*p][0] = r[0]; bh2[2*p][1] = r[1];
                bh2[2*p+1][0] = r[2]; bh2[2*p+1][1] = r[3];
                ldsm4(r, sb + 18432 + woff);
                bl2[2*p][0] = r[0]; bl2[2*p][1] = r[1];
                bl2[2*p+1][0] = r[2]; bl2[2*p+1][1] = r[3];
            }
            #pragma unroll
            for (int mi = 0; mi < 4; mi++)
                #pragma unroll
                for (int ni = 0; ni < 4; ni++) {
                    mma_bf16(acc[mi][ni], ah[mi], bh2[ni]);
                    mma_bf16(acc[mi][ni], ah[mi], bl2[ni]);
                    mma_bf16(acc[mi][ni], al[mi], bh2[ni]);
                }
        }
        __syncthreads();
        st  = (st  == 2) ? 0 : st + 1;
        sti = (sti == 2) ? 0 : sti + 1;
    }
    #undef ISSUE

    #pragma unroll
    for (int mi = 0; mi < 4; mi++) {
        #pragma unroll
        for (int ni = 0; ni < 4; ni++) {
            long long row0 = m0 + wm0 + mi * 16 + g;
            int col = n0 + wn0 + ni * 8 + tg * 2;
            if (OUT == 0) {
                *reinterpret_cast<float2*>(&C[row0 * N + col]) =
                    make_float2(acc[mi][ni][0], acc[mi][ni][1]);
                *reinterpret_cast<float2*>(&C[(row0 + 8) * N + col]) =
                    make_float2(acc[mi][ni][2], acc[mi][ni][3]);
            } else {
                float r[4];
                #pragma unroll
                for (int t = 0; t < 4; t++) {
                    float v = acc[mi][ni][t];
                    r[t] = 0.5f * v * (1.0f + erff(v * 0.70710678118654752f));
                }
                uint32_t h0, l0, h1, l1;
                cvt_hl(r[0], r[1], h0, l0);
                cvt_hl(r[2], r[3], h1, l1);
                size_t w0 = (size_t)(row0 * N + col) >> 1;
                size_t w1 = (size_t)((row0 + 8) * N + col) >> 1;
                Oh[w0] = h0; Ol[w0] = l0;
                Oh[w1] = h1; Ol[w1] = l1;
            }
        }
    }
}

// ---------------- fused flash attention (bf16x3, online softmax, prefetch) ----
#define FA_SK 36
__global__ __launch_bounds__(256)
void k_flash(const float* __restrict__ qp, const float* __restrict__ kp,
             const float* __restrict__ vpT, float* __restrict__ Og, int Tk)
{
    __shared__ uint32_t khw[64*FA_SK], klw[64*FA_SK];
    __shared__ uint32_t vhw[64*FA_SK], vlw[64*FA_SK];

    const int nh = blockIdx.y;
    const int q0 = blockIdx.x * 128;
    const int tid = threadIdx.x, wid = tid >> 5, lane = tid & 31;
    const int g = lane >> 2, tg = lane & 3;

    const float* Qb = qp + ((size_t)nh * LTOK + q0) * HD;
    const float* Kb = kp + (size_t)nh * Tk * HD;
    const float* Vb = vpT + (size_t)nh * HD * Tk;

    const int row0 = wid * 16 + g;
    uint32_t qh[4][4], ql[4][4];
    #pragma unroll
    for (int kk = 0; kk < 4; kk++) {
        int col = kk * 16 + tg * 2;
        float2 q00 = *reinterpret_cast<const float2*>(&Qb[(size_t)row0 * HD + col]);
        float2 q01 = *reinterpret_cast<const float2*>(&Qb[(size_t)row0 * HD + col + 8]);
        float2 q10 = *reinterpret_cast<const float2*>(&Qb[(size_t)(row0 + 8) * HD + col]);
        float2 q11 = *reinterpret_cast<const float2*>(&Qb[(size_t)(row0 + 8) * HD + col + 8]);
        cvt_hl(q00.x * 0.125f, q00.y * 0.125f, qh[kk][0], ql[kk][0]);
        cvt_hl(q10.x * 0.125f, q10.y * 0.125f, qh[kk][1], ql[kk][1]);
        cvt_hl(q01.x * 0.125f, q01.y * 0.125f, qh[kk][2], ql[kk][2]);
        cvt_hl(q11.x * 0.125f, q11.y * 0.125f, qh[kk][3], ql[kk][3]);
    }

    float m0 = -1e30f, m1 = -1e30f, l0 = 0.f, l1 = 0.f;
    float oacc[8][4];
    #pragma unroll
    for (int i = 0; i < 8; i++)
        #pragma unroll
        for (int t = 0; t < 4; t++) oacc[i][t] = 0.f;

    const int r = tid >> 2, c = (tid & 3) * 16;
    float4 rk[4], rv[4];
    {
        const float* sk = Kb + (size_t)r * HD + c;
        const float* sv = Vb + (size_t)r * Tk + c;
        #pragma unroll
        for (int j = 0; j < 4; j++) {
            rk[j] = *reinterpret_cast<const float4*>(sk + j * 4);
            rv[j] = *reinterpret_cast<const float4*>(sv + j * 4);
        }
    }

    for (int kv0 = 0; kv0 < Tk; kv0 += 64) {
        #pragma unroll
        for (int j = 0; j < 4; j++) {
            int w = r * FA_SK + (c >> 1) + j * 2;
            uint32_t h, l;
            cvt_hl(rk[j].x, rk[j].y, h, l); khw[w] = h;   klw[w] = l;
            cvt_hl(rk[j].z, rk[j].w, h, l); khw[w+1] = h; klw[w+1] = l;
            cvt_hl(rv[j].x, rv[j].y, h, l); vhw[w] = h;   vlw[w] = l;
            cvt_hl(rv[j].z, rv[j].w, h, l); vhw[w+1] = h; vlw[w+1] = l;
        }
        __syncthreads();

        if (kv0 + 64 < Tk) {
            const float* sk = Kb + (size_t)(kv0 + 64 + r) * HD + c;
            const float* sv = Vb + (size_t)r * Tk + (kv0 + 64) + c;
            #pragma unroll
            for (int j = 0; j < 4; j++) {
                rk[j] = *reinterpret_cast<const float4*>(sk + j * 4);
                rv[j] = *reinterpret_cast<const float4*>(sv + j * 4);
            }
        }

        float sacc[8][4];
        #pragma unroll
        for (int i = 0; i < 8; i++)
            #pragma unroll
            for (int t = 0; t < 4; t++) sacc[i][t] = 0.f;
        #pragma unroll
        for (int kk = 0; kk < 4; kk++) {
            #pragma unroll
            for (int ni = 0; ni < 8; ni++) {
                uint32_t bh[2], bl[2];
                int off = (ni * 8 + g) * FA_SK + kk * 8 + tg;
                bh[0] = khw[off]; bh[1] = khw[off + 4];
                bl[0] = klw[off]; bl[1] = klw[off + 4];
                mma_bf16(sacc[ni], qh[kk], bh);
                mma_bf16(sacc[ni], qh[kk], bl);
                mma_bf16(sacc[ni], ql[kk], bh);
            }
        }

        float mx0 = -1e30f, mx1 = -1e30f;
        #pragma unroll
        for (int ni = 0; ni < 8; ni++) {
            mx0 = fmaxf(mx0, fmaxf(sacc[ni][0], sacc[ni][1]));
            mx1 = fmaxf(mx1, fmaxf(sacc[ni][2], sacc[ni][3]));
        }
        mx0 = fmaxf(mx0, __shfl_xor_sync(0xffffffff, mx0, 1));
        mx0 = fmaxf(mx0, __shfl_xor_sync(0xffffffff, mx0, 2));
        mx1 = fmaxf(mx1, __shfl_xor_sync(0xffffffff, mx1, 1));
        mx1 = fmaxf(mx1, __shfl_xor_sync(0xffffffff, mx1, 2));
        float nm0 = fmaxf(m0, mx0), nm1 = fmaxf(m1, mx1);
        float al0 = __expf(m0 - nm0), al1 = __expf(m1 - nm1);
        float rs0 = 0.f, rs1 = 0.f;
        #pragma unroll
        for (int ni = 0; ni < 8; ni++) {
            sacc[ni][0] = __expf(sacc[ni][0] - nm0);
            sacc[ni][1] = __expf(sacc[ni][1] - nm0);
            sacc[ni][2] = __expf(sacc[ni][2] - nm1);
            sacc[ni][3] = __expf(sacc[ni][3] - nm1);
            rs0 += sacc[ni][0] + sacc[ni][1];
            rs1 += sacc[ni][2] + sacc[ni][3];
        }
        rs0 += __shfl_xor_sync(0xffffffff, rs0, 1);
        rs0 += __shfl_xor_sync(0xffffffff, rs0, 2);
        rs1 += __shfl_xor_sync(0xffffffff, rs1, 1);
        rs1 += __shfl_xor_sync(0xffffffff, rs1, 2);
        l0 = l0 * al0 + rs0;  l1 = l1 * al1 + rs1;
        m0 = nm0;  m1 = nm1;
        #pragma unroll
        for (int nd = 0; nd < 8; nd++) {
            oacc[nd][0] *= al0; oacc[nd][1] *= al0;
            oacc[nd][2] *= al1; oacc[nd][3] *= al1;
        }

        #pragma unroll
        for (int kk = 0; kk < 4; kk++) {
            uint32_t ph[4], pl[4];
            cvt_hl(sacc[2*kk][0],   sacc[2*kk][1],   ph[0], pl[0]);
            cvt_hl(sacc[2*kk][2],   sacc[2*kk][3],   ph[1], pl[1]);
            cvt_hl(sacc[2*kk+1][0], sacc[2*kk+1][1], ph[2], pl[2]);
            cvt_hl(sacc[2*kk+1][2], sacc[2*kk+1][3], ph[3], pl[3]);
            #pragma unroll
            for (int nd = 0; nd < 8; nd++) {
                uint32_t vh[2], vl[2];
                int off = (nd * 8 + g) * FA_SK + kk * 8 + tg;
                vh[0] = vhw[off]; vh[1] = vhw[off + 4];
                vl[0] = vlw[off]; vl[1] = vlw[off + 4];
                mma_bf16(oacc[nd], ph, vh);
                mma_bf16(oacc[nd], ph, vl);
                mma_bf16(oacc[nd], pl, vh);
            }
        }
        __syncthreads();
    }

    float il0 = 1.0f / l0, il1 = 1.0f / l1;
    float* Ob = Og + ((size_t)nh * LTOK + q0) * HD;
    #pragma unroll
    for (int nd = 0; nd < 8; nd++) {
        int col = nd * 8 + tg * 2;
        *reinterpret_cast<float2*>(&Ob[(size_t)row0 * HD + col]) =
            make_float2(oacc[nd][0] * il0, oacc[nd][1] * il0);
        *reinterpret_cast<float2*>(&Ob[(size_t)(row0 + 8) * HD + col]) =
            make_float2(oacc[nd][2] * il1, oacc[nd][3] * il1);
    }
}

// ---------------- layout kernels ----------------
__global__ void k_build_x(const float* __restrict__ f, float* __restrict__ x,
                          uint32_t* __restrict__ xh, uint32_t* __restrict__ xl) {
    int idx = blockIdx.x * blockDim.x + threadIdx.x;
    if (idx >= XW) return;
    int c2 = idx & 127;
    int l  = (idx >> 7) & (LTOK-1);
    int n  = idx >> 17;
    int c  = c2 * 2;
    float a = f[((size_t)n*CC + c)*LTOK + l];
    float b = f[((size_t)n*CC + c + 1)*LTOK + l];
    reinterpret_cast<float2*>(x)[idx] = make_float2(a, b);
    uint32_t h, lw;
    cvt_hl(a, b, h, lw);
    xh[idx] = h; xl[idx] = lw;
}

__global__ void k_final(const float* __restrict__ x, float* __restrict__ o) {
    int idx = blockIdx.x * blockDim.x + threadIdx.x;
    if (idx >= ROWS_*CC) return;
    int l = idx & (LTOK-1);
    int c = (idx >> 10) & (CC-1);
    int n = idx >> 18;
    o[idx] = x[((size_t)n*LTOK + l)*CC + c];
}

// ---------------- PRoPE matrix build ----------------
__device__ __forceinline__ void prope_forward(const float* vm, const float* Kc,
                                              float u, float vyy, float* M) {
    float fx = Kc[0] * (1.0f/128.0f), fy = Kc[4] * (1.0f/128.0f);
    float cx = Kc[2] * (1.0f/128.0f), cy = Kc[5] * (1.0f/128.0f);
    float a = cx - u, b = cy - vyy;
    #pragma unroll
    for (int c = 0; c < 4; c++) {
        M[0*4+c] = fx*vm[0*4+c] + a*vm[2*4+c];
        M[1*4+c] = fy*vm[1*4+c] + b*vm[2*4+c];
        M[2*4+c] = vm[2*4+c];
        M[3*4+c] = vm[3*4+c];
    }
}

__global__ void k_prope_q(const float* __restrict__ vms, const float* __restrict__ Ks,
                          float* __restrict__ Mq, float* __restrict__ Mqi) {
    int idx = blockIdx.x * blockDim.x + threadIdx.x;
    if (idx >= NVB*LTOK) return;
    int n = idx >> 10, t = idx & (LTOK-1);
    int px = t & 31, py = t >> 5;
    float u  = (px + 0.5f) * (1.0f/32.0f);
    float vy = (py + 0.5f) * (1.0f/32.0f);
    const float* vm = vms + n*16;
    const float* Kc = Ks + n*9;
    float M[16];
    prope_forward(vm, Kc, u, vy, M);
    #pragma unroll
    for (int i = 0; i < 16; i++) Mq[idx*16+i] = M[i];

    float r00=vm[0],r01=vm[1],r02=vm[2],  t0=vm[3];
    float r10=vm[4],r11=vm[5],r12=vm[6],  t1=vm[7];
    float r20=vm[8],r21=vm[9],r22=vm[10], t2=vm[11];
    float det = r00*(r11*r22-r12*r21) - r01*(r10*r22-r12*r20) + r02*(r10*r21-r11*r20);
    float id = 1.0f/det;
    float Ri[9];
    Ri[0]=(r11*r22-r12*r21)*id; Ri[1]=(r02*r21-r01*r22)*id; Ri[2]=(r01*r12-r02*r11)*id;
    Ri[3]=(r12*r20-r10*r22)*id; Ri[4]=(r00*r22-r02*r20)*id; Ri[5]=(r02*r10-r00*r12)*id;
    Ri[6]=(r10*r21-r11*r20)*id; Ri[7]=(r01*r20-r00*r21)*id; Ri[8]=(r00*r11-r01*r10)*id;
    float ti0 = -(Ri[0]*t0 + Ri[1]*t1 + Ri[2]*t2);
    float ti1 = -(Ri[3]*t0 + Ri[4]*t1 + Ri[5]*t2);
    float ti2 = -(Ri[6]*t0 + Ri[7]*t1 + Ri[8]*t2);
    float fx = Kc[0]*(1.0f/128.0f), fy = Kc[4]*(1.0f/128.0f);
    float cx = Kc[2]*(1.0f/128.0f), cy = Kc[5]*(1.0f/128.0f);
    float a = cx - u, b = cy - vy;
    float ifx = 1.0f/fx, ify = 1.0f/fy;
    float Mi[16];
    float tv[3] = {ti0, ti1, ti2};
    #pragma unroll
    for (int i = 0; i < 3; i++) {
        Mi[i*4+0] = Ri[i*3+0]*ifx;
        Mi[i*4+1] = Ri[i*3+1]*ify;
        Mi[i*4+2] = -Ri[i*3+0]*a*ifx - Ri[i*3+1]*b*ify + Ri[i*3+2];
        Mi[i*4+3] = tv[i];
    }
    Mi[12]=0.f; Mi[13]=0.f; Mi[14]=0.f; Mi[15]=1.f;
    #pragma unroll
    for (int i = 0; i < 16; i++) Mqi[idx*16+i] = Mi[i];
}

__global__ void k_prope_kv(const float* __restrict__ vms, const float* __restrict__ Ks,
                           float* __restrict__ Mkv) {
    int idx = blockIdx.x * blockDim.x + threadIdx.x;
    if (idx >= NVB*TKX) return;
    int n = idx >> 11, tt = idx & (TKX-1);
    int m = tt >> 10, l = tt & (LTOK-1);
    int vvi = n >> 1, b = n & 1;
    int j = m + (m >= vvi ? 1 : 0);
    int cam = j*BB + b;
    int px = l & 31, py = l >> 5;
    float u  = (px + 0.5f)*(1.0f/32.0f);
    float vy = (py + 0.5f)*(1.0f/32.0f);
    float M[16];
    prope_forward(vms + cam*16, Ks + cam*9, u, vy, M);
    #pragma unroll
    for (int i = 0; i < 16; i++) Mkv[idx*16+i] = M[i];
}

// ---------------- per-token 4x4 projective applies (strided sources) ---------
__global__ void k_apply_q(const float* __restrict__ q, int stride,
                          const float* __restrict__ Mi, float* __restrict__ qp) {
    int idx = blockIdx.x * blockDim.x + threadIdx.x;
    if (idx >= NVB*LTOK*NH*16) return;
    int g = idx & 15, h = (idx >> 4) & 3, t = (idx >> 6) & (LTOK-1), n = idx >> 16;
    const float* M = Mi + ((size_t)(n*LTOK + t))*16;
    const float* s = q + ((size_t)(n*LTOK + t))*stride + h*HD + g*4;
    float x0=s[0], x1=s[1], x2=s[2], x3=s[3];
    float* d = qp + (((size_t)(n*NH + h))*LTOK + t)*HD + g*4;
    #pragma unroll
    for (int i = 0; i < 4; i++)
        d[i] = M[0*4+i]*x0 + M[1*4+i]*x1 + M[2*4+i]*x2 + M[3*4+i]*x3;
}

__global__ void k_apply_kv(const float* __restrict__ ks, int stride,
                           const float* __restrict__ Mats,
                           float* __restrict__ kp, int Tk, int gather) {
    int idx = blockIdx.x * blockDim.x + threadIdx.x;
    if (idx >= NVB*Tk*NH*16) return;
    int g = idx & 15, h = (idx >> 4) & 3;
    int tt = (idx >> 6) % Tk, n = (idx >> 6) / Tk;
    size_t srcRow;
    if (gather) {
        int m = tt >> 10, l = tt & (LTOK-1);
        int vvi = n >> 1, b = n & 1;
        int j = m + (m >= vvi ? 1 : 0);
        srcRow = (size_t)(j*BB + b)*LTOK + l;
    } else {
        srcRow = (size_t)n*LTOK + tt;
    }
    const float* M = Mats + ((size_t)n*Tk + tt)*16;
    const float* s = ks + srcRow*stride + h*HD + g*4;
    float x0=s[0], x1=s[1], x2=s[2], x3=s[3];
    float* d = kp + (((size_t)(n*NH + h))*Tk + tt)*HD + g*4;
    #pragma unroll
    for (int i = 0; i < 4; i++)
        d[i] = M[i*4+0]*x0 + M[i*4+1]*x1 + M[i*4+2]*x2 + M[i*4+3]*x3;
}

__global__ void k_apply_v_t(const float* __restrict__ vs, int stride,
                            const float* __restrict__ Mats,
                            float* __restrict__ vpT, int Tk, int gather) {
    int idx = blockIdx.x * blockDim.x + threadIdx.x;
    if (idx >= NVB*NH*16*Tk) return;
    int tt = idx % Tk;
    int rest = idx / Tk;
    int g = rest & 15, h = (rest >> 4) & 3, n = rest >> 6;
    size_t srcRow;
    if (gather) {
        int m = tt >> 10, l = tt & (LTOK-1);
        int vvi = n >> 1, b = n & 1;
        int j = m + (m >= vvi ? 1 : 0);
        srcRow = (size_t)(j*BB + b)*LTOK + l;
    } else {
        srcRow = (size_t)n*LTOK + tt;
    }
    const float* M = Mats + ((size_t)n*Tk + tt)*16;
    const float* s = vs + srcRow*stride + h*HD + g*4;
    float x0=s[0], x1=s[1], x2=s[2], x3=s[3];
    float* dbase = vpT + ((size_t)(n*NH + h)*HD + g*4)*Tk + tt;
    #pragma unroll
    for (int i = 0; i < 4; i++)
        dbase[(size_t)i*Tk] = M[i*4+0]*x0 + M[i*4+1]*x1 + M[i*4+2]*x2 + M[i*4+3]*x3;
}

__global__ void k_apply_out(const float* __restrict__ O, const float* __restrict__ Mi,
                            uint32_t* __restrict__ omh, uint32_t* __restrict__ oml) {
    int idx = blockIdx.x * blockDim.x + threadIdx.x;
    if (idx >= NVB*LTOK*NH*16) return;
    int g = idx & 15, h = (idx >> 4) & 3, t = (idx >> 6) & (LTOK-1), n = idx >> 16;
    const float* M = Mi + ((size_t)(n*LTOK + t))*16;
    const float* s = O + (((size_t)(n*NH + h))*LTOK + t)*HD + g*4;
    float x0=s[0], x1=s[1], x2=s[2], x3=s[3];
    float d[4];
    #pragma unroll
    for (int i = 0; i < 4; i++)
        d[i] = M[i*4+0]*x0 + M[i*4+1]*x1 + M[i*4+2]*x2 + M[i*4+3]*x3;
    size_t w = (((size_t)(n*LTOK + t))*CC + h*HD + g*4) >> 1;
    uint32_t h0, l0, h1, l1;
    cvt_hl(d[0], d[1], h0, l0);
    cvt_hl(d[2], d[3], h1, l1);
    omh[w] = h0;   oml[w] = l0;
    omh[w+1] = h1; oml[w+1] = l1;
}

// ---------------- layernorm ----------------
__global__ void k_ln(float* __restrict__ dst, const float* __restrict__ src,
                     const float* __restrict__ w, const float* __restrict__ b, int add,
                     uint32_t* __restrict__ oh, uint32_t* __restrict__ ol) {
    __shared__ float red[256];
    int row = blockIdx.x, tid = threadIdx.x;
    float v = src[(size_t)row*CC + tid];
    red[tid] = v; __syncthreads();
    for (int s = 128; s > 0; s >>= 1) { if (tid < s) red[tid] += red[tid+s]; __syncthreads(); }
    float mu = red[0] * (1.0f/CC); __syncthreads();
    float d = v - mu;
    red[tid] = d * d; __syncthreads();
    for (int s = 128; s > 0; s >>= 1) { if (tid < s) red[tid] += red[tid+s]; __syncthreads(); }
    float var = red[0] * (1.0f/CC);
    float o = d * rsqrtf(var + 1e-5f) * w[tid] + b[tid];
    float fin;
    if (add) { fin = dst[(size_t)row*CC + tid] + o; dst[(size_t)row*CC + tid] = fin; }
    else     { fin = o; dst[(size_t)row*CC + tid] = fin; }
    if (oh) {
        __syncthreads();
        red[tid] = fin;
        __syncthreads();
        if (tid < 128) {
            uint32_t h, l;
            cvt_hl(red[2*tid], red[2*tid+1], h, l);
            oh[(size_t)row*(CC/2) + tid] = h;
            ol[(size_t)row*(CC/2) + tid] = l;
        }
    }
}

// ---------------- concat -> bf16 hi/lo ----------------
__global__ void k_cat(const float* __restrict__ x, const float* __restrict__ msg,
                      uint32_t* __restrict__ ch, uint32_t* __restrict__ cl) {
    int idx = blockIdx.x * blockDim.x + threadIdx.x;
    if (idx >= ROWS_*(FFNI/2)) return;
    int c2 = idx & 255, row = idx >> 8;
    float2 v;
    if (c2 < 128) v = reinterpret_cast<const float2*>(x + (size_t)row*CC)[c2];
    else          v = reinterpret_cast<const float2*>(msg + (size_t)row*CC)[c2 - 128];
    uint32_t h, l;
    cvt_hl(v.x, v.y, h, l);
    ch[idx] = h; cl[idx] = l;
}

// ---------------- host driver ----------------
static const int GSMEM = 147456;   // 3 stages x 49152 B

static void gemm4(const uint32_t* Ah, const uint32_t* Al,
                  const uint32_t* A2h, const uint32_t* A2l, int nsplit,
                  const uint32_t* Bh, const uint32_t* Bl,
                  float* C, int M, int N, int K) {
    dim3 g(N/128, M/128);
    tc_gemm4<0><<<g, 256, GSMEM>>>(Ah, Al, A2h, A2l, nsplit, Bh, Bl,
                                   C, nullptr, nullptr, M, N, K);
}
static void gemm4_gelu_hl(const uint32_t* Ah, const uint32_t* Al,
                          const uint32_t* Bh, const uint32_t* Bl,
                          uint32_t* Oh, uint32_t* Ol, int M, int N, int K) {
    dim3 g(N/128, M/128);
    tc_gemm4<1><<<g, 256, GSMEM>>>(Ah, Al, Ah, Al, 1<<30, Bh, Bl,
                                   nullptr, Oh, Ol, M, N, K);
}

extern "C" void kernel_launch(void* const* d_in, const int* in_sizes, int n_in,
                              void* d_out, int out_size) {
    const float* feats = (const float*)d_in[0];
    const float* vms   = (const float*)d_in[1];
    const float* Ks    = (const float*)d_in[2];
    const float* Wq    = (const float*)d_in[3];
    const float* Wk    = (const float*)d_in[4];
    const float* Wv    = (const float*)d_in[5];
    const float* Wm    = (const float*)d_in[6];
    const float* n1w   = (const float*)d_in[7];
    const float* n1b   = (const float*)d_in[8];
    const float* W1    = (const float*)d_in[9];
    const float* W2    = (const float*)d_in[10];
    const float* n2w   = (const float*)d_in[11];
    const float* n2b   = (const float*)d_in[12];

    cudaFuncSetAttribute(tc_gemm4<0>, cudaFuncAttributeMaxDynamicSharedMemorySize, GSMEM);
    cudaFuncSetAttribute(tc_gemm4<1>, cudaFuncAttributeMaxDynamicSharedMemorySize, GSMEM);

    void* p;
    float *x,*qkv,*qp,*kp,*vp,*O,*msg,*h2,*Mq,*Mqi,*Mkv;
    uint32_t *xh,*xl,*xpreh,*xprel,*omh,*oml,*cath,*catl,*hh,*hl,*wh,*wl;
    cudaGetSymbolAddress(&p, g_x);    x   = (float*)p;
    cudaGetSymbolAddress(&p, g_qkv);  qkv = (float*)p;
    cudaGetSymbolAddress(&p, g_qp);   qp  = (float*)p;
    cudaGetSymbolAddress(&p, g_kp);   kp  = (float*)p;
    cudaGetSymbolAddress(&p, g_vp);   vp  = (float*)p;
    cudaGetSymbolAddress(&p, g_O);    O   = (float*)p;
    cudaGetSymbolAddress(&p, g_msg);  msg = (float*)p;
    cudaGetSymbolAddress(&p, g_h2);   h2  = (float*)p;
    cudaGetSymbolAddress(&p, g_Mq);   Mq  = (float*)p;
    cudaGetSymbolAddress(&p, g_Mqi);  Mqi = (float*)p;
    cudaGetSymbolAddress(&p, g_Mkv);  Mkv = (float*)p;
    cudaGetSymbolAddress(&p, g_xh);    xh    = (uint32_t*)p;
    cudaGetSymbolAddress(&p, g_xl);    xl    = (uint32_t*)p;
    cudaGetSymbolAddress(&p, g_xpreh); xpreh = (uint32_t*)p;
    cudaGetSymbolAddress(&p, g_xprel); xprel = (uint32_t*)p;
    cudaGetSymbolAddress(&p, g_omh);   omh   = (uint32_t*)p;
    cudaGetSymbolAddress(&p, g_oml);   oml   = (uint32_t*)p;
    cudaGetSymbolAddress(&p, g_cath);  cath  = (uint32_t*)p;
    cudaGetSymbolAddress(&p, g_catl);  catl  = (uint32_t*)p;
    cudaGetSymbolAddress(&p, g_hh);    hh    = (uint32_t*)p;
    cudaGetSymbolAddress(&p, g_hl);    hl    = (uint32_t*)p;
    cudaGetSymbolAddress(&p, g_wh);    wh    = (uint32_t*)p;
    cudaGetSymbolAddress(&p, g_wl);    wl    = (uint32_t*)p;

    const int ROWS = ROWS_;
    const int NEL  = ROWS * CC;
    const int NAPP = NVB*LTOK*NH*16;

    // launch 1: all weights in one kernel (also makes ncu -s 5 land on the GEMM)
    k_cvt_all<<<WTOT/256, 256>>>(Wq, Wk, Wv, Wm, W1, W2, wh, wl);
    k_build_x<<<(XW+255)/256, 256>>>(feats, x, xh, xl);           // 2
    k_prope_q<<<(ROWS+255)/256, 256>>>(vms, Ks, Mq, Mqi);         // 3
    k_prope_kv<<<(NVB*TKX+255)/256, 256>>>(vms, Ks, Mkv);         // 4

    for (int ly = 0; ly < 2; ly++) {
        // snapshot x (pre-self-attn) for cross-attn KV                 5
        k_cvt<<<(XW+255)/256, 256>>>(x, xpreh, xprel, XW);

        // ---------- self attention (fused QKV, N=768) ----------      6  <- ncu lands here
        gemm4(xh, xl, xh, xl, 1<<30,
              wh + WQKV0 + (ly*2+0)*98304, wl + WQKV0 + (ly*2+0)*98304,
              qkv, ROWS, 768, CC);
        k_apply_q  <<<NAPP/256, 256>>>(qkv + 0,   768, Mqi, qp);
        k_apply_kv <<<NAPP/256, 256>>>(qkv + 256, 768, Mq, kp, LTOK, 0);
        k_apply_v_t<<<NAPP/256, 256>>>(qkv + 512, 768, Mq, vp, LTOK, 0);
        k_flash<<<dim3(LTOK/128, NVB*NH), 256>>>(qp, kp, vp, O, LTOK);
        k_apply_out<<<NAPP/256, 256>>>(O, Mqi, omh, oml);
        gemm4(omh, oml, omh, oml, 1<<30,
              wh + WMO + (ly*2+0)*32768, wl + WMO + (ly*2+0)*32768,
              msg, ROWS, CC, CC);
        k_ln<<<ROWS, 256>>>(x, msg, n1w + (ly*2+0)*CC, n1b + (ly*2+0)*CC, 1, xh, xl);

        // ---------- cross attention (fused Q|K|V, N=768, A split at 256) ----------
        gemm4(xh, xl, xpreh, xprel, 256,
              wh + WQKV0 + (ly*2+1)*98304, wl + WQKV0 + (ly*2+1)*98304,
              qkv, ROWS, 768, CC);
        k_apply_q  <<<NAPP/256, 256>>>(qkv + 0,   768, Mqi, qp);
        k_apply_kv <<<(NVB*TKX*NH*16)/256, 256>>>(qkv + 256, 768, Mkv, kp, TKX, 1);
        k_apply_v_t<<<(NVB*TKX*NH*16)/256, 256>>>(qkv + 512, 768, Mkv, vp, TKX, 1);
        k_flash<<<dim3(LTOK/128, NVB*NH), 256>>>(qp, kp, vp, O, TKX);
        k_apply_out<<<NAPP/256, 256>>>(O, Mqi, omh, oml);
        gemm4(omh, oml, omh, oml, 1<<30,
              wh + WMO + (ly*2+1)*32768, wl + WMO + (ly*2+1)*32768,
              msg, ROWS, CC, CC);
        k_ln<<<ROWS, 256>>>(msg, msg, n1w + (ly*2+1)*CC, n1b + (ly*2+1)*CC, 0,
                            nullptr, nullptr);

        // ---------- FFN ----------
        k_cat<<<(ROWS*(FFNI/2))/256, 256>>>(x, msg, cath, catl);
        gemm4_gelu_hl(cath, catl,
                      wh + W1O + (size_t)ly*524288, wl + W1O + (size_t)ly*524288,
                      hh, hl, ROWS, FFNH, FFNI);
        gemm4(hh, hl, hh, hl, 1<<30,
              wh + W2O + (size_t)ly*262144, wl + W2O + (size_t)ly*262144,
              h2, ROWS, CC, FFNH);
        k_ln<<<ROWS, 256>>>(x, h2, n2w + ly*CC, n2b + ly*CC, 1, xh, xl);
    }

    k_final<<<(NEL+255)/256, 256>>>(x, (float*)d_out);
}

// round 10
// speedup vs baseline: 1.0407x; 1.0407x over previous
#include <cuda_runtime.h>
#include <cuda_bf16.h>
#include <math.h>
#include <stdint.h>

// ---------------- problem constants ----------------
#define NVB   6
#define VV    3
#define BB    2
#define CC    256
#define LTOK  1024
#define TKX   2048
#define NH    4
#define HD    64
#define FFNI  512
#define FFNH  2048

#define ROWS_ (NVB*LTOK)          // 6144
#define XW    (NVB*LTOK*CC/2)     // words in x hi/lo

// ---------------- device scratch ----------------
__device__ float g_x   [ROWS_*CC];
__device__ float g_qkv [ROWS_*768];           // fused Q|K|V outputs (self & cross)
__device__ float g_qp  [NVB*NH*LTOK*HD];
__device__ float g_kp  [NVB*NH*TKX*HD];
__device__ float g_vp  [NVB*NH*TKX*HD];       // TRANSPOSED: [n][h][HD][Tk]
__device__ float g_O   [NVB*NH*LTOK*HD];
__device__ float g_msg [ROWS_*CC];
__device__ float g_h2  [ROWS_*CC];
__device__ float g_Mq  [NVB*LTOK*16];
__device__ float g_Mqi [NVB*LTOK*16];
__device__ float g_Mkv [NVB*TKX*16];

// packed bf16 hi/lo operand buffers
__device__ uint32_t g_xh   [XW],  g_xl   [XW];
__device__ uint32_t g_xpreh[XW],  g_xprel[XW];
__device__ uint32_t g_omh  [XW],  g_oml  [XW];
__device__ uint32_t g_cath [ROWS_*FFNI/2], g_catl[ROWS_*FFNI/2];
__device__ uint32_t g_hh   [ROWS_*FFNH/2], g_hl  [ROWS_*FFNH/2];
// weights (words): qkv blocks [4 x 98304: selfL0,crossL0,selfL1,crossL1] | wm 4x32768 | w1 | w2
#define WQKV0 0
#define WMO   393216
#define W1O   524288
#define W2O   1572864
#define WTOT  2097152
__device__ uint32_t g_wh[WTOT], g_wl[WTOT];

// ---------------- helpers ----------------
__device__ __forceinline__ void cvt_hl(float x, float y, uint32_t& hi, uint32_t& lo) {
    __nv_bfloat162 h = __floats2bfloat162_rn(x, y);
    float rx = x - __bfloat162float(h.x);
    float ry = y - __bfloat162float(h.y);
    __nv_bfloat162 l = __floats2bfloat162_rn(rx, ry);
    hi = *reinterpret_cast<uint32_t*>(&h);
    lo = *reinterpret_cast<uint32_t*>(&l);
}

__device__ __forceinline__ void mma_bf16(float* c, const uint32_t* a, const uint32_t* b) {
    asm volatile(
        "mma.sync.aligned.m16n8k16.row.col.f32.bf16.bf16.f32 "
        "{%0,%1,%2,%3}, {%4,%5,%6,%7}, {%8,%9}, {%0,%1,%2,%3};"
        : "+f"(c[0]), "+f"(c[1]), "+f"(c[2]), "+f"(c[3])
        : "r"(a[0]), "r"(a[1]), "r"(a[2]), "r"(a[3]), "r"(b[0]), "r"(b[1]));
}

__device__ __forceinline__ void ldsm4(uint32_t* r, uint32_t addr) {
    asm volatile("ldmatrix.sync.aligned.m8n8.x4.shared.b16 {%0,%1,%2,%3}, [%4];"
        : "=r"(r[0]), "=r"(r[1]), "=r"(r[2]), "=r"(r[3]) : "r"(addr));
}

__device__ __forceinline__ uint32_t smem_u32(const void* p) {
    uint32_t a;
    asm("{ .reg .u64 t; cvta.to.shared.u64 t, %1; cvt.u32.u64 %0, t; }" : "=r"(a) : "l"(p));
    return a;
}

__device__ __forceinline__ void cp16(uint32_t smem, const void* g) {
    asm volatile("cp.async.cg.shared.global [%0], [%1], 16;" :: "r"(smem), "l"(g));
}
#define CP_COMMIT() asm volatile("cp.async.commit_group;")
#define CP_WAIT(N)  asm volatile("cp.async.wait_group %0;" :: "n"(N))

// ---------------- all-weight conversion + QKV repack, ONE launch ----------------
__global__ void k_cvt_all(const float* __restrict__ Wq, const float* __restrict__ Wk,
                          const float* __restrict__ Wv, const float* __restrict__ Wm,
                          const float* __restrict__ W1, const float* __restrict__ W2,
                          uint32_t* __restrict__ wh, uint32_t* __restrict__ wl) {
    int i = blockIdx.x * blockDim.x + threadIdx.x;
    if (i >= WTOT) return;
    const float* src;
    if (i < WMO) {
        int lyp  = i / 98304;            // (ly*2+half) block index
        int sub  = i % 98304;
        int which = sub / 32768;         // 0=q 1=k 2=v
        int woff  = sub % 32768;
        const float* base = (which == 0) ? Wq : (which == 1) ? Wk : Wv;
        src = base + (size_t)lyp * 65536 + (size_t)woff * 2;
    } else if (i < W1O) {
        src = Wm + (size_t)(i - WMO) * 2;
    } else if (i < W2O) {
        src = W1 + (size_t)(i - W1O) * 2;
    } else {
        src = W2 + (size_t)(i - W2O) * 2;
    }
    float2 v = *reinterpret_cast<const float2*>(src);
    uint32_t h, l;
    cvt_hl(v.x, v.y, h, l);
    wh[i] = h; wl[i] = l;
}

// ---------------- float -> bf16 hi/lo conversion ----------------
__global__ void k_cvt(const float* __restrict__ src, uint32_t* __restrict__ hi,
                      uint32_t* __restrict__ lo, int nw) {
    int i = blockIdx.x * blockDim.x + threadIdx.x;
    if (i >= nw) return;
    float2 v = reinterpret_cast<const float2*>(src)[i];
    uint32_t h, l;
    cvt_hl(v.x, v.y, h, l);
    hi[i] = h; lo[i] = l;
}

// ---------------- tensor-core bf16x3 GEMM (R8 mainloop + A-select) ----------
// C = act(A @ B^T). Per-block A select: n0 >= nsplit uses A2 (fused cross QKV).
// A/B hi/lo [rows, K/2 words]. M%128==0, N%128==0, K%16==0.
// 256 threads, warp tile 64x32 (2x4). Dynamic smem 4 stages x 24576 B = 96 KB.
template<int OUT>
__global__ __launch_bounds__(256)
void tc_gemm(const uint32_t* __restrict__ Ah, const uint32_t* __restrict__ Al,
             const uint32_t* __restrict__ A2h, const uint32_t* __restrict__ A2l,
             int nsplit,
             const uint32_t* __restrict__ Bh, const uint32_t* __restrict__ Bl,
             float* __restrict__ C, uint32_t* __restrict__ Oh, uint32_t* __restrict__ Ol,
             int M, int N, int K)
{
    extern __shared__ uint32_t smem[];
    const uint32_t sb0 = smem_u32(smem);

    const int m0 = blockIdx.y * 128;
    const int n0 = blockIdx.x * 128;
    const int tid = threadIdx.x;
    const int wid = tid >> 5, lane = tid & 31;
    const int g = lane >> 2, tg = lane & 3;
    const int warp_m = wid >> 2, warp_n = wid & 3;
    const int wm0 = warp_m * 64, wn0 = warp_n * 32;
    const int K2 = K >> 1;

    const int rowa = tid >> 1, hw = (tid & 1) * 4;

    const int a_lrow = lane & 15;
    const int a_lcol = (lane >> 4) * 4;
    const int b_lrow = (lane & 7) + ((lane >> 4) << 3);
    const int b_lcol = ((lane >> 3) & 1) * 4;

    float acc[4][4][4];
    #pragma unroll
    for (int i = 0; i < 4; i++)
        #pragma unroll
        for (int j = 0; j < 4; j++)
            #pragma unroll
            for (int r = 0; r < 4; r++) acc[i][j][r] = 0.f;

    const bool useA2 = (n0 >= nsplit);
    const uint32_t* Ab  = (useA2 ? A2h : Ah) + (size_t)(m0 + rowa) * K2 + hw;
    const uint32_t* Alb = (useA2 ? A2l : Al) + (size_t)(m0 + rowa) * K2 + hw;
    const uint32_t* Bb  = Bh + (size_t)(n0 + rowa) * K2 + hw;
    const uint32_t* Blb = Bl + (size_t)(n0 + rowa) * K2 + hw;

    const uint32_t dst_off = (uint32_t)(rowa * 12 + hw) * 4;
    const int nk = K >> 4;

    // stage layout (bytes): ash +0, asl +6144, bsh +12288, bsl +18432; stride 24576
    #define ISSUE(tile, stage) do {                              \
        uint32_t sb = sb0 + (stage) * 24576u + dst_off;          \
        int ko = (tile) * 8;                                     \
        cp16(sb,         Ab + ko);                               \
        cp16(sb + 6144,  Alb + ko);                              \
        cp16(sb + 12288, Bb + ko);                               \
        cp16(sb + 18432, Blb + ko);                              \
    } while (0)

    #pragma unroll
    for (int s = 0; s < 3; s++) {
        if (s < nk) ISSUE(s, s);
        CP_COMMIT();
    }

    for (int kt = 0; kt < nk; kt++) {
        if (kt + 3 < nk) ISSUE(kt + 3, (kt + 3) & 3);
        CP_COMMIT();
        CP_WAIT(3);
        __syncthreads();

        const uint32_t sb = sb0 + (kt & 3) * 24576u;
        uint32_t ah[4][4], al[4][4], bh2[4][2], bl2[4][2];
        #pragma unroll
        for (int mi = 0; mi < 4; mi++) {
            uint32_t woff = (uint32_t)((wm0 + mi*16 + a_lrow) * 12 + a_lcol) * 4;
            ldsm4(ah[mi], sb + woff);
            ldsm4(al[mi], sb + 6144 + woff);
        }
        #pragma unroll
        for (int p = 0; p < 2; p++) {
            uint32_t woff = (uint32_t)((wn0 + p*16 + b_lrow) * 12 + b_lcol) * 4;
            uint32_t r[4];
            ldsm4(r, sb + 12288 + woff);
            bh2[2*p][0] = r[0]; bh2[2*p][1] = r[1];
            bh2[2*p+1][0] = r[2]; bh2[2*p+1][1] = r[3];
            ldsm4(r, sb + 18432 + woff);
            bl2[2*p][0] = r[0]; bl2[2*p][1] = r[1];
            bl2[2*p+1][0] = r[2]; bl2[2*p+1][1] = r[3];
        }
        #pragma unroll
        for (int mi = 0; mi < 4; mi++)
            #pragma unroll
            for (int ni = 0; ni < 4; ni++) {
                mma_bf16(acc[mi][ni], ah[mi], bh2[ni]);
                mma_bf16(acc[mi][ni], ah[mi], bl2[ni]);
                mma_bf16(acc[mi][ni], al[mi], bh2[ni]);
            }
        __syncthreads();
    }
    #undef ISSUE

    #pragma unroll
    for (int mi = 0; mi < 4; mi++) {
        #pragma unroll
        for (int ni = 0; ni < 4; ni++) {
            long long row0 = m0 + wm0 + mi * 16 + g;
            int col = n0 + wn0 + ni * 8 + tg * 2;
            if (OUT == 0) {
                *reinterpret_cast<float2*>(&C[row0 * N + col]) =
                    make_float2(acc[mi][ni][0], acc[mi][ni][1]);
                *reinterpret_cast<float2*>(&C[(row0 + 8) * N + col]) =
                    make_float2(acc[mi][ni][2], acc[mi][ni][3]);
            } else {
                float r[4];
                #pragma unroll
                for (int t = 0; t < 4; t++) {
                    float v = acc[mi][ni][t];
                    r[t] = 0.5f * v * (1.0f + erff(v * 0.70710678118654752f));
                }
                uint32_t h0, l0, h1, l1;
                cvt_hl(r[0], r[1], h0, l0);
                cvt_hl(r[2], r[3], h1, l1);
                size_t w0 = (size_t)(row0 * N + col) >> 1;
                size_t w1 = (size_t)((row0 + 8) * N + col) >> 1;
                Oh[w0] = h0; Ol[w0] = l0;
                Oh[w1] = h1; Ol[w1] = l1;
            }
        }
    }
}

// ---------------- fused flash attention (bf16x3, online softmax, prefetch) ----
#define FA_SK 36
__global__ __launch_bounds__(256)
void k_flash(const float* __restrict__ qp, const float* __restrict__ kp,
             const float* __restrict__ vpT, float* __restrict__ Og, int Tk)
{
    __shared__ uint32_t khw[64*FA_SK], klw[64*FA_SK];
    __shared__ uint32_t vhw[64*FA_SK], vlw[64*FA_SK];

    const int nh = blockIdx.y;
    const int q0 = blockIdx.x * 128;
    const int tid = threadIdx.x, wid = tid >> 5, lane = tid & 31;
    const int g = lane >> 2, tg = lane & 3;

    const float* Qb = qp + ((size_t)nh * LTOK + q0) * HD;
    const float* Kb = kp + (size_t)nh * Tk * HD;
    const float* Vb = vpT + (size_t)nh * HD * Tk;

    const int row0 = wid * 16 + g;
    uint32_t qh[4][4], ql[4][4];
    #pragma unroll
    for (int kk = 0; kk < 4; kk++) {
        int col = kk * 16 + tg * 2;
        float2 q00 = *reinterpret_cast<const float2*>(&Qb[(size_t)row0 * HD + col]);
        float2 q01 = *reinterpret_cast<const float2*>(&Qb[(size_t)row0 * HD + col + 8]);
        float2 q10 = *reinterpret_cast<const float2*>(&Qb[(size_t)(row0 + 8) * HD + col]);
        float2 q11 = *reinterpret_cast<const float2*>(&Qb[(size_t)(row0 + 8) * HD + col + 8]);
        cvt_hl(q00.x * 0.125f, q00.y * 0.125f, qh[kk][0], ql[kk][0]);
        cvt_hl(q10.x * 0.125f, q10.y * 0.125f, qh[kk][1], ql[kk][1]);
        cvt_hl(q01.x * 0.125f, q01.y * 0.125f, qh[kk][2], ql[kk][2]);
        cvt_hl(q11.x * 0.125f, q11.y * 0.125f, qh[kk][3], ql[kk][3]);
    }

    float m0 = -1e30f, m1 = -1e30f, l0 = 0.f, l1 = 0.f;
    float oacc[8][4];
    #pragma unroll
    for (int i = 0; i < 8; i++)
        #pragma unroll
        for (int t = 0; t < 4; t++) oacc[i][t] = 0.f;

    const int r = tid >> 2, c = (tid & 3) * 16;
    float4 rk[4], rv[4];
    {
        const float* sk = Kb + (size_t)r * HD + c;
        const float* sv = Vb + (size_t)r * Tk + c;
        #pragma unroll
        for (int j = 0; j < 4; j++) {
            rk[j] = *reinterpret_cast<const float4*>(sk + j * 4);
            rv[j] = *reinterpret_cast<const float4*>(sv + j * 4);
        }
    }

    for (int kv0 = 0; kv0 < Tk; kv0 += 64) {
        #pragma unroll
        for (int j = 0; j < 4; j++) {
            int w = r * FA_SK + (c >> 1) + j * 2;
            uint32_t h, l;
            cvt_hl(rk[j].x, rk[j].y, h, l); khw[w] = h;   klw[w] = l;
            cvt_hl(rk[j].z, rk[j].w, h, l); khw[w+1] = h; klw[w+1] = l;
            cvt_hl(rv[j].x, rv[j].y, h, l); vhw[w] = h;   vlw[w] = l;
            cvt_hl(rv[j].z, rv[j].w, h, l); vhw[w+1] = h; vlw[w+1] = l;
        }
        __syncthreads();

        if (kv0 + 64 < Tk) {
            const float* sk = Kb + (size_t)(kv0 + 64 + r) * HD + c;
            const float* sv = Vb + (size_t)r * Tk + (kv0 + 64) + c;
            #pragma unroll
            for (int j = 0; j < 4; j++) {
                rk[j] = *reinterpret_cast<const float4*>(sk + j * 4);
                rv[j] = *reinterpret_cast<const float4*>(sv + j * 4);
            }
        }

        float sacc[8][4];
        #pragma unroll
        for (int i = 0; i < 8; i++)
            #pragma unroll
            for (int t = 0; t < 4; t++) sacc[i][t] = 0.f;
        #pragma unroll
        for (int kk = 0; kk < 4; kk++) {
            #pragma unroll
            for (int ni = 0; ni < 8; ni++) {
                uint32_t bh[2], bl[2];
                int off = (ni * 8 + g) * FA_SK + kk * 8 + tg;
                bh[0] = khw[off]; bh[1] = khw[off + 4];
                bl[0] = klw[off]; bl[1] = klw[off + 4];
                mma_bf16(sacc[ni], qh[kk], bh);
                mma_bf16(sacc[ni], qh[kk], bl);
                mma_bf16(sacc[ni], ql[kk], bh);
            }
        }

        float mx0 = -1e30f, mx1 = -1e30f;
        #pragma unroll
        for (int ni = 0; ni < 8; ni++) {
            mx0 = fmaxf(mx0, fmaxf(sacc[ni][0], sacc[ni][1]));
            mx1 = fmaxf(mx1, fmaxf(sacc[ni][2], sacc[ni][3]));
        }
        mx0 = fmaxf(mx0, __shfl_xor_sync(0xffffffff, mx0, 1));
        mx0 = fmaxf(mx0, __shfl_xor_sync(0xffffffff, mx0, 2));
        mx1 = fmaxf(mx1, __shfl_xor_sync(0xffffffff, mx1, 1));
        mx1 = fmaxf(mx1, __shfl_xor_sync(0xffffffff, mx1, 2));
        float nm0 = fmaxf(m0, mx0), nm1 = fmaxf(m1, mx1);
        float al0 = __expf(m0 - nm0), al1 = __expf(m1 - nm1);
        float rs0 = 0.f, rs1 = 0.f;
        #pragma unroll
        for (int ni = 0; ni < 8; ni++) {
            sacc[ni][0] = __expf(sacc[ni][0] - nm0);
            sacc[ni][1] = __expf(sacc[ni][1] - nm0);
            sacc[ni][2] = __expf(sacc[ni][2] - nm1);
            sacc[ni][3] = __expf(sacc[ni][3] - nm1);
            rs0 += sacc[ni][0] + sacc[ni][1];
            rs1 += sacc[ni][2] + sacc[ni][3];
        }
        rs0 += __shfl_xor_sync(0xffffffff, rs0, 1);
        rs0 += __shfl_xor_sync(0xffffffff, rs0, 2);
        rs1 += __shfl_xor_sync(0xffffffff, rs1, 1);
        rs1 += __shfl_xor_sync(0xffffffff, rs1, 2);
        l0 = l0 * al0 + rs0;  l1 = l1 * al1 + rs1;
        m0 = nm0;  m1 = nm1;
        #pragma unroll
        for (int nd = 0; nd < 8; nd++) {
            oacc[nd][0] *= al0; oacc[nd][1] *= al0;
            oacc[nd][2] *= al1; oacc[nd][3] *= al1;
        }

        #pragma unroll
        for (int kk = 0; kk < 4; kk++) {
            uint32_t ph[4], pl[4];
            cvt_hl(sacc[2*kk][0],   sacc[2*kk][1],   ph[0], pl[0]);
            cvt_hl(sacc[2*kk][2],   sacc[2*kk][3],   ph[1], pl[1]);
            cvt_hl(sacc[2*kk+1][0], sacc[2*kk+1][1], ph[2], pl[2]);
            cvt_hl(sacc[2*kk+1][2], sacc[2*kk+1][3], ph[3], pl[3]);
            #pragma unroll
            for (int nd = 0; nd < 8; nd++) {
                uint32_t vh[2], vl[2];
                int off = (nd * 8 + g) * FA_SK + kk * 8 + tg;
                vh[0] = vhw[off]; vh[1] = vhw[off + 4];
                vl[0] = vlw[off]; vl[1] = vlw[off + 4];
                mma_bf16(oacc[nd], ph, vh);
                mma_bf16(oacc[nd], ph, vl);
                mma_bf16(oacc[nd], pl, vh);
            }
        }
        __syncthreads();
    }

    float il0 = 1.0f / l0, il1 = 1.0f / l1;
    float* Ob = Og + ((size_t)nh * LTOK + q0) * HD;
    #pragma unroll
    for (int nd = 0; nd < 8; nd++) {
        int col = nd * 8 + tg * 2;
        *reinterpret_cast<float2*>(&Ob[(size_t)row0 * HD + col]) =
            make_float2(oacc[nd][0] * il0, oacc[nd][1] * il0);
        *reinterpret_cast<float2*>(&Ob[(size_t)(row0 + 8) * HD + col]) =
            make_float2(oacc[nd][2] * il1, oacc[nd][3] * il1);
    }
}

// ---------------- layout kernels ----------------
__global__ void k_build_x(const float* __restrict__ f, float* __restrict__ x,
                          uint32_t* __restrict__ xh, uint32_t* __restrict__ xl) {
    int idx = blockIdx.x * blockDim.x + threadIdx.x;
    if (idx >= XW) return;
    int c2 = idx & 127;
    int l  = (idx >> 7) & (LTOK-1);
    int n  = idx >> 17;
    int c  = c2 * 2;
    float a = f[((size_t)n*CC + c)*LTOK + l];
    float b = f[((size_t)n*CC + c + 1)*LTOK + l];
    reinterpret_cast<float2*>(x)[idx] = make_float2(a, b);
    uint32_t h, lw;
    cvt_hl(a, b, h, lw);
    xh[idx] = h; xl[idx] = lw;
}

__global__ void k_final(const float* __restrict__ x, float* __restrict__ o) {
    int idx = blockIdx.x * blockDim.x + threadIdx.x;
    if (idx >= ROWS_*CC) return;
    int l = idx & (LTOK-1);
    int c = (idx >> 10) & (CC-1);
    int n = idx >> 18;
    o[idx] = x[((size_t)n*LTOK + l)*CC + c];
}

// ---------------- PRoPE matrix build ----------------
__device__ __forceinline__ void prope_forward(const float* vm, const float* Kc,
                                              float u, float vyy, float* M) {
    float fx = Kc[0] * (1.0f/128.0f), fy = Kc[4] * (1.0f/128.0f);
    float cx = Kc[2] * (1.0f/128.0f), cy = Kc[5] * (1.0f/128.0f);
    float a = cx - u, b = cy - vyy;
    #pragma unroll
    for (int c = 0; c < 4; c++) {
        M[0*4+c] = fx*vm[0*4+c] + a*vm[2*4+c];
        M[1*4+c] = fy*vm[1*4+c] + b*vm[2*4+c];
        M[2*4+c] = vm[2*4+c];
        M[3*4+c] = vm[3*4+c];
    }
}

__global__ void k_prope_q(const float* __restrict__ vms, const float* __restrict__ Ks,
                          float* __restrict__ Mq, float* __restrict__ Mqi) {
    int idx = blockIdx.x * blockDim.x + threadIdx.x;
    if (idx >= NVB*LTOK) return;
    int n = idx >> 10, t = idx & (LTOK-1);
    int px = t & 31, py = t >> 5;
    float u  = (px + 0.5f) * (1.0f/32.0f);
    float vy = (py + 0.5f) * (1.0f/32.0f);
    const float* vm = vms + n*16;
    const float* Kc = Ks + n*9;
    float M[16];
    prope_forward(vm, Kc, u, vy, M);
    #pragma unroll
    for (int i = 0; i < 16; i++) Mq[idx*16+i] = M[i];

    float r00=vm[0],r01=vm[1],r02=vm[2],  t0=vm[3];
    float r10=vm[4],r11=vm[5],r12=vm[6],  t1=vm[7];
    float r20=vm[8],r21=vm[9],r22=vm[10], t2=vm[11];
    float det = r00*(r11*r22-r12*r21) - r01*(r10*r22-r12*r20) + r02*(r10*r21-r11*r20);
    float id = 1.0f/det;
    float Ri[9];
    Ri[0]=(r11*r22-r12*r21)*id; Ri[1]=(r02*r21-r01*r22)*id; Ri[2]=(r01*r12-r02*r11)*id;
    Ri[3]=(r12*r20-r10*r22)*id; Ri[4]=(r00*r22-r02*r20)*id; Ri[5]=(r02*r10-r00*r12)*id;
    Ri[6]=(r10*r21-r11*r20)*id; Ri[7]=(r01*r20-r00*r21)*id; Ri[8]=(r00*r11-r01*r10)*id;
    float ti0 = -(Ri[0]*t0 + Ri[1]*t1 + Ri[2]*t2);
    float ti1 = -(Ri[3]*t0 + Ri[4]*t1 + Ri[5]*t2);
    float ti2 = -(Ri[6]*t0 + Ri[7]*t1 + Ri[8]*t2);
    float fx = Kc[0]*(1.0f/128.0f), fy = Kc[4]*(1.0f/128.0f);
    float cx = Kc[2]*(1.0f/128.0f), cy = Kc[5]*(1.0f/128.0f);
    float a = cx - u, b = cy - vy;
    float ifx = 1.0f/fx, ify = 1.0f/fy;
    float Mi[16];
    float tv[3] = {ti0, ti1, ti2};
    #pragma unroll
    for (int i = 0; i < 3; i++) {
        Mi[i*4+0] = Ri[i*3+0]*ifx;
        Mi[i*4+1] = Ri[i*3+1]*ify;
        Mi[i*4+2] = -Ri[i*3+0]*a*ifx - Ri[i*3+1]*b*ify + Ri[i*3+2];
        Mi[i*4+3] = tv[i];
    }
    Mi[12]=0.f; Mi[13]=0.f; Mi[14]=0.f; Mi[15]=1.f;
    #pragma unroll
    for (int i = 0; i < 16; i++) Mqi[idx*16+i] = Mi[i];
}

__global__ void k_prope_kv(const float* __restrict__ vms, const float* __restrict__ Ks,
                           float* __restrict__ Mkv) {
    int idx = blockIdx.x * blockDim.x + threadIdx.x;
    if (idx >= NVB*TKX) return;
    int n = idx >> 11, tt = idx & (TKX-1);
    int m = tt >> 10, l = tt & (LTOK-1);
    int vvi = n >> 1, b = n & 1;
    int j = m + (m >= vvi ? 1 : 0);
    int cam = j*BB + b;
    int px = l & 31, py = l >> 5;
    float u  = (px + 0.5f)*(1.0f/32.0f);
    float vy = (py + 0.5f)*(1.0f/32.0f);
    float M[16];
    prope_forward(vms + cam*16, Ks + cam*9, u, vy, M);
    #pragma unroll
    for (int i = 0; i < 16; i++) Mkv[idx*16+i] = M[i];
}

// ---------------- per-token 4x4 projective applies (strided sources) ---------
__global__ void k_apply_q(const float* __restrict__ q, int stride,
                          const float* __restrict__ Mi, float* __restrict__ qp) {
    int idx = blockIdx.x * blockDim.x + threadIdx.x;
    if (idx >= NVB*LTOK*NH*16) return;
    int g = idx & 15, h = (idx >> 4) & 3, t = (idx >> 6) & (LTOK-1), n = idx >> 16;
    const float* M = Mi + ((size_t)(n*LTOK + t))*16;
    const float* s = q + ((size_t)(n*LTOK + t))*stride + h*HD + g*4;
    float x0=s[0], x1=s[1], x2=s[2], x3=s[3];
    float* d = qp + (((size_t)(n*NH + h))*LTOK + t)*HD + g*4;
    #pragma unroll
    for (int i = 0; i < 4; i++)
        d[i] = M[0*4+i]*x0 + M[1*4+i]*x1 + M[2*4+i]*x2 + M[3*4+i]*x3;
}

__global__ void k_apply_kv(const float* __restrict__ ks, int stride,
                           const float* __restrict__ Mats,
                           float* __restrict__ kp, int Tk, int gather) {
    int idx = blockIdx.x * blockDim.x + threadIdx.x;
    if (idx >= NVB*Tk*NH*16) return;
    int g = idx & 15, h = (idx >> 4) & 3;
    int tt = (idx >> 6) % Tk, n = (idx >> 6) / Tk;
    size_t srcRow;
    if (gather) {
        int m = tt >> 10, l = tt & (LTOK-1);
        int vvi = n >> 1, b = n & 1;
        int j = m + (m >= vvi ? 1 : 0);
        srcRow = (size_t)(j*BB + b)*LTOK + l;
    } else {
        srcRow = (size_t)n*LTOK + tt;
    }
    const float* M = Mats + ((size_t)n*Tk + tt)*16;
    const float* s = ks + srcRow*stride + h*HD + g*4;
    float x0=s[0], x1=s[1], x2=s[2], x3=s[3];
    float* d = kp + (((size_t)(n*NH + h))*Tk + tt)*HD + g*4;
    #pragma unroll
    for (int i = 0; i < 4; i++)
        d[i] = M[i*4+0]*x0 + M[i*4+1]*x1 + M[i*4+2]*x2 + M[i*4+3]*x3;
}

__global__ void k_apply_v_t(const float* __restrict__ vs, int stride,
                            const float* __restrict__ Mats,
                            float* __restrict__ vpT, int Tk, int gather) {
    int idx = blockIdx.x * blockDim.x + threadIdx.x;
    if (idx >= NVB*NH*16*Tk) return;
    int tt = idx % Tk;
    int rest = idx / Tk;
    int g = rest & 15, h = (rest >> 4) & 3, n = rest >> 6;
    size_t srcRow;
    if (gather) {
        int m = tt >> 10, l = tt & (LTOK-1);
        int vvi = n >> 1, b = n & 1;
        int j = m + (m >= vvi ? 1 : 0);
        srcRow = (size_t)(j*BB + b)*LTOK + l;
    } else {
        srcRow = (size_t)n*LTOK + tt;
    }
    const float* M = Mats + ((size_t)n*Tk + tt)*16;
    const float* s = vs + srcRow*stride + h*HD + g*4;
    float x0=s[0], x1=s[1], x2=s[2], x3=s[3];
    float* dbase = vpT + ((size_t)(n*NH + h)*HD + g*4)*Tk + tt;
    #pragma unroll
    for (int i = 0; i < 4; i++)
        dbase[(size_t)i*Tk] = M[i*4+0]*x0 + M[i*4+1]*x1 + M[i*4+2]*x2 + M[i*4+3]*x3;
}

__global__ void k_apply_out(const float* __restrict__ O, const float* __restrict__ Mi,
                            uint32_t* __restrict__ omh, uint32_t* __restrict__ oml) {
    int idx = blockIdx.x * blockDim.x + threadIdx.x;
    if (idx >= NVB*LTOK*NH*16) return;
    int g = idx & 15, h = (idx >> 4) & 3, t = (idx >> 6) & (LTOK-1), n = idx >> 16;
    const float* M = Mi + ((size_t)(n*LTOK + t))*16;
    const float* s = O + (((size_t)(n*NH + h))*LTOK + t)*HD + g*4;
    float x0=s[0], x1=s[1], x2=s[2], x3=s[3];
    float d[4];
    #pragma unroll
    for (int i = 0; i < 4; i++)
        d[i] = M[i*4+0]*x0 + M[i*4+1]*x1 + M[i*4+2]*x2 + M[i*4+3]*x3;
    size_t w = (((size_t)(n*LTOK + t))*CC + h*HD + g*4) >> 1;
    uint32_t h0, l0, h1, l1;
    cvt_hl(d[0], d[1], h0, l0);
    cvt_hl(d[2], d[3], h1, l1);
    omh[w] = h0;   oml[w] = l0;
    omh[w+1] = h1; oml[w+1] = l1;
}

// ---------------- layernorm ----------------
__global__ void k_ln(float* __restrict__ dst, const float* __restrict__ src,
                     const float* __restrict__ w, const float* __restrict__ b, int add,
                     uint32_t* __restrict__ oh, uint32_t* __restrict__ ol) {
    __shared__ float red[256];
    int row = blockIdx.x, tid = threadIdx.x;
    float v = src[(size_t)row*CC + tid];
    red[tid] = v; __syncthreads();
    for (int s = 128; s > 0; s >>= 1) { if (tid < s) red[tid] += red[tid+s]; __syncthreads(); }
    float mu = red[0] * (1.0f/CC); __syncthreads();
    float d = v - mu;
    red[tid] = d * d; __syncthreads();
    for (int s = 128; s > 0; s >>= 1) { if (tid < s) red[tid] += red[tid+s]; __syncthreads(); }
    float var = red[0] * (1.0f/CC);
    float o = d * rsqrtf(var + 1e-5f) * w[tid] + b[tid];
    float fin;
    if (add) { fin = dst[(size_t)row*CC + tid] + o; dst[(size_t)row*CC + tid] = fin; }
    else     { fin = o; dst[(size_t)row*CC + tid] = fin; }
    if (oh) {
        __syncthreads();
        red[tid] = fin;
        __syncthreads();
        if (tid < 128) {
            uint32_t h, l;
            cvt_hl(red[2*tid], red[2*tid+1], h, l);
            oh[(size_t)row*(CC/2) + tid] = h;
            ol[(size_t)row*(CC/2) + tid] = l;
        }
    }
}

// ---------------- concat -> bf16 hi/lo ----------------
__global__ void k_cat(const float* __restrict__ x, const float* __restrict__ msg,
                      uint32_t* __restrict__ ch, uint32_t* __restrict__ cl) {
    int idx = blockIdx.x * blockDim.x + threadIdx.x;
    if (idx >= ROWS_*(FFNI/2)) return;
    int c2 = idx & 255, row = idx >> 8;
    float2 v;
    if (c2 < 128) v = reinterpret_cast<const float2*>(x + (size_t)row*CC)[c2];
    else          v = reinterpret_cast<const float2*>(msg + (size_t)row*CC)[c2 - 128];
    uint32_t h, l;
    cvt_hl(v.x, v.y, h, l);
    ch[idx] = h; cl[idx] = l;
}

// ---------------- host driver ----------------
static const int GSMEM = 98304;   // 4 stages x 24576 B (2 CTAs/SM)

static void gemm(const uint32_t* Ah, const uint32_t* Al,
                 const uint32_t* A2h, const uint32_t* A2l, int nsplit,
                 const uint32_t* Bh, const uint32_t* Bl,
                 float* C, int M, int N, int K) {
    dim3 g(N/128, M/128);
    tc_gemm<0><<<g, 256, GSMEM>>>(Ah, Al, A2h, A2l, nsplit, Bh, Bl,
                                  C, nullptr, nullptr, M, N, K);
}
static void gemm_gelu_hl(const uint32_t* Ah, const uint32_t* Al,
                         const uint32_t* Bh, const uint32_t* Bl,
                         uint32_t* Oh, uint32_t* Ol, int M, int N, int K) {
    dim3 g(N/128, M/128);
    tc_gemm<1><<<g, 256, GSMEM>>>(Ah, Al, Ah, Al, 1<<30, Bh, Bl,
                                  nullptr, Oh, Ol, M, N, K);
}

extern "C" void kernel_launch(void* const* d_in, const int* in_sizes, int n_in,
                              void* d_out, int out_size) {
    const float* feats = (const float*)d_in[0];
    const float* vms   = (const float*)d_in[1];
    const float* Ks    = (const float*)d_in[2];
    const float* Wq    = (const float*)d_in[3];
    const float* Wk    = (const float*)d_in[4];
    const float* Wv    = (const float*)d_in[5];
    const float* Wm    = (const float*)d_in[6];
    const float* n1w   = (const float*)d_in[7];
    const float* n1b   = (const float*)d_in[8];
    const float* W1    = (const float*)d_in[9];
    const float* W2    = (const float*)d_in[10];
    const float* n2w   = (const float*)d_in[11];
    const float* n2b   = (const float*)d_in[12];

    cudaFuncSetAttribute(tc_gemm<0>, cudaFuncAttributeMaxDynamicSharedMemorySize, GSMEM);
    cudaFuncSetAttribute(tc_gemm<1>, cudaFuncAttributeMaxDynamicSharedMemorySize, GSMEM);

    void* p;
    float *x,*qkv,*qp,*kp,*vp,*O,*msg,*h2,*Mq,*Mqi,*Mkv;
    uint32_t *xh,*xl,*xpreh,*xprel,*omh,*oml,*cath,*catl,*hh,*hl,*wh,*wl;
    cudaGetSymbolAddress(&p, g_x);    x   = (float*)p;
    cudaGetSymbolAddress(&p, g_qkv);  qkv = (float*)p;
    cudaGetSymbolAddress(&p, g_qp);   qp  = (float*)p;
    cudaGetSymbolAddress(&p, g_kp);   kp  = (float*)p;
    cudaGetSymbolAddress(&p, g_vp);   vp  = (float*)p;
    cudaGetSymbolAddress(&p, g_O);    O   = (float*)p;
    cudaGetSymbolAddress(&p, g_msg);  msg = (float*)p;
    cudaGetSymbolAddress(&p, g_h2);   h2  = (float*)p;
    cudaGetSymbolAddress(&p, g_Mq);   Mq  = (float*)p;
    cudaGetSymbolAddress(&p, g_Mqi);  Mqi = (float*)p;
    cudaGetSymbolAddress(&p, g_Mkv);  Mkv = (float*)p;
    cudaGetSymbolAddress(&p, g_xh);    xh    = (uint32_t*)p;
    cudaGetSymbolAddress(&p, g_xl);    xl    = (uint32_t*)p;
    cudaGetSymbolAddress(&p, g_xpreh); xpreh = (uint32_t*)p;
    cudaGetSymbolAddress(&p, g_xprel); xprel = (uint32_t*)p;
    cudaGetSymbolAddress(&p, g_omh);   omh   = (uint32_t*)p;
    cudaGetSymbolAddress(&p, g_oml);   oml   = (uint32_t*)p;
    cudaGetSymbolAddress(&p, g_cath);  cath  = (uint32_t*)p;
    cudaGetSymbolAddress(&p, g_catl);  catl  = (uint32_t*)p;
    cudaGetSymbolAddress(&p, g_hh);    hh    = (uint32_t*)p;
    cudaGetSymbolAddress(&p, g_hl);    hl    = (uint32_t*)p;
    cudaGetSymbolAddress(&p, g_wh);    wh    = (uint32_t*)p;
    cudaGetSymbolAddress(&p, g_wl);    wl    = (uint32_t*)p;

    const int ROWS = ROWS_;
    const int NEL  = ROWS * CC;
    const int NAPP = NVB*LTOK*NH*16;

    k_cvt_all<<<WTOT/256, 256>>>(Wq, Wk, Wv, Wm, W1, W2, wh, wl);
    k_build_x<<<(XW+255)/256, 256>>>(feats, x, xh, xl);
    k_prope_q<<<(ROWS+255)/256, 256>>>(vms, Ks, Mq, Mqi);
    k_prope_kv<<<(NVB*TKX+255)/256, 256>>>(vms, Ks, Mkv);

    for (int ly = 0; ly < 2; ly++) {
        // snapshot x (pre-self-attn) for cross-attn KV
        k_cvt<<<(XW+255)/256, 256>>>(x, xpreh, xprel, XW);

        // ---------- self attention (fused QKV, N=768) ----------
        gemm(xh, xl, xh, xl, 1<<30,
             wh + WQKV0 + (ly*2+0)*98304, wl + WQKV0 + (ly*2+0)*98304,
             qkv, ROWS, 768, CC);
        k_apply_q  <<<NAPP/256, 256>>>(qkv + 0,   768, Mqi, qp);
        k_apply_kv <<<NAPP/256, 256>>>(qkv + 256, 768, Mq, kp, LTOK, 0);
        k_apply_v_t<<<NAPP/256, 256>>>(qkv + 512, 768, Mq, vp, LTOK, 0);
        k_flash<<<dim3(LTOK/128, NVB*NH), 256>>>(qp, kp, vp, O, LTOK);
        k_apply_out<<<NAPP/256, 256>>>(O, Mqi, omh, oml);
        gemm(omh, oml, omh, oml, 1<<30,
             wh + WMO + (ly*2+0)*32768, wl + WMO + (ly*2+0)*32768,
             msg, ROWS, CC, CC);
        k_ln<<<ROWS, 256>>>(x, msg, n1w + (ly*2+0)*CC, n1b + (ly*2+0)*CC, 1, xh, xl);

        // ---------- cross attention (fused Q|K|V, N=768, A split at 256) ----------
        gemm(xh, xl, xpreh, xprel, 256,
             wh + WQKV0 + (ly*2+1)*98304, wl + WQKV0 + (ly*2+1)*98304,
             qkv, ROWS, 768, CC);
        k_apply_q  <<<NAPP/256, 256>>>(qkv + 0,   768, Mqi, qp);
        k_apply_kv <<<(NVB*TKX*NH*16)/256, 256>>>(qkv + 256, 768, Mkv, kp, TKX, 1);
        k_apply_v_t<<<(NVB*TKX*NH*16)/256, 256>>>(qkv + 512, 768, Mkv, vp, TKX, 1);
        k_flash<<<dim3(LTOK/128, NVB*NH), 256>>>(qp, kp, vp, O, TKX);
        k_apply_out<<<NAPP/256, 256>>>(O, Mqi, omh, oml);
        gemm(omh, oml, omh, oml, 1<<30,
             wh + WMO + (ly*2+1)*32768, wl + WMO + (ly*2+1)*32768,
             msg, ROWS, CC, CC);
        k_ln<<<ROWS, 256>>>(msg, msg, n1w + (ly*2+1)*CC, n1b + (ly*2+1)*CC, 0,
                            nullptr, nullptr);

        // ---------- FFN ----------
        k_cat<<<(ROWS*(FFNI/2))/256, 256>>>(x, msg, cath, catl);
        gemm_gelu_hl(cath, catl,
                     wh + W1O + (size_t)ly*524288, wl + W1O + (size_t)ly*524288,
                     hh, hl, ROWS, FFNH, FFNI);
        gemm(hh, hl, hh, hl, 1<<30,
             wh + W2O + (size_t)ly*262144, wl + W2O + (size_t)ly*262144,
             h2, ROWS, CC, FFNH);
        k_ln<<<ROWS, 256>>>(x, h2, n2w + ly*CC, n2b + ly*CC, 1, xh, xl);
    }

    k_final<<<(NEL+255)/256, 256>>>(x, (float*)d_out);
}

// round 11
// speedup vs baseline: 1.0504x; 1.0093x over previous
#include <cuda_runtime.h>
#include <cuda_bf16.h>
#include <math.h>
#include <stdint.h>

// ---------------- problem constants ----------------
#define NVB   6
#define VV    3
#define BB    2
#define CC    256
#define LTOK  1024
#define TKX   2048
#define NH    4
#define HD    64
#define FFNI  512
#define FFNH  2048

#define ROWS_ (NVB*LTOK)          // 6144
#define XW    (NVB*LTOK*CC/2)     // words in x hi/lo
#define NAPP  (NVB*LTOK*NH*16)    // 393216

// ---------------- device scratch ----------------
__device__ float g_x   [ROWS_*CC];
__device__ float g_qkv [ROWS_*768];
__device__ float g_qp  [NVB*NH*LTOK*HD];
__device__ float g_kp  [NVB*NH*TKX*HD];
__device__ float g_vp  [NVB*NH*TKX*HD];       // TRANSPOSED: [n][h][HD][Tk]
__device__ float g_O   [NVB*NH*LTOK*HD];
__device__ float g_msg [ROWS_*CC];
__device__ float g_h2  [ROWS_*CC];
__device__ float g_Mq  [NVB*LTOK*16];
__device__ float g_Mqi [NVB*LTOK*16];
__device__ float g_Mkv [NVB*TKX*16];

// packed bf16 hi/lo operand buffers
__device__ uint32_t g_xh   [XW],  g_xl   [XW];
__device__ uint32_t g_xpreh[XW],  g_xprel[XW];
__device__ uint32_t g_omh  [XW],  g_oml  [XW];
__device__ uint32_t g_cath [ROWS_*FFNI/2], g_catl[ROWS_*FFNI/2];
__device__ uint32_t g_hh   [ROWS_*FFNH/2], g_hl  [ROWS_*FFNH/2];
// weights (words): qkv blocks [4 x 98304: selfL0,crossL0,selfL1,crossL1] | wm 4x32768 | w1 | w2
#define WQKV0 0
#define WMO   393216
#define W1O   524288
#define W2O   1572864
#define WTOT  2097152
__device__ uint32_t g_wh[WTOT], g_wl[WTOT];

// ---------------- helpers ----------------
__device__ __forceinline__ void cvt_hl(float x, float y, uint32_t& hi, uint32_t& lo) {
    __nv_bfloat162 h = __floats2bfloat162_rn(x, y);
    float rx = x - __bfloat162float(h.x);
    float ry = y - __bfloat162float(h.y);
    __nv_bfloat162 l = __floats2bfloat162_rn(rx, ry);
    hi = *reinterpret_cast<uint32_t*>(&h);
    lo = *reinterpret_cast<uint32_t*>(&l);
}

__device__ __forceinline__ void mma_bf16(float* c, const uint32_t* a, const uint32_t* b) {
    asm volatile(
        "mma.sync.aligned.m16n8k16.row.col.f32.bf16.bf16.f32 "
        "{%0,%1,%2,%3}, {%4,%5,%6,%7}, {%8,%9}, {%0,%1,%2,%3};"
        : "+f"(c[0]), "+f"(c[1]), "+f"(c[2]), "+f"(c[3])
        : "r"(a[0]), "r"(a[1]), "r"(a[2]), "r"(a[3]), "r"(b[0]), "r"(b[1]));
}

__device__ __forceinline__ void ldsm4(uint32_t* r, uint32_t addr) {
    asm volatile("ldmatrix.sync.aligned.m8n8.x4.shared.b16 {%0,%1,%2,%3}, [%4];"
        : "=r"(r[0]), "=r"(r[1]), "=r"(r[2]), "=r"(r[3]) : "r"(addr));
}

__device__ __forceinline__ uint32_t smem_u32(const void* p) {
    uint32_t a;
    asm("{ .reg .u64 t; cvta.to.shared.u64 t, %1; cvt.u32.u64 %0, t; }" : "=r"(a) : "l"(p));
    return a;
}

__device__ __forceinline__ void cp16(uint32_t smem, const void* g) {
    asm volatile("cp.async.cg.shared.global [%0], [%1], 16;" :: "r"(smem), "l"(g));
}
#define CP_COMMIT() asm volatile("cp.async.commit_group;")
#define CP_WAIT(N)  asm volatile("cp.async.wait_group %0;" :: "n"(N))

// ---------------- all-weight conversion + QKV repack, ONE launch ----------------
__global__ void k_cvt_all(const float* __restrict__ Wq, const float* __restrict__ Wk,
                          const float* __restrict__ Wv, const float* __restrict__ Wm,
                          const float* __restrict__ W1, const float* __restrict__ W2,
                          uint32_t* __restrict__ wh, uint32_t* __restrict__ wl) {
    int i = blockIdx.x * blockDim.x + threadIdx.x;
    if (i >= WTOT) return;
    const float* src;
    if (i < WMO) {
        int lyp  = i / 98304;
        int sub  = i % 98304;
        int which = sub / 32768;
        int woff  = sub % 32768;
        const float* base = (which == 0) ? Wq : (which == 1) ? Wk : Wv;
        src = base + (size_t)lyp * 65536 + (size_t)woff * 2;
    } else if (i < W1O) {
        src = Wm + (size_t)(i - WMO) * 2;
    } else if (i < W2O) {
        src = W1 + (size_t)(i - W1O) * 2;
    } else {
        src = W2 + (size_t)(i - W2O) * 2;
    }
    float2 v = *reinterpret_cast<const float2*>(src);
    uint32_t h, l;
    cvt_hl(v.x, v.y, h, l);
    wh[i] = h; wl[i] = l;
}

// ---------------- tensor-core bf16x3 GEMM (BN template, 4-stage cp.async) ----
// C = act(A @ B^T). Per-block A select: n0 >= nsplit uses A2.
// A/B hi/lo [rows, K/2 words]. M%128==0, N%BN==0, K%16==0.
// 256 threads. BN=128: warp 64x32 (2x4), stage 24576 B. BN=64: warp 32x32 (4x2),
// stage 18432 B.
template<int BN, int OUT>
__global__ __launch_bounds__(256)
void tc_gemm(const uint32_t* __restrict__ Ah, const uint32_t* __restrict__ Al,
             const uint32_t* __restrict__ A2h, const uint32_t* __restrict__ A2l,
             int nsplit,
             const uint32_t* __restrict__ Bh, const uint32_t* __restrict__ Bl,
             float* __restrict__ C, uint32_t* __restrict__ Oh, uint32_t* __restrict__ Ol,
             int M, int N, int K)
{
    constexpr int WARPS_N = BN / 32;               // 4 or 2
    constexpr int WM = 16 * (8 / WARPS_N);         // 32 or 64 ... wait: 128/(8/WARPS_N)
    constexpr int WMX = 128 / (8 / WARPS_N);       // 64 (BN=128) or 32 (BN=64)
    constexpr int MT = WMX / 16;                   // 4 or 2
    constexpr int B_HI = BN * 48;                  // bytes per B hi area
    constexpr int STAGE = 12288 + 2 * B_HI;        // 24576 or 18432
    (void)WM;

    extern __shared__ uint32_t smem[];
    const uint32_t sb0 = smem_u32(smem);

    const int m0 = blockIdx.y * 128;
    const int n0 = blockIdx.x * BN;
    const int tid = threadIdx.x;
    const int wid = tid >> 5, lane = tid & 31;
    const int g = lane >> 2, tg = lane & 3;
    const int warp_m = wid / WARPS_N, warp_n = wid % WARPS_N;
    const int wm0 = warp_m * WMX, wn0 = warp_n * 32;
    const int K2 = K >> 1;

    const int rowa = tid >> 1, hw = (tid & 1) * 4;

    const int a_lrow = lane & 15;
    const int a_lcol = (lane >> 4) * 4;
    const int b_lrow = (lane & 7) + ((lane >> 4) << 3);
    const int b_lcol = ((lane >> 3) & 1) * 4;

    float acc[MT][4][4];
    #pragma unroll
    for (int i = 0; i < MT; i++)
        #pragma unroll
        for (int j = 0; j < 4; j++)
            #pragma unroll
            for (int r = 0; r < 4; r++) acc[i][j][r] = 0.f;

    const bool useA2 = (n0 >= nsplit);
    const uint32_t* Ab  = (useA2 ? A2h : Ah) + (size_t)(m0 + rowa) * K2 + hw;
    const uint32_t* Alb = (useA2 ? A2l : Al) + (size_t)(m0 + rowa) * K2 + hw;
    // B row index: BN=128 uses rowa (all 256 threads); BN=64 uses rowa but only tid<128
    const uint32_t* Bb  = Bh + (size_t)(n0 + rowa) * K2 + hw;
    const uint32_t* Blb = Bl + (size_t)(n0 + rowa) * K2 + hw;

    const uint32_t dst_off = (uint32_t)(rowa * 12 + hw) * 4;
    const int nk = K >> 4;

    #define ISSUE(tile, stage) do {                                   \
        uint32_t sb = sb0 + (stage) * (uint32_t)STAGE;                \
        int ko = (tile) * 8;                                          \
        cp16(sb + dst_off,        Ab + ko);                           \
        cp16(sb + 6144 + dst_off, Alb + ko);                          \
        if (BN == 128 || tid < 128) {                                 \
            cp16(sb + 12288 + dst_off,        Bb + ko);               \
            cp16(sb + 12288 + B_HI + dst_off, Blb + ko);              \
        }                                                             \
    } while (0)

    #pragma unroll
    for (int s = 0; s < 3; s++) {
        if (s < nk) ISSUE(s, s);
        CP_COMMIT();
    }

    for (int kt = 0; kt < nk; kt++) {
        if (kt + 3 < nk) ISSUE(kt + 3, (kt + 3) & 3);
        CP_COMMIT();
        CP_WAIT(3);
        __syncthreads();

        const uint32_t sb = sb0 + (kt & 3) * (uint32_t)STAGE;
        uint32_t ah[MT][4], al[MT][4], bh2[4][2], bl2[4][2];
        #pragma unroll
        for (int mi = 0; mi < MT; mi++) {
            uint32_t woff = (uint32_t)((wm0 + mi*16 + a_lrow) * 12 + a_lcol) * 4;
            ldsm4(ah[mi], sb + woff);
            ldsm4(al[mi], sb + 6144 + woff);
        }
        #pragma unroll
        for (int p = 0; p < 2; p++) {
            uint32_t woff = (uint32_t)((wn0 + p*16 + b_lrow) * 12 + b_lcol) * 4;
            uint32_t r[4];
            ldsm4(r, sb + 12288 + woff);
            bh2[2*p][0] = r[0]; bh2[2*p][1] = r[1];
            bh2[2*p+1][0] = r[2]; bh2[2*p+1][1] = r[3];
            ldsm4(r, sb + 12288 + B_HI + woff);
            bl2[2*p][0] = r[0]; bl2[2*p][1] = r[1];
            bl2[2*p+1][0] = r[2]; bl2[2*p+1][1] = r[3];
        }
        #pragma unroll
        for (int mi = 0; mi < MT; mi++)
            #pragma unroll
            for (int ni = 0; ni < 4; ni++) {
                mma_bf16(acc[mi][ni], ah[mi], bh2[ni]);
                mma_bf16(acc[mi][ni], ah[mi], bl2[ni]);
                mma_bf16(acc[mi][ni], al[mi], bh2[ni]);
            }
        __syncthreads();
    }
    #undef ISSUE

    #pragma unroll
    for (int mi = 0; mi < MT; mi++) {
        #pragma unroll
        for (int ni = 0; ni < 4; ni++) {
            long long row0 = m0 + wm0 + mi * 16 + g;
            int col = n0 + wn0 + ni * 8 + tg * 2;
            if (OUT == 0) {
                *reinterpret_cast<float2*>(&C[row0 * N + col]) =
                    make_float2(acc[mi][ni][0], acc[mi][ni][1]);
                *reinterpret_cast<float2*>(&C[(row0 + 8) * N + col]) =
                    make_float2(acc[mi][ni][2], acc[mi][ni][3]);
            } else {
                float r[4];
                #pragma unroll
                for (int t = 0; t < 4; t++) {
                    float v = acc[mi][ni][t];
                    r[t] = 0.5f * v * (1.0f + erff(v * 0.70710678118654752f));
                }
                uint32_t h0, l0, h1, l1;
                cvt_hl(r[0], r[1], h0, l0);
                cvt_hl(r[2], r[3], h1, l1);
                size_t w0 = (size_t)(row0 * N + col) >> 1;
                size_t w1 = (size_t)((row0 + 8) * N + col) >> 1;
                Oh[w0] = h0; Ol[w0] = l0;
                Oh[w1] = h1; Ol[w1] = l1;
            }
        }
    }
}

// ---------------- fused flash attention (bf16x3, online softmax, prefetch) ----
#define FA_SK 36
__global__ __launch_bounds__(256)
void k_flash(const float* __restrict__ qp, const float* __restrict__ kp,
             const float* __restrict__ vpT, float* __restrict__ Og, int Tk)
{
    __shared__ uint32_t khw[64*FA_SK], klw[64*FA_SK];
    __shared__ uint32_t vhw[64*FA_SK], vlw[64*FA_SK];

    const int nh = blockIdx.y;
    const int q0 = blockIdx.x * 128;
    const int tid = threadIdx.x, wid = tid >> 5, lane = tid & 31;
    const int g = lane >> 2, tg = lane & 3;

    const float* Qb = qp + ((size_t)nh * LTOK + q0) * HD;
    const float* Kb = kp + (size_t)nh * Tk * HD;
    const float* Vb = vpT + (size_t)nh * HD * Tk;

    const int row0 = wid * 16 + g;
    uint32_t qh[4][4], ql[4][4];
    #pragma unroll
    for (int kk = 0; kk < 4; kk++) {
        int col = kk * 16 + tg * 2;
        float2 q00 = *reinterpret_cast<const float2*>(&Qb[(size_t)row0 * HD + col]);
        float2 q01 = *reinterpret_cast<const float2*>(&Qb[(size_t)row0 * HD + col + 8]);
        float2 q10 = *reinterpret_cast<const float2*>(&Qb[(size_t)(row0 + 8) * HD + col]);
        float2 q11 = *reinterpret_cast<const float2*>(&Qb[(size_t)(row0 + 8) * HD + col + 8]);
        cvt_hl(q00.x * 0.125f, q00.y * 0.125f, qh[kk][0], ql[kk][0]);
        cvt_hl(q10.x * 0.125f, q10.y * 0.125f, qh[kk][1], ql[kk][1]);
        cvt_hl(q01.x * 0.125f, q01.y * 0.125f, qh[kk][2], ql[kk][2]);
        cvt_hl(q11.x * 0.125f, q11.y * 0.125f, qh[kk][3], ql[kk][3]);
    }

    float m0 = -1e30f, m1 = -1e30f, l0 = 0.f, l1 = 0.f;
    float oacc[8][4];
    #pragma unroll
    for (int i = 0; i < 8; i++)
        #pragma unroll
        for (int t = 0; t < 4; t++) oacc[i][t] = 0.f;

    const int r = tid >> 2, c = (tid & 3) * 16;
    float4 rk[4], rv[4];
    {
        const float* sk = Kb + (size_t)r * HD + c;
        const float* sv = Vb + (size_t)r * Tk + c;
        #pragma unroll
        for (int j = 0; j < 4; j++) {
            rk[j] = *reinterpret_cast<const float4*>(sk + j * 4);
            rv[j] = *reinterpret_cast<const float4*>(sv + j * 4);
        }
    }

    for (int kv0 = 0; kv0 < Tk; kv0 += 64) {
        #pragma unroll
        for (int j = 0; j < 4; j++) {
            int w = r * FA_SK + (c >> 1) + j * 2;
            uint32_t h, l;
            cvt_hl(rk[j].x, rk[j].y, h, l); khw[w] = h;   klw[w] = l;
            cvt_hl(rk[j].z, rk[j].w, h, l); khw[w+1] = h; klw[w+1] = l;
            cvt_hl(rv[j].x, rv[j].y, h, l); vhw[w] = h;   vlw[w] = l;
            cvt_hl(rv[j].z, rv[j].w, h, l); vhw[w+1] = h; vlw[w+1] = l;
        }
        __syncthreads();

        if (kv0 + 64 < Tk) {
            const float* sk = Kb + (size_t)(kv0 + 64 + r) * HD + c;
            const float* sv = Vb + (size_t)r * Tk + (kv0 + 64) + c;
            #pragma unroll
            for (int j = 0; j < 4; j++) {
                rk[j] = *reinterpret_cast<const float4*>(sk + j * 4);
                rv[j] = *reinterpret_cast<const float4*>(sv + j * 4);
            }
        }

        float sacc[8][4];
        #pragma unroll
        for (int i = 0; i < 8; i++)
            #pragma unroll
            for (int t = 0; t < 4; t++) sacc[i][t] = 0.f;
        #pragma unroll
        for (int kk = 0; kk < 4; kk++) {
            #pragma unroll
            for (int ni = 0; ni < 8; ni++) {
                uint32_t bh[2], bl[2];
                int off = (ni * 8 + g) * FA_SK + kk * 8 + tg;
                bh[0] = khw[off]; bh[1] = khw[off + 4];
                bl[0] = klw[off]; bl[1] = klw[off + 4];
                mma_bf16(sacc[ni], qh[kk], bh);
                mma_bf16(sacc[ni], qh[kk], bl);
                mma_bf16(sacc[ni], ql[kk], bh);
            }
        }

        float mx0 = -1e30f, mx1 = -1e30f;
        #pragma unroll
        for (int ni = 0; ni < 8; ni++) {
            mx0 = fmaxf(mx0, fmaxf(sacc[ni][0], sacc[ni][1]));
            mx1 = fmaxf(mx1, fmaxf(sacc[ni][2], sacc[ni][3]));
        }
        mx0 = fmaxf(mx0, __shfl_xor_sync(0xffffffff, mx0, 1));
        mx0 = fmaxf(mx0, __shfl_xor_sync(0xffffffff, mx0, 2));
        mx1 = fmaxf(mx1, __shfl_xor_sync(0xffffffff, mx1, 1));
        mx1 = fmaxf(mx1, __shfl_xor_sync(0xffffffff, mx1, 2));
        float nm0 = fmaxf(m0, mx0), nm1 = fmaxf(m1, mx1);
        float al0 = __expf(m0 - nm0), al1 = __expf(m1 - nm1);
        float rs0 = 0.f, rs1 = 0.f;
        #pragma unroll
        for (int ni = 0; ni < 8; ni++) {
            sacc[ni][0] = __expf(sacc[ni][0] - nm0);
            sacc[ni][1] = __expf(sacc[ni][1] - nm0);
            sacc[ni][2] = __expf(sacc[ni][2] - nm1);
            sacc[ni][3] = __expf(sacc[ni][3] - nm1);
            rs0 += sacc[ni][0] + sacc[ni][1];
            rs1 += sacc[ni][2] + sacc[ni][3];
        }
        rs0 += __shfl_xor_sync(0xffffffff, rs0, 1);
        rs0 += __shfl_xor_sync(0xffffffff, rs0, 2);
        rs1 += __shfl_xor_sync(0xffffffff, rs1, 1);
        rs1 += __shfl_xor_sync(0xffffffff, rs1, 2);
        l0 = l0 * al0 + rs0;  l1 = l1 * al1 + rs1;
        m0 = nm0;  m1 = nm1;
        #pragma unroll
        for (int nd = 0; nd < 8; nd++) {
            oacc[nd][0] *= al0; oacc[nd][1] *= al0;
            oacc[nd][2] *= al1; oacc[nd][3] *= al1;
        }

        #pragma unroll
        for (int kk = 0; kk < 4; kk++) {
            uint32_t ph[4], pl[4];
            cvt_hl(sacc[2*kk][0],   sacc[2*kk][1],   ph[0], pl[0]);
            cvt_hl(sacc[2*kk][2],   sacc[2*kk][3],   ph[1], pl[1]);
            cvt_hl(sacc[2*kk+1][0], sacc[2*kk+1][1], ph[2], pl[2]);
            cvt_hl(sacc[2*kk+1][2], sacc[2*kk+1][3], ph[3], pl[3]);
            #pragma unroll
            for (int nd = 0; nd < 8; nd++) {
                uint32_t vh[2], vl[2];
                int off = (nd * 8 + g) * FA_SK + kk * 8 + tg;
                vh[0] = vhw[off]; vh[1] = vhw[off + 4];
                vl[0] = vlw[off]; vl[1] = vlw[off + 4];
                mma_bf16(oacc[nd], ph, vh);
                mma_bf16(oacc[nd], ph, vl);
                mma_bf16(oacc[nd], pl, vh);
            }
        }
        __syncthreads();
    }

    float il0 = 1.0f / l0, il1 = 1.0f / l1;
    float* Ob = Og + ((size_t)nh * LTOK + q0) * HD;
    #pragma unroll
    for (int nd = 0; nd < 8; nd++) {
        int col = nd * 8 + tg * 2;
        *reinterpret_cast<float2*>(&Ob[(size_t)row0 * HD + col]) =
            make_float2(oacc[nd][0] * il0, oacc[nd][1] * il0);
        *reinterpret_cast<float2*>(&Ob[(size_t)(row0 + 8) * HD + col]) =
            make_float2(oacc[nd][2] * il1, oacc[nd][3] * il1);
    }
}

// ---------------- layout kernels ----------------
__global__ void k_build_x(const float* __restrict__ f, float* __restrict__ x,
                          uint32_t* __restrict__ xh, uint32_t* __restrict__ xl,
                          uint32_t* __restrict__ xph, uint32_t* __restrict__ xpl) {
    int idx = blockIdx.x * blockDim.x + threadIdx.x;
    if (idx >= XW) return;
    int c2 = idx & 127;
    int l  = (idx >> 7) & (LTOK-1);
    int n  = idx >> 17;
    int c  = c2 * 2;
    float a = f[((size_t)n*CC + c)*LTOK + l];
    float b = f[((size_t)n*CC + c + 1)*LTOK + l];
    reinterpret_cast<float2*>(x)[idx] = make_float2(a, b);
    uint32_t h, lw;
    cvt_hl(a, b, h, lw);
    xh[idx] = h; xl[idx] = lw;
    xph[idx] = h; xpl[idx] = lw;
}

__global__ void k_final(const float* __restrict__ x, float* __restrict__ o) {
    int idx = blockIdx.x * blockDim.x + threadIdx.x;
    if (idx >= ROWS_*CC) return;
    int l = idx & (LTOK-1);
    int c = (idx >> 10) & (CC-1);
    int n = idx >> 18;
    o[idx] = x[((size_t)n*LTOK + l)*CC + c];
}

// ---------------- PRoPE matrix build ----------------
__device__ __forceinline__ void prope_forward(const float* vm, const float* Kc,
                                              float u, float vyy, float* M) {
    float fx = Kc[0] * (1.0f/128.0f), fy = Kc[4] * (1.0f/128.0f);
    float cx = Kc[2] * (1.0f/128.0f), cy = Kc[5] * (1.0f/128.0f);
    float a = cx - u, b = cy - vyy;
    #pragma unroll
    for (int c = 0; c < 4; c++) {
        M[0*4+c] = fx*vm[0*4+c] + a*vm[2*4+c];
        M[1*4+c] = fy*vm[1*4+c] + b*vm[2*4+c];
        M[2*4+c] = vm[2*4+c];
        M[3*4+c] = vm[3*4+c];
    }
}

__global__ void k_prope_q(const float* __restrict__ vms, const float* __restrict__ Ks,
                          float* __restrict__ Mq, float* __restrict__ Mqi) {
    int idx = blockIdx.x * blockDim.x + threadIdx.x;
    if (idx >= NVB*LTOK) return;
    int n = idx >> 10, t = idx & (LTOK-1);
    int px = t & 31, py = t >> 5;
    float u  = (px + 0.5f) * (1.0f/32.0f);
    float vy = (py + 0.5f) * (1.0f/32.0f);
    const float* vm = vms + n*16;
    const float* Kc = Ks + n*9;
    float M[16];
    prope_forward(vm, Kc, u, vy, M);
    #pragma unroll
    for (int i = 0; i < 16; i++) Mq[idx*16+i] = M[i];

    float r00=vm[0],r01=vm[1],r02=vm[2],  t0=vm[3];
    float r10=vm[4],r11=vm[5],r12=vm[6],  t1=vm[7];
    float r20=vm[8],r21=vm[9],r22=vm[10], t2=vm[11];
    float det = r00*(r11*r22-r12*r21) - r01*(r10*r22-r12*r20) + r02*(r10*r21-r11*r20);
    float id = 1.0f/det;
    float Ri[9];
    Ri[0]=(r11*r22-r12*r21)*id; Ri[1]=(r02*r21-r01*r22)*id; Ri[2]=(r01*r12-r02*r11)*id;
    Ri[3]=(r12*r20-r10*r22)*id; Ri[4]=(r00*r22-r02*r20)*id; Ri[5]=(r02*r10-r00*r12)*id;
    Ri[6]=(r10*r21-r11*r20)*id; Ri[7]=(r01*r20-r00*r21)*id; Ri[8]=(r00*r11-r01*r10)*id;
    float ti0 = -(Ri[0]*t0 + Ri[1]*t1 + Ri[2]*t2);
    float ti1 = -(Ri[3]*t0 + Ri[4]*t1 + Ri[5]*t2);
    float ti2 = -(Ri[6]*t0 + Ri[7]*t1 + Ri[8]*t2);
    float fx = Kc[0]*(1.0f/128.0f), fy = Kc[4]*(1.0f/128.0f);
    float cx = Kc[2]*(1.0f/128.0f), cy = Kc[5]*(1.0f/128.0f);
    float a = cx - u, b = cy - vy;
    float ifx = 1.0f/fx, ify = 1.0f/fy;
    float Mi[16];
    float tv[3] = {ti0, ti1, ti2};
    #pragma unroll
    for (int i = 0; i < 3; i++) {
        Mi[i*4+0] = Ri[i*3+0]*ifx;
        Mi[i*4+1] = Ri[i*3+1]*ify;
        Mi[i*4+2] = -Ri[i*3+0]*a*ifx - Ri[i*3+1]*b*ify + Ri[i*3+2];
        Mi[i*4+3] = tv[i];
    }
    Mi[12]=0.f; Mi[13]=0.f; Mi[14]=0.f; Mi[15]=1.f;
    #pragma unroll
    for (int i = 0; i < 16; i++) Mqi[idx*16+i] = Mi[i];
}

__global__ void k_prope_kv(const float* __restrict__ vms, const float* __restrict__ Ks,
                           float* __restrict__ Mkv) {
    int idx = blockIdx.x * blockDim.x + threadIdx.x;
    if (idx >= NVB*TKX) return;
    int n = idx >> 11, tt = idx & (TKX-1);
    int m = tt >> 10, l = tt & (LTOK-1);
    int vvi = n >> 1, b = n & 1;
    int j = m + (m >= vvi ? 1 : 0);
    int cam = j*BB + b;
    int px = l & 31, py = l >> 5;
    float u  = (px + 0.5f)*(1.0f/32.0f);
    float vy = (py + 0.5f)*(1.0f/32.0f);
    float M[16];
    prope_forward(vms + cam*16, Ks + cam*9, u, vy, M);
    #pragma unroll
    for (int i = 0; i < 16; i++) Mkv[idx*16+i] = M[i];
}

// ---------------- fused per-token applies: q, k, v in one launch --------------
// src = qkv buffer (stride cols). q cols [0,256), k [256,512), v [512,768).
__global__ void k_apply_all(const float* __restrict__ qkv, int stride,
                            const float* __restrict__ Mqi, const float* __restrict__ Mats,
                            float* __restrict__ qp, float* __restrict__ kp,
                            float* __restrict__ vp,
                            int Tk, int gather, int nkv)
{
    int idx = blockIdx.x * blockDim.x + threadIdx.x;
    if (idx < NAPP) {
        // ---- Q path ----
        int g = idx & 15, h = (idx >> 4) & 3, t = (idx >> 6) & (LTOK-1), n = idx >> 16;
        const float* M = Mqi + ((size_t)(n*LTOK + t))*16;
        const float* s = qkv + ((size_t)(n*LTOK + t))*stride + h*HD + g*4;
        float x0=s[0], x1=s[1], x2=s[2], x3=s[3];
        float* d = qp + (((size_t)(n*NH + h))*LTOK + t)*HD + g*4;
        #pragma unroll
        for (int i = 0; i < 4; i++)
            d[i] = M[0*4+i]*x0 + M[1*4+i]*x1 + M[2*4+i]*x2 + M[3*4+i]*x3;
    } else if (idx < NAPP + nkv) {
        // ---- K path ----
        int i2 = idx - NAPP;
        int g = i2 & 15, h = (i2 >> 4) & 3;
        int tt = (i2 >> 6) % Tk, n = (i2 >> 6) / Tk;
        size_t srcRow;
        if (gather) {
            int m = tt >> 10, l = tt & (LTOK-1);
            int vvi = n >> 1, b = n & 1;
            int j = m + (m >= vvi ? 1 : 0);
            srcRow = (size_t)(j*BB + b)*LTOK + l;
        } else {
            srcRow = (size_t)n*LTOK + tt;
        }
        const float* M = Mats + ((size_t)n*Tk + tt)*16;
        const float* s = qkv + srcRow*stride + 256 + h*HD + g*4;
        float x0=s[0], x1=s[1], x2=s[2], x3=s[3];
        float* d = kp + (((size_t)(n*NH + h))*Tk + tt)*HD + g*4;
        #pragma unroll
        for (int i = 0; i < 4; i++)
            d[i] = M[i*4+0]*x0 + M[i*4+1]*x1 + M[i*4+2]*x2 + M[i*4+3]*x3;
    } else if (idx < NAPP + 2*nkv) {
        // ---- V path (transposed output) ----
        int i2 = idx - NAPP - nkv;
        int tt = i2 % Tk;
        int rest = i2 / Tk;
        int g = rest & 15, h = (rest >> 4) & 3, n = rest >> 6;
        size_t srcRow;
        if (gather) {
            int m = tt >> 10, l = tt & (LTOK-1);
            int vvi = n >> 1, b = n & 1;
            int j = m + (m >= vvi ? 1 : 0);
            srcRow = (size_t)(j*BB + b)*LTOK + l;
        } else {
            srcRow = (size_t)n*LTOK + tt;
        }
        const float* M = Mats + ((size_t)n*Tk + tt)*16;
        const float* s = qkv + srcRow*stride + 512 + h*HD + g*4;
        float x0=s[0], x1=s[1], x2=s[2], x3=s[3];
        float* dbase = vp + ((size_t)(n*NH + h)*HD + g*4)*Tk + tt;
        #pragma unroll
        for (int i = 0; i < 4; i++)
            dbase[(size_t)i*Tk] = M[i*4+0]*x0 + M[i*4+1]*x1 + M[i*4+2]*x2 + M[i*4+3]*x3;
    }
}

__global__ void k_apply_out(const float* __restrict__ O, const float* __restrict__ Mi,
                            uint32_t* __restrict__ omh, uint32_t* __restrict__ oml) {
    int idx = blockIdx.x * blockDim.x + threadIdx.x;
    if (idx >= NAPP) return;
    int g = idx & 15, h = (idx >> 4) & 3, t = (idx >> 6) & (LTOK-1), n = idx >> 16;
    const float* M = Mi + ((size_t)(n*LTOK + t))*16;
    const float* s = O + (((size_t)(n*NH + h))*LTOK + t)*HD + g*4;
    float x0=s[0], x1=s[1], x2=s[2], x3=s[3];
    float d[4];
    #pragma unroll
    for (int i = 0; i < 4; i++)
        d[i] = M[i*4+0]*x0 + M[i*4+1]*x1 + M[i*4+2]*x2 + M[i*4+3]*x3;
    size_t w = (((size_t)(n*LTOK + t))*CC + h*HD + g*4) >> 1;
    uint32_t h0, l0, h1, l1;
    cvt_hl(d[0], d[1], h0, l0);
    cvt_hl(d[2], d[3], h1, l1);
    omh[w] = h0;   oml[w] = l0;
    omh[w+1] = h1; oml[w+1] = l1;
}

// ---------------- layernorm ----------------
__global__ void k_ln(float* __restrict__ dst, const float* __restrict__ src,
                     const float* __restrict__ w, const float* __restrict__ b, int add,
                     uint32_t* __restrict__ oh, uint32_t* __restrict__ ol,
                     uint32_t* __restrict__ oh2, uint32_t* __restrict__ ol2) {
    __shared__ float red[256];
    int row = blockIdx.x, tid = threadIdx.x;
    float v = src[(size_t)row*CC + tid];
    red[tid] = v; __syncthreads();
    for (int s = 128; s > 0; s >>= 1) { if (tid < s) red[tid] += red[tid+s]; __syncthreads(); }
    float mu = red[0] * (1.0f/CC); __syncthreads();
    float d = v - mu;
    red[tid] = d * d; __syncthreads();
    for (int s = 128; s > 0; s >>= 1) { if (tid < s) red[tid] += red[tid+s]; __syncthreads(); }
    float var = red[0] * (1.0f/CC);
    float o = d * rsqrtf(var + 1e-5f) * w[tid] + b[tid];
    float fin;
    if (add) { fin = dst[(size_t)row*CC + tid] + o; dst[(size_t)row*CC + tid] = fin; }
    else     { fin = o; dst[(size_t)row*CC + tid] = fin; }
    if (oh) {
        __syncthreads();
        red[tid] = fin;
        __syncthreads();
        if (tid < 128) {
            uint32_t h, l;
            cvt_hl(red[2*tid], red[2*tid+1], h, l);
            oh[(size_t)row*(CC/2) + tid] = h;
            ol[(size_t)row*(CC/2) + tid] = l;
            if (oh2) {
                oh2[(size_t)row*(CC/2) + tid] = h;
                ol2[(size_t)row*(CC/2) + tid] = l;
            }
        }
    }
}

// ---------------- concat -> bf16 hi/lo ----------------
__global__ void k_cat(const float* __restrict__ x, const float* __restrict__ msg,
                      uint32_t* __restrict__ ch, uint32_t* __restrict__ cl) {
    int idx = blockIdx.x * blockDim.x + threadIdx.x;
    if (idx >= ROWS_*(FFNI/2)) return;
    int c2 = idx & 255, row = idx >> 8;
    float2 v;
    if (c2 < 128) v = reinterpret_cast<const float2*>(x + (size_t)row*CC)[c2];
    else          v = reinterpret_cast<const float2*>(msg + (size_t)row*CC)[c2 - 128];
    uint32_t h, l;
    cvt_hl(v.x, v.y, h, l);
    ch[idx] = h; cl[idx] = l;
}

// ---------------- host driver ----------------
static const int GSMEM128 = 98304;   // 4 stages x 24576 B
static const int GSMEM64  = 73728;   // 4 stages x 18432 B

static void gemm128(const uint32_t* Ah, const uint32_t* Al,
                    const uint32_t* A2h, const uint32_t* A2l, int nsplit,
                    const uint32_t* Bh, const uint32_t* Bl,
                    float* C, int M, int N, int K) {
    dim3 g(N/128, M/128);
    tc_gemm<128,0><<<g, 256, GSMEM128>>>(Ah, Al, A2h, A2l, nsplit, Bh, Bl,
                                         C, nullptr, nullptr, M, N, K);
}
static void gemm64(const uint32_t* Ah, const uint32_t* Al,
                   const uint32_t* Bh, const uint32_t* Bl,
                   float* C, int M, int N, int K) {
    dim3 g(N/64, M/128);
    tc_gemm<64,0><<<g, 256, GSMEM64>>>(Ah, Al, Ah, Al, 1<<30, Bh, Bl,
                                       C, nullptr, nullptr, M, N, K);
}
static void gemm_gelu_hl(const uint32_t* Ah, const uint32_t* Al,
                         const uint32_t* Bh, const uint32_t* Bl,
                         uint32_t* Oh, uint32_t* Ol, int M, int N, int K) {
    dim3 g(N/128, M/128);
    tc_gemm<128,1><<<g, 256, GSMEM128>>>(Ah, Al, Ah, Al, 1<<30, Bh, Bl,
                                         nullptr, Oh, Ol, M, N, K);
}

extern "C" void kernel_launch(void* const* d_in, const int* in_sizes, int n_in,
                              void* d_out, int out_size) {
    const float* feats = (const float*)d_in[0];
    const float* vms   = (const float*)d_in[1];
    const float* Ks    = (const float*)d_in[2];
    const float* Wq    = (const float*)d_in[3];
    const float* Wk    = (const float*)d_in[4];
    const float* Wv    = (const float*)d_in[5];
    const float* Wm    = (const float*)d_in[6];
    const float* n1w   = (const float*)d_in[7];
    const float* n1b   = (const float*)d_in[8];
    const float* W1    = (const float*)d_in[9];
    const float* W2    = (const float*)d_in[10];
    const float* n2w   = (const float*)d_in[11];
    const float* n2b   = (const float*)d_in[12];

    cudaFuncSetAttribute(tc_gemm<128,0>, cudaFuncAttributeMaxDynamicSharedMemorySize, GSMEM128);
    cudaFuncSetAttribute(tc_gemm<128,1>, cudaFuncAttributeMaxDynamicSharedMemorySize, GSMEM128);
    cudaFuncSetAttribute(tc_gemm<64,0>,  cudaFuncAttributeMaxDynamicSharedMemorySize, GSMEM64);

    void* p;
    float *x,*qkv,*qp,*kp,*vp,*O,*msg,*h2,*Mq,*Mqi,*Mkv;
    uint32_t *xh,*xl,*xpreh,*xprel,*omh,*oml,*cath,*catl,*hh,*hl,*wh,*wl;
    cudaGetSymbolAddress(&p, g_x);    x   = (float*)p;
    cudaGetSymbolAddress(&p, g_qkv);  qkv = (float*)p;
    cudaGetSymbolAddress(&p, g_qp);   qp  = (float*)p;
    cudaGetSymbolAddress(&p, g_kp);   kp  = (float*)p;
    cudaGetSymbolAddress(&p, g_vp);   vp  = (float*)p;
    cudaGetSymbolAddress(&p, g_O);    O   = (float*)p;
    cudaGetSymbolAddress(&p, g_msg);  msg = (float*)p;
    cudaGetSymbolAddress(&p, g_h2);   h2  = (float*)p;
    cudaGetSymbolAddress(&p, g_Mq);   Mq  = (float*)p;
    cudaGetSymbolAddress(&p, g_Mqi);  Mqi = (float*)p;
    cudaGetSymbolAddress(&p, g_Mkv);  Mkv = (float*)p;
    cudaGetSymbolAddress(&p, g_xh);    xh    = (uint32_t*)p;
    cudaGetSymbolAddress(&p, g_xl);    xl    = (uint32_t*)p;
    cudaGetSymbolAddress(&p, g_xpreh); xpreh = (uint32_t*)p;
    cudaGetSymbolAddress(&p, g_xprel); xprel = (uint32_t*)p;
    cudaGetSymbolAddress(&p, g_omh);   omh   = (uint32_t*)p;
    cudaGetSymbolAddress(&p, g_oml);   oml   = (uint32_t*)p;
    cudaGetSymbolAddress(&p, g_cath);  cath  = (uint32_t*)p;
    cudaGetSymbolAddress(&p, g_catl);  catl  = (uint32_t*)p;
    cudaGetSymbolAddress(&p, g_hh);    hh    = (uint32_t*)p;
    cudaGetSymbolAddress(&p, g_hl);    hl    = (uint32_t*)p;
    cudaGetSymbolAddress(&p, g_wh);    wh    = (uint32_t*)p;
    cudaGetSymbolAddress(&p, g_wl);    wl    = (uint32_t*)p;

    const int ROWS = ROWS_;
    const int NEL  = ROWS * CC;
    const int NKV_SELF  = NAPP;              // NVB*LTOK*NH*16
    const int NKV_CROSS = NVB*TKX*NH*16;     // 2x

    k_cvt_all<<<WTOT/256, 256>>>(Wq, Wk, Wv, Wm, W1, W2, wh, wl);
    k_build_x<<<(XW+255)/256, 256>>>(feats, x, xh, xl, xpreh, xprel);
    k_prope_q<<<(ROWS+255)/256, 256>>>(vms, Ks, Mq, Mqi);
    k_prope_kv<<<(NVB*TKX+255)/256, 256>>>(vms, Ks, Mkv);

    for (int ly = 0; ly < 2; ly++) {
        // ---------- self attention (fused QKV, N=768) ----------
        gemm128(xh, xl, xh, xl, 1<<30,
                wh + WQKV0 + (ly*2+0)*98304, wl + WQKV0 + (ly*2+0)*98304,
                qkv, ROWS, 768, CC);
        k_apply_all<<<(NAPP + 2*NKV_SELF + 255)/256, 256>>>(
            qkv, 768, Mqi, Mq, qp, kp, vp, LTOK, 0, NKV_SELF);
        k_flash<<<dim3(LTOK/128, NVB*NH), 256>>>(qp, kp, vp, O, LTOK);
        k_apply_out<<<NAPP/256, 256>>>(O, Mqi, omh, oml);
        gemm64(omh, oml, wh + WMO + (ly*2+0)*32768, wl + WMO + (ly*2+0)*32768,
               msg, ROWS, CC, CC);
        k_ln<<<ROWS, 256>>>(x, msg, n1w + (ly*2+0)*CC, n1b + (ly*2+0)*CC, 1,
                            xh, xl, nullptr, nullptr);

        // ---------- cross attention (fused Q|K|V, N=768, A split at 256) ----------
        gemm128(xh, xl, xpreh, xprel, 256,
                wh + WQKV0 + (ly*2+1)*98304, wl + WQKV0 + (ly*2+1)*98304,
                qkv, ROWS, 768, CC);
        k_apply_all<<<(NAPP + 2*NKV_CROSS + 255)/256, 256>>>(
            qkv, 768, Mqi, Mkv, qp, kp, vp, TKX, 1, NKV_CROSS);
        k_flash<<<dim3(LTOK/128, NVB*NH), 256>>>(qp, kp, vp, O, TKX);
        k_apply_out<<<NAPP/256, 256>>>(O, Mqi, omh, oml);
        gemm64(omh, oml, wh + WMO + (ly*2+1)*32768, wl + WMO + (ly*2+1)*32768,
               msg, ROWS, CC, CC);
        k_ln<<<ROWS, 256>>>(msg, msg, n1w + (ly*2+1)*CC, n1b + (ly*2+1)*CC, 0,
                            nullptr, nullptr, nullptr, nullptr);

        // ---------- FFN ----------
        k_cat<<<(ROWS*(FFNI/2))/256, 256>>>(x, msg, cath, catl);
        gemm_gelu_hl(cath, catl,
                     wh + W1O + (size_t)ly*524288, wl + W1O + (size_t)ly*524288,
                     hh, hl, ROWS, FFNH, FFNI);
        gemm64(hh, hl, wh + W2O + (size_t)ly*262144, wl + W2O + (size_t)ly*262144,
               h2, ROWS, CC, FFNH);
        // final LN of layer: write x, xh/xl AND xpre (pre-self-attn snapshot for next layer)
        k_ln<<<ROWS, 256>>>(x, h2, n2w + ly*CC, n2b + ly*CC, 1,
                            xh, xl, xpreh, xprel);
    }

    k_final<<<(NEL+255)/256, 256>>>(x, (float*)d_out);
}

// round 12
// speedup vs baseline: 1.1182x; 1.0645x over previous
#include <cuda_runtime.h>
#include <cuda_bf16.h>
#include <math.h>
#include <stdint.h>

// ---------------- problem constants ----------------
#define NVB   6
#define VV    3
#define BB    2
#define CC    256
#define LTOK  1024
#define TKX   2048
#define NH    4
#define HD    64
#define FFNI  512
#define FFNH  2048

#define ROWS_ (NVB*LTOK)          // 6144
#define XW    (NVB*LTOK*CC/2)
#define NAPP  (NVB*LTOK*NH*16)    // 393216

// ---------------- device scratch ----------------
__device__ float g_x   [ROWS_*CC];
__device__ float g_qkv [ROWS_*768];
__device__ float g_qp  [NVB*NH*LTOK*HD];
__device__ uint32_t g_kph[NVB*NH*TKX*HD/2], g_kpl[NVB*NH*TKX*HD/2];
__device__ uint32_t g_vph[NVB*NH*TKX*HD/2], g_vpl[NVB*NH*TKX*HD/2];  // V^T packed
__device__ float g_O   [NVB*NH*LTOK*HD];
__device__ float g_msg [ROWS_*CC];
__device__ float g_msg2[2*ROWS_*CC];          // split-K partials
__device__ float g_h22 [2*ROWS_*CC];          // split-K partials (W2)
__device__ float g_Mq  [NVB*LTOK*16];
__device__ float g_Mqi [NVB*LTOK*16];
__device__ float g_Mkv [NVB*TKX*16];

__device__ uint32_t g_xh   [XW],  g_xl   [XW];
__device__ uint32_t g_xpreh[XW],  g_xprel[XW];
__device__ uint32_t g_omh  [XW],  g_oml  [XW];
__device__ uint32_t g_cath [ROWS_*FFNI/2], g_catl[ROWS_*FFNI/2];
__device__ uint32_t g_hh   [ROWS_*FFNH/2], g_hl  [ROWS_*FFNH/2];
#define WQKV0 0
#define WMO   393216
#define W1O   524288
#define W2O   1572864
#define WTOT  2097152
__device__ uint32_t g_wh[WTOT], g_wl[WTOT];

// ---------------- helpers ----------------
__device__ __forceinline__ void cvt_hl(float x, float y, uint32_t& hi, uint32_t& lo) {
    __nv_bfloat162 h = __floats2bfloat162_rn(x, y);
    float rx = x - __bfloat162float(h.x);
    float ry = y - __bfloat162float(h.y);
    __nv_bfloat162 l = __floats2bfloat162_rn(rx, ry);
    hi = *reinterpret_cast<uint32_t*>(&h);
    lo = *reinterpret_cast<uint32_t*>(&l);
}

__device__ __forceinline__ void mma_bf16(float* c, const uint32_t* a, const uint32_t* b) {
    asm volatile(
        "mma.sync.aligned.m16n8k16.row.col.f32.bf16.bf16.f32 "
        "{%0,%1,%2,%3}, {%4,%5,%6,%7}, {%8,%9}, {%0,%1,%2,%3};"
        : "+f"(c[0]), "+f"(c[1]), "+f"(c[2]), "+f"(c[3])
        : "r"(a[0]), "r"(a[1]), "r"(a[2]), "r"(a[3]), "r"(b[0]), "r"(b[1]));
}

__device__ __forceinline__ void ldsm4(uint32_t* r, uint32_t addr) {
    asm volatile("ldmatrix.sync.aligned.m8n8.x4.shared.b16 {%0,%1,%2,%3}, [%4];"
        : "=r"(r[0]), "=r"(r[1]), "=r"(r[2]), "=r"(r[3]) : "r"(addr));
}

__device__ __forceinline__ uint32_t smem_u32(const void* p) {
    uint32_t a;
    asm("{ .reg .u64 t; cvta.to.shared.u64 t, %1; cvt.u32.u64 %0, t; }" : "=r"(a) : "l"(p));
    return a;
}

__device__ __forceinline__ void cp16(uint32_t smem, const void* g) {
    asm volatile("cp.async.cg.shared.global [%0], [%1], 16;" :: "r"(smem), "l"(g));
}
#define CP_COMMIT() asm volatile("cp.async.commit_group;")
#define CP_WAIT(N)  asm volatile("cp.async.wait_group %0;" :: "n"(N))

// ---------------- all-weight conversion + QKV repack ----------------
__global__ void k_cvt_all(const float* __restrict__ Wq, const float* __restrict__ Wk,
                          const float* __restrict__ Wv, const float* __restrict__ Wm,
                          const float* __restrict__ W1, const float* __restrict__ W2,
                          uint32_t* __restrict__ wh, uint32_t* __restrict__ wl) {
    int i = blockIdx.x * blockDim.x + threadIdx.x;
    if (i >= WTOT) return;
    const float* src;
    if (i < WMO) {
        int lyp  = i / 98304;
        int sub  = i % 98304;
        int which = sub / 32768;
        int woff  = sub % 32768;
        const float* base = (which == 0) ? Wq : (which == 1) ? Wk : Wv;
        src = base + (size_t)lyp * 65536 + (size_t)woff * 2;
    } else if (i < W1O) {
        src = Wm + (size_t)(i - WMO) * 2;
    } else if (i < W2O) {
        src = W1 + (size_t)(i - W1O) * 2;
    } else {
        src = W2 + (size_t)(i - W2O) * 2;
    }
    float2 v = *reinterpret_cast<const float2*>(src);
    uint32_t h, l;
    cvt_hl(v.x, v.y, h, l);
    wh[i] = h; wl[i] = l;
}

// ---------------- tensor-core bf16x3 GEMM (BN template, split-K via z) -------
// C = act(A @ B^T). K = loop extent (per z-slice), Krow = full row stride.
// blockIdx.z picks K-slice and C partial buffer (C + z*M*N).
template<int BN, int OUT>
__global__ __launch_bounds__(256)
void tc_gemm(const uint32_t* __restrict__ Ah, const uint32_t* __restrict__ Al,
             const uint32_t* __restrict__ A2h, const uint32_t* __restrict__ A2l,
             int nsplit,
             const uint32_t* __restrict__ Bh, const uint32_t* __restrict__ Bl,
             float* __restrict__ C, uint32_t* __restrict__ Oh, uint32_t* __restrict__ Ol,
             int M, int N, int K, int Krow)
{
    constexpr int WARPS_N = BN / 32;
    constexpr int WMX = 128 / (8 / WARPS_N);
    constexpr int MT = WMX / 16;
    constexpr int B_HI = BN * 48;
    constexpr int STAGE = 12288 + 2 * B_HI;

    extern __shared__ uint32_t smem[];
    const uint32_t sb0 = smem_u32(smem);

    const int m0 = blockIdx.y * 128;
    const int n0 = blockIdx.x * BN;
    const int kz = blockIdx.z;
    const int tid = threadIdx.x;
    const int wid = tid >> 5, lane = tid & 31;
    const int g = lane >> 2, tg = lane & 3;
    const int warp_m = wid / WARPS_N, warp_n = wid % WARPS_N;
    const int wm0 = warp_m * WMX, wn0 = warp_n * 32;
    const int Krow2 = Krow >> 1;
    const size_t kzoff = (size_t)kz * (K >> 1);

    const int rowa = tid >> 1, hw = (tid & 1) * 4;

    const int a_lrow = lane & 15;
    const int a_lcol = (lane >> 4) * 4;
    const int b_lrow = (lane & 7) + ((lane >> 4) << 3);
    const int b_lcol = ((lane >> 3) & 1) * 4;

    float acc[MT][4][4];
    #pragma unroll
    for (int i = 0; i < MT; i++)
        #pragma unroll
        for (int j = 0; j < 4; j++)
            #pragma unroll
            for (int r = 0; r < 4; r++) acc[i][j][r] = 0.f;

    const bool useA2 = (n0 >= nsplit);
    const uint32_t* Ab  = (useA2 ? A2h : Ah) + (size_t)(m0 + rowa) * Krow2 + hw + kzoff;
    const uint32_t* Alb = (useA2 ? A2l : Al) + (size_t)(m0 + rowa) * Krow2 + hw + kzoff;
    const uint32_t* Bb  = Bh + (size_t)(n0 + rowa) * Krow2 + hw + kzoff;
    const uint32_t* Blb = Bl + (size_t)(n0 + rowa) * Krow2 + hw + kzoff;
    C += (size_t)kz * M * N;

    const uint32_t dst_off = (uint32_t)(rowa * 12 + hw) * 4;
    const int nk = K >> 4;

    #define ISSUE(tile, stage) do {                                   \
        uint32_t sb = sb0 + (stage) * (uint32_t)STAGE;                \
        int ko = (tile) * 8;                                          \
        cp16(sb + dst_off,        Ab + ko);                           \
        cp16(sb + 6144 + dst_off, Alb + ko);                          \
        if (BN == 128 || tid < 128) {                                 \
            cp16(sb + 12288 + dst_off,        Bb + ko);               \
            cp16(sb + 12288 + B_HI + dst_off, Blb + ko);              \
        }                                                             \
    } while (0)

    #pragma unroll
    for (int s = 0; s < 3; s++) {
        if (s < nk) ISSUE(s, s);
        CP_COMMIT();
    }

    for (int kt = 0; kt < nk; kt++) {
        if (kt + 3 < nk) ISSUE(kt + 3, (kt + 3) & 3);
        CP_COMMIT();
        CP_WAIT(3);
        __syncthreads();

        const uint32_t sb = sb0 + (kt & 3) * (uint32_t)STAGE;
        uint32_t ah[MT][4], al[MT][4], bh2[4][2], bl2[4][2];
        #pragma unroll
        for (int mi = 0; mi < MT; mi++) {
            uint32_t woff = (uint32_t)((wm0 + mi*16 + a_lrow) * 12 + a_lcol) * 4;
            ldsm4(ah[mi], sb + woff);
            ldsm4(al[mi], sb + 6144 + woff);
        }
        #pragma unroll
        for (int p = 0; p < 2; p++) {
            uint32_t woff = (uint32_t)((wn0 + p*16 + b_lrow) * 12 + b_lcol) * 4;
            uint32_t r[4];
            ldsm4(r, sb + 12288 + woff);
            bh2[2*p][0] = r[0]; bh2[2*p][1] = r[1];
            bh2[2*p+1][0] = r[2]; bh2[2*p+1][1] = r[3];
            ldsm4(r, sb + 12288 + B_HI + woff);
            bl2[2*p][0] = r[0]; bl2[2*p][1] = r[1];
            bl2[2*p+1][0] = r[2]; bl2[2*p+1][1] = r[3];
        }
        #pragma unroll
        for (int mi = 0; mi < MT; mi++)
            #pragma unroll
            for (int ni = 0; ni < 4; ni++) {
                mma_bf16(acc[mi][ni], ah[mi], bh2[ni]);
                mma_bf16(acc[mi][ni], ah[mi], bl2[ni]);
                mma_bf16(acc[mi][ni], al[mi], bh2[ni]);
            }
        __syncthreads();
    }
    #undef ISSUE

    #pragma unroll
    for (int mi = 0; mi < MT; mi++) {
        #pragma unroll
        for (int ni = 0; ni < 4; ni++) {
            long long row0 = m0 + wm0 + mi * 16 + g;
            int col = n0 + wn0 + ni * 8 + tg * 2;
            if (OUT == 0) {
                *reinterpret_cast<float2*>(&C[row0 * N + col]) =
                    make_float2(acc[mi][ni][0], acc[mi][ni][1]);
                *reinterpret_cast<float2*>(&C[(row0 + 8) * N + col]) =
                    make_float2(acc[mi][ni][2], acc[mi][ni][3]);
            } else {
                float r[4];
                #pragma unroll
                for (int t = 0; t < 4; t++) {
                    float v = acc[mi][ni][t];
                    r[t] = 0.5f * v * (1.0f + erff(v * 0.70710678118654752f));
                }
                uint32_t h0, l0, h1, l1;
                cvt_hl(r[0], r[1], h0, l0);
                cvt_hl(r[2], r[3], h1, l1);
                size_t w0 = (size_t)(row0 * N + col) >> 1;
                size_t w1 = (size_t)((row0 + 8) * N + col) >> 1;
                Oh[w0] = h0; Ol[w0] = l0;
                Oh[w1] = h1; Ol[w1] = l1;
            }
        }
    }
}

// ---------------- fused flash attention (packed bf16 K/V, online softmax) ----
#define FA_SK 36
__global__ __launch_bounds__(256)
void k_flash(const float* __restrict__ qp,
             const uint32_t* __restrict__ kph, const uint32_t* __restrict__ kpl,
             const uint32_t* __restrict__ vph, const uint32_t* __restrict__ vpl,
             float* __restrict__ Og, int Tk)
{
    __shared__ uint32_t khw[64*FA_SK], klw[64*FA_SK];
    __shared__ uint32_t vhw[64*FA_SK], vlw[64*FA_SK];

    const int nh = blockIdx.y;
    const int q0 = blockIdx.x * 128;
    const int tid = threadIdx.x, wid = tid >> 5, lane = tid & 31;
    const int g = lane >> 2, tg = lane & 3;

    const float* Qb = qp + ((size_t)nh * LTOK + q0) * HD;
    const uint32_t* Kh = kph + (size_t)nh * Tk * 32;
    const uint32_t* Kl = kpl + (size_t)nh * Tk * 32;
    const uint32_t* Vh = vph + (size_t)nh * HD * (Tk >> 1);
    const uint32_t* Vl = vpl + (size_t)nh * HD * (Tk >> 1);

    const int row0 = wid * 16 + g;
    uint32_t qh[4][4], ql[4][4];
    #pragma unroll
    for (int kk = 0; kk < 4; kk++) {
        int col = kk * 16 + tg * 2;
        float2 q00 = *reinterpret_cast<const float2*>(&Qb[(size_t)row0 * HD + col]);
        float2 q01 = *reinterpret_cast<const float2*>(&Qb[(size_t)row0 * HD + col + 8]);
        float2 q10 = *reinterpret_cast<const float2*>(&Qb[(size_t)(row0 + 8) * HD + col]);
        float2 q11 = *reinterpret_cast<const float2*>(&Qb[(size_t)(row0 + 8) * HD + col + 8]);
        cvt_hl(q00.x * 0.125f, q00.y * 0.125f, qh[kk][0], ql[kk][0]);
        cvt_hl(q10.x * 0.125f, q10.y * 0.125f, qh[kk][1], ql[kk][1]);
        cvt_hl(q01.x * 0.125f, q01.y * 0.125f, qh[kk][2], ql[kk][2]);
        cvt_hl(q11.x * 0.125f, q11.y * 0.125f, qh[kk][3], ql[kk][3]);
    }

    float m0 = -1e30f, m1 = -1e30f, l0 = 0.f, l1 = 0.f;
    float oacc[8][4];
    #pragma unroll
    for (int i = 0; i < 8; i++)
        #pragma unroll
        for (int t = 0; t < 4; t++) oacc[i][t] = 0.f;

    const int r = tid >> 2, c2 = (tid & 3) * 8;     // word col
    uint4 kh0, kh1, kl0, kl1, vh0, vh1, vl0, vl1;
    {
        const uint32_t* sk = Kh + (size_t)r * 32 + c2;
        const uint32_t* sl = Kl + (size_t)r * 32 + c2;
        const uint32_t* tv = Vh + (size_t)r * (Tk >> 1) + c2;
        const uint32_t* tl = Vl + (size_t)r * (Tk >> 1) + c2;
        kh0 = *reinterpret_cast<const uint4*>(sk);
        kh1 = *reinterpret_cast<const uint4*>(sk + 4);
        kl0 = *reinterpret_cast<const uint4*>(sl);
        kl1 = *reinterpret_cast<const uint4*>(sl + 4);
        vh0 = *reinterpret_cast<const uint4*>(tv);
        vh1 = *reinterpret_cast<const uint4*>(tv + 4);
        vl0 = *reinterpret_cast<const uint4*>(tl);
        vl1 = *reinterpret_cast<const uint4*>(tl + 4);
    }

    for (int kv0 = 0; kv0 < Tk; kv0 += 64) {
        {
            int w = r * FA_SK + c2;
            *reinterpret_cast<uint4*>(&khw[w]) = kh0;
            *reinterpret_cast<uint4*>(&khw[w + 4]) = kh1;
            *reinterpret_cast<uint4*>(&klw[w]) = kl0;
            *reinterpret_cast<uint4*>(&klw[w + 4]) = kl1;
            *reinterpret_cast<uint4*>(&vhw[w]) = vh0;
            *reinterpret_cast<uint4*>(&vhw[w + 4]) = vh1;
            *reinterpret_cast<uint4*>(&vlw[w]) = vl0;
            *reinterpret_cast<uint4*>(&vlw[w + 4]) = vl1;
        }
        __syncthreads();

        if (kv0 + 64 < Tk) {
            const uint32_t* sk = Kh + (size_t)(kv0 + 64 + r) * 32 + c2;
            const uint32_t* sl = Kl + (size_t)(kv0 + 64 + r) * 32 + c2;
            const uint32_t* tv = Vh + (size_t)r * (Tk >> 1) + ((kv0 + 64) >> 1) + c2;
            const uint32_t* tl = Vl + (size_t)r * (Tk >> 1) + ((kv0 + 64) >> 1) + c2;
            kh0 = *reinterpret_cast<const uint4*>(sk);
            kh1 = *reinterpret_cast<const uint4*>(sk + 4);
            kl0 = *reinterpret_cast<const uint4*>(sl);
            kl1 = *reinterpret_cast<const uint4*>(sl + 4);
            vh0 = *reinterpret_cast<const uint4*>(tv);
            vh1 = *reinterpret_cast<const uint4*>(tv + 4);
            vl0 = *reinterpret_cast<const uint4*>(tl);
            vl1 = *reinterpret_cast<const uint4*>(tl + 4);
        }

        float sacc[8][4];
        #pragma unroll
        for (int i = 0; i < 8; i++)
            #pragma unroll
            for (int t = 0; t < 4; t++) sacc[i][t] = 0.f;
        #pragma unroll
        for (int kk = 0; kk < 4; kk++) {
            #pragma unroll
            for (int ni = 0; ni < 8; ni++) {
                uint32_t bh[2], bl[2];
                int off = (ni * 8 + g) * FA_SK + kk * 8 + tg;
                bh[0] = khw[off]; bh[1] = khw[off + 4];
                bl[0] = klw[off]; bl[1] = klw[off + 4];
                mma_bf16(sacc[ni], qh[kk], bh);
                mma_bf16(sacc[ni], qh[kk], bl);
                mma_bf16(sacc[ni], ql[kk], bh);
            }
        }

        float mx0 = -1e30f, mx1 = -1e30f;
        #pragma unroll
        for (int ni = 0; ni < 8; ni++) {
            mx0 = fmaxf(mx0, fmaxf(sacc[ni][0], sacc[ni][1]));
            mx1 = fmaxf(mx1, fmaxf(sacc[ni][2], sacc[ni][3]));
        }
        mx0 = fmaxf(mx0, __shfl_xor_sync(0xffffffff, mx0, 1));
        mx0 = fmaxf(mx0, __shfl_xor_sync(0xffffffff, mx0, 2));
        mx1 = fmaxf(mx1, __shfl_xor_sync(0xffffffff, mx1, 1));
        mx1 = fmaxf(mx1, __shfl_xor_sync(0xffffffff, mx1, 2));
        float nm0 = fmaxf(m0, mx0), nm1 = fmaxf(m1, mx1);
        float al0 = __expf(m0 - nm0), al1 = __expf(m1 - nm1);
        float rs0 = 0.f, rs1 = 0.f;
        #pragma unroll
        for (int ni = 0; ni < 8; ni++) {
            sacc[ni][0] = __expf(sacc[ni][0] - nm0);
            sacc[ni][1] = __expf(sacc[ni][1] - nm0);
            sacc[ni][2] = __expf(sacc[ni][2] - nm1);
            sacc[ni][3] = __expf(sacc[ni][3] - nm1);
            rs0 += sacc[ni][0] + sacc[ni][1];
            rs1 += sacc[ni][2] + sacc[ni][3];
        }
        rs0 += __shfl_xor_sync(0xffffffff, rs0, 1);
        rs0 += __shfl_xor_sync(0xffffffff, rs0, 2);
        rs1 += __shfl_xor_sync(0xffffffff, rs1, 1);
        rs1 += __shfl_xor_sync(0xffffffff, rs1, 2);
        l0 = l0 * al0 + rs0;  l1 = l1 * al1 + rs1;
        m0 = nm0;  m1 = nm1;
        #pragma unroll
        for (int nd = 0; nd < 8; nd++) {
            oacc[nd][0] *= al0; oacc[nd][1] *= al0;
            oacc[nd][2] *= al1; oacc[nd][3] *= al1;
        }

        #pragma unroll
        for (int kk = 0; kk < 4; kk++) {
            uint32_t ph[4], pl[4];
            cvt_hl(sacc[2*kk][0],   sacc[2*kk][1],   ph[0], pl[0]);
            cvt_hl(sacc[2*kk][2],   sacc[2*kk][3],   ph[1], pl[1]);
            cvt_hl(sacc[2*kk+1][0], sacc[2*kk+1][1], ph[2], pl[2]);
            cvt_hl(sacc[2*kk+1][2], sacc[2*kk+1][3], ph[3], pl[3]);
            #pragma unroll
            for (int nd = 0; nd < 8; nd++) {
                uint32_t vh[2], vl[2];
                int off = (nd * 8 + g) * FA_SK + kk * 8 + tg;
                vh[0] = vhw[off]; vh[1] = vhw[off + 4];
                vl[0] = vlw[off]; vl[1] = vlw[off + 4];
                mma_bf16(oacc[nd], ph, vh);
                mma_bf16(oacc[nd], ph, vl);
                mma_bf16(oacc[nd], pl, vh);
            }
        }
        __syncthreads();
    }

    float il0 = 1.0f / l0, il1 = 1.0f / l1;
    float* Ob = Og + ((size_t)nh * LTOK + q0) * HD;
    #pragma unroll
    for (int nd = 0; nd < 8; nd++) {
        int col = nd * 8 + tg * 2;
        *reinterpret_cast<float2*>(&Ob[(size_t)row0 * HD + col]) =
            make_float2(oacc[nd][0] * il0, oacc[nd][1] * il0);
        *reinterpret_cast<float2*>(&Ob[(size_t)(row0 + 8) * HD + col]) =
            make_float2(oacc[nd][2] * il1, oacc[nd][3] * il1);
    }
}

// ---------------- layout kernels ----------------
__global__ void k_build_x(const float* __restrict__ f, float* __restrict__ x,
                          uint32_t* __restrict__ xh, uint32_t* __restrict__ xl,
                          uint32_t* __restrict__ xph, uint32_t* __restrict__ xpl) {
    int idx = blockIdx.x * blockDim.x + threadIdx.x;
    if (idx >= XW) return;
    int c2 = idx & 127;
    int l  = (idx >> 7) & (LTOK-1);
    int n  = idx >> 17;
    int c  = c2 * 2;
    float a = f[((size_t)n*CC + c)*LTOK + l];
    float b = f[((size_t)n*CC + c + 1)*LTOK + l];
    reinterpret_cast<float2*>(x)[idx] = make_float2(a, b);
    uint32_t h, lw;
    cvt_hl(a, b, h, lw);
    xh[idx] = h; xl[idx] = lw;
    xph[idx] = h; xpl[idx] = lw;
}

__global__ void k_final(const float* __restrict__ x, float* __restrict__ o) {
    int idx = blockIdx.x * blockDim.x + threadIdx.x;
    if (idx >= ROWS_*CC) return;
    int l = idx & (LTOK-1);
    int c = (idx >> 10) & (CC-1);
    int n = idx >> 18;
    o[idx] = x[((size_t)n*LTOK + l)*CC + c];
}

// ---------------- PRoPE matrix build ----------------
__device__ __forceinline__ void prope_forward(const float* vm, const float* Kc,
                                              float u, float vyy, float* M) {
    float fx = Kc[0] * (1.0f/128.0f), fy = Kc[4] * (1.0f/128.0f);
    float cx = Kc[2] * (1.0f/128.0f), cy = Kc[5] * (1.0f/128.0f);
    float a = cx - u, b = cy - vyy;
    #pragma unroll
    for (int c = 0; c < 4; c++) {
        M[0*4+c] = fx*vm[0*4+c] + a*vm[2*4+c];
        M[1*4+c] = fy*vm[1*4+c] + b*vm[2*4+c];
        M[2*4+c] = vm[2*4+c];
        M[3*4+c] = vm[3*4+c];
    }
}

__global__ void k_prope_q(const float* __restrict__ vms, const float* __restrict__ Ks,
                          float* __restrict__ Mq, float* __restrict__ Mqi) {
    int idx = blockIdx.x * blockDim.x + threadIdx.x;
    if (idx >= NVB*LTOK) return;
    int n = idx >> 10, t = idx & (LTOK-1);
    int px = t & 31, py = t >> 5;
    float u  = (px + 0.5f) * (1.0f/32.0f);
    float vy = (py + 0.5f) * (1.0f/32.0f);
    const float* vm = vms + n*16;
    const float* Kc = Ks + n*9;
    float M[16];
    prope_forward(vm, Kc, u, vy, M);
    #pragma unroll
    for (int i = 0; i < 16; i++) Mq[idx*16+i] = M[i];

    float r00=vm[0],r01=vm[1],r02=vm[2],  t0=vm[3];
    float r10=vm[4],r11=vm[5],r12=vm[6],  t1=vm[7];
    float r20=vm[8],r21=vm[9],r22=vm[10], t2=vm[11];
    float det = r00*(r11*r22-r12*r21) - r01*(r10*r22-r12*r20) + r02*(r10*r21-r11*r20);
    float id = 1.0f/det;
    float Ri[9];
    Ri[0]=(r11*r22-r12*r21)*id; Ri[1]=(r02*r21-r01*r22)*id; Ri[2]=(r01*r12-r02*r11)*id;
    Ri[3]=(r12*r20-r10*r22)*id; Ri[4]=(r00*r22-r02*r20)*id; Ri[5]=(r02*r10-r00*r12)*id;
    Ri[6]=(r10*r21-r11*r20)*id; Ri[7]=(r01*r20-r00*r21)*id; Ri[8]=(r00*r11-r01*r10)*id;
    float ti0 = -(Ri[0]*t0 + Ri[1]*t1 + Ri[2]*t2);
    float ti1 = -(Ri[3]*t0 + Ri[4]*t1 + Ri[5]*t2);
    float ti2 = -(Ri[6]*t0 + Ri[7]*t1 + Ri[8]*t2);
    float fx = Kc[0]*(1.0f/128.0f), fy = Kc[4]*(1.0f/128.0f);
    float cx = Kc[2]*(1.0f/128.0f), cy = Kc[5]*(1.0f/128.0f);
    float a = cx - u, b = cy - vy;
    float ifx = 1.0f/fx, ify = 1.0f/fy;
    float Mi[16];
    float tv[3] = {ti0, ti1, ti2};
    #pragma unroll
    for (int i = 0; i < 3; i++) {
        Mi[i*4+0] = Ri[i*3+0]*ifx;
        Mi[i*4+1] = Ri[i*3+1]*ify;
        Mi[i*4+2] = -Ri[i*3+0]*a*ifx - Ri[i*3+1]*b*ify + Ri[i*3+2];
        Mi[i*4+3] = tv[i];
    }
    Mi[12]=0.f; Mi[13]=0.f; Mi[14]=0.f; Mi[15]=1.f;
    #pragma unroll
    for (int i = 0; i < 16; i++) Mqi[idx*16+i] = Mi[i];
}

__global__ void k_prope_kv(const float* __restrict__ vms, const float* __restrict__ Ks,
                           float* __restrict__ Mkv) {
    int idx = blockIdx.x * blockDim.x + threadIdx.x;
    if (idx >= NVB*TKX) return;
    int n = idx >> 11, tt = idx & (TKX-1);
    int m = tt >> 10, l = tt & (LTOK-1);
    int vvi = n >> 1, b = n & 1;
    int j = m + (m >= vvi ? 1 : 0);
    int cam = j*BB + b;
    int px = l & 31, py = l >> 5;
    float u  = (px + 0.5f)*(1.0f/32.0f);
    float vy = (py + 0.5f)*(1.0f/32.0f);
    float M[16];
    prope_forward(vms + cam*16, Ks + cam*9, u, vy, M);
    #pragma unroll
    for (int i = 0; i < 16; i++) Mkv[idx*16+i] = M[i];
}

// ---------------- fused per-token applies (packed K/V outputs) ---------------
__global__ void k_apply_all(const float* __restrict__ qkv, int stride,
                            const float* __restrict__ Mqi, const float* __restrict__ Mats,
                            float* __restrict__ qp,
                            uint32_t* __restrict__ kph, uint32_t* __restrict__ kpl,
                            uint32_t* __restrict__ vph, uint32_t* __restrict__ vpl,
                            int Tk, int gather, int nkv)
{
    int idx = blockIdx.x * blockDim.x + threadIdx.x;
    if (idx < NAPP) {
        int g = idx & 15, h = (idx >> 4) & 3, t = (idx >> 6) & (LTOK-1), n = idx >> 16;
        const float* M = Mqi + ((size_t)(n*LTOK + t))*16;
        const float* s = qkv + ((size_t)(n*LTOK + t))*stride + h*HD + g*4;
        float x0=s[0], x1=s[1], x2=s[2], x3=s[3];
        float* d = qp + (((size_t)(n*NH + h))*LTOK + t)*HD + g*4;
        #pragma unroll
        for (int i = 0; i < 4; i++)
            d[i] = M[0*4+i]*x0 + M[1*4+i]*x1 + M[2*4+i]*x2 + M[3*4+i]*x3;
    } else if (idx < NAPP + nkv) {
        int i2 = idx - NAPP;
        int g = i2 & 15, h = (i2 >> 4) & 3;
        int tt = (i2 >> 6) % Tk, n = (i2 >> 6) / Tk;
        size_t srcRow;
        if (gather) {
            int m = tt >> 10, l = tt & (LTOK-1);
            int vvi = n >> 1, b = n & 1;
            int j = m + (m >= vvi ? 1 : 0);
            srcRow = (size_t)(j*BB + b)*LTOK + l;
        } else {
            srcRow = (size_t)n*LTOK + tt;
        }
        const float* M = Mats + ((size_t)n*Tk + tt)*16;
        const float* s = qkv + srcRow*stride + 256 + h*HD + g*4;
        float x0=s[0], x1=s[1], x2=s[2], x3=s[3];
        float d[4];
        #pragma unroll
        for (int i = 0; i < 4; i++)
            d[i] = M[i*4+0]*x0 + M[i*4+1]*x1 + M[i*4+2]*x2 + M[i*4+3]*x3;
        size_t wb = (((size_t)(n*NH + h))*Tk + tt)*32 + g*2;
        uint32_t h0, l0, h1, l1;
        cvt_hl(d[0], d[1], h0, l0);
        cvt_hl(d[2], d[3], h1, l1);
        kph[wb] = h0;   kpl[wb] = l0;
        kph[wb+1] = h1; kpl[wb+1] = l1;
    } else if (idx < NAPP + 2*nkv) {
        int i2 = idx - NAPP - nkv;
        int tt = i2 % Tk;
        int rest = i2 / Tk;
        int g = rest & 15, h = (rest >> 4) & 3, n = rest >> 6;
        size_t srcRow;
        if (gather) {
            int m = tt >> 10, l = tt & (LTOK-1);
            int vvi = n >> 1, b = n & 1;
            int j = m + (m >= vvi ? 1 : 0);
            srcRow = (size_t)(j*BB + b)*LTOK + l;
        } else {
            srcRow = (size_t)n*LTOK + tt;
        }
        const float* M = Mats + ((size_t)n*Tk + tt)*16;
        const float* s = qkv + srcRow*stride + 512 + h*HD + g*4;
        float x0=s[0], x1=s[1], x2=s[2], x3=s[3];
        #pragma unroll
        for (int i = 0; i < 4; i++) {
            float v = M[i*4+0]*x0 + M[i*4+1]*x1 + M[i*4+2]*x2 + M[i*4+3]*x3;
            float vn = __shfl_down_sync(0xffffffff, v, 1);
            if ((tt & 1) == 0) {
                uint32_t hh2, ll2;
                cvt_hl(v, vn, hh2, ll2);
                size_t wb = ((size_t)(n*NH + h)*HD + g*4 + i)*(Tk >> 1) + (tt >> 1);
                vph[wb] = hh2; vpl[wb] = ll2;
            }
        }
    }
}

__global__ void k_apply_out(const float* __restrict__ O, const float* __restrict__ Mi,
                            uint32_t* __restrict__ omh, uint32_t* __restrict__ oml) {
    int idx = blockIdx.x * blockDim.x + threadIdx.x;
    if (idx >= NAPP) return;
    int g = idx & 15, h = (idx >> 4) & 3, t = (idx >> 6) & (LTOK-1), n = idx >> 16;
    const float* M = Mi + ((size_t)(n*LTOK + t))*16;
    const float* s = O + (((size_t)(n*NH + h))*LTOK + t)*HD + g*4;
    float x0=s[0], x1=s[1], x2=s[2], x3=s[3];
    float d[4];
    #pragma unroll
    for (int i = 0; i < 4; i++)
        d[i] = M[i*4+0]*x0 + M[i*4+1]*x1 + M[i*4+2]*x2 + M[i*4+3]*x3;
    size_t w = (((size_t)(n*LTOK + t))*CC + h*HD + g*4) >> 1;
    uint32_t h0, l0, h1, l1;
    cvt_hl(d[0], d[1], h0, l0);
    cvt_hl(d[2], d[3], h1, l1);
    omh[w] = h0;   oml[w] = l0;
    omh[w+1] = h1; oml[w+1] = l1;
}

// ---------------- layernorm (src may be split partial sum) ----------------
__global__ void k_ln(float* __restrict__ dst, const float* __restrict__ src,
                     const float* __restrict__ src2,
                     const float* __restrict__ w, const float* __restrict__ b, int add,
                     uint32_t* __restrict__ oh, uint32_t* __restrict__ ol,
                     uint32_t* __restrict__ oh2, uint32_t* __restrict__ ol2) {
    __shared__ float red[256];
    int row = blockIdx.x, tid = threadIdx.x;
    float v = src[(size_t)row*CC + tid];
    if (src2) v += src2[(size_t)row*CC + tid];
    red[tid] = v; __syncthreads();
    for (int s = 128; s > 0; s >>= 1) { if (tid < s) red[tid] += red[tid+s]; __syncthreads(); }
    float mu = red[0] * (1.0f/CC); __syncthreads();
    float d = v - mu;
    red[tid] = d * d; __syncthreads();
    for (int s = 128; s > 0; s >>= 1) { if (tid < s) red[tid] += red[tid+s]; __syncthreads(); }
    float var = red[0] * (1.0f/CC);
    float o = d * rsqrtf(var + 1e-5f) * w[tid] + b[tid];
    float fin;
    if (add) { fin = dst[(size_t)row*CC + tid] + o; dst[(size_t)row*CC + tid] = fin; }
    else     { fin = o; dst[(size_t)row*CC + tid] = fin; }
    if (oh) {
        __syncthreads();
        red[tid] = fin;
        __syncthreads();
        if (tid < 128) {
            uint32_t h, l;
            cvt_hl(red[2*tid], red[2*tid+1], h, l);
            oh[(size_t)row*(CC/2) + tid] = h;
            ol[(size_t)row*(CC/2) + tid] = l;
            if (oh2) {
                oh2[(size_t)row*(CC/2) + tid] = h;
                ol2[(size_t)row*(CC/2) + tid] = l;
            }
        }
    }
}

// ---------------- concat -> bf16 hi/lo ----------------
__global__ void k_cat(const float* __restrict__ x, const float* __restrict__ msg,
                      uint32_t* __restrict__ ch, uint32_t* __restrict__ cl) {
    int idx = blockIdx.x * blockDim.x + threadIdx.x;
    if (idx >= ROWS_*(FFNI/2)) return;
    int c2 = idx & 255, row = idx >> 8;
    float2 v;
    if (c2 < 128) v = reinterpret_cast<const float2*>(x + (size_t)row*CC)[c2];
    else          v = reinterpret_cast<const float2*>(msg + (size_t)row*CC)[c2 - 128];
    uint32_t h, l;
    cvt_hl(v.x, v.y, h, l);
    ch[idx] = h; cl[idx] = l;
}

// ---------------- host driver ----------------
static const int GSMEM128 = 98304;
static const int GSMEM64  = 73728;

static void gemm128(const uint32_t* Ah, const uint32_t* Al,
                    const uint32_t* A2h, const uint32_t* A2l, int nsplit,
                    const uint32_t* Bh, const uint32_t* Bl,
                    float* C, int M, int N, int K) {
    dim3 g(N/128, M/128, 1);
    tc_gemm<128,0><<<g, 256, GSMEM128>>>(Ah, Al, A2h, A2l, nsplit, Bh, Bl,
                                         C, nullptr, nullptr, M, N, K, K);
}
// split-K x2: writes partials to C[0..M*N) and C[M*N..2*M*N)
static void gemm64s(const uint32_t* Ah, const uint32_t* Al,
                    const uint32_t* Bh, const uint32_t* Bl,
                    float* C, int M, int N, int Ktot) {
    dim3 g(N/64, M/128, 2);
    tc_gemm<64,0><<<g, 256, GSMEM64>>>(Ah, Al, Ah, Al, 1<<30, Bh, Bl,
                                       C, nullptr, nullptr, M, N, Ktot/2, Ktot);
}
static void gemm_gelu_hl(const uint32_t* Ah, const uint32_t* Al,
                         const uint32_t* Bh, const uint32_t* Bl,
                         uint32_t* Oh, uint32_t* Ol, int M, int N, int K) {
    dim3 g(N/128, M/128, 1);
    tc_gemm<128,1><<<g, 256, GSMEM128>>>(Ah, Al, Ah, Al, 1<<30, Bh, Bl,
                                         nullptr, Oh, Ol, M, N, K, K);
}

extern "C" void kernel_launch(void* const* d_in, const int* in_sizes, int n_in,
                              void* d_out, int out_size) {
    const float* feats = (const float*)d_in[0];
    const float* vms   = (const float*)d_in[1];
    const float* Ks    = (const float*)d_in[2];
    const float* Wq    = (const float*)d_in[3];
    const float* Wk    = (const float*)d_in[4];
    const float* Wv    = (const float*)d_in[5];
    const float* Wm    = (const float*)d_in[6];
    const float* n1w   = (const float*)d_in[7];
    const float* n1b   = (const float*)d_in[8];
    const float* W1    = (const float*)d_in[9];
    const float* W2    = (const float*)d_in[10];
    const float* n2w   = (const float*)d_in[11];
    const float* n2b   = (const float*)d_in[12];

    cudaFuncSetAttribute(tc_gemm<128,0>, cudaFuncAttributeMaxDynamicSharedMemorySize, GSMEM128);
    cudaFuncSetAttribute(tc_gemm<128,1>, cudaFuncAttributeMaxDynamicSharedMemorySize, GSMEM128);
    cudaFuncSetAttribute(tc_gemm<64,0>,  cudaFuncAttributeMaxDynamicSharedMemorySize, GSMEM64);

    void* p;
    float *x,*qkv,*qp,*O,*msg,*msg2,*h22,*Mq,*Mqi,*Mkv;
    uint32_t *kph,*kpl,*vph,*vpl;
    uint32_t *xh,*xl,*xpreh,*xprel,*omh,*oml,*cath,*catl,*hh,*hl,*wh,*wl;
    cudaGetSymbolAddress(&p, g_x);    x   = (float*)p;
    cudaGetSymbolAddress(&p, g_qkv);  qkv = (float*)p;
    cudaGetSymbolAddress(&p, g_qp);   qp  = (float*)p;
    cudaGetSymbolAddress(&p, g_kph);  kph = (uint32_t*)p;
    cudaGetSymbolAddress(&p, g_kpl);  kpl = (uint32_t*)p;
    cudaGetSymbolAddress(&p, g_vph);  vph = (uint32_t*)p;
    cudaGetSymbolAddress(&p, g_vpl);  vpl = (uint32_t*)p;
    cudaGetSymbolAddress(&p, g_O);    O   = (float*)p;
    cudaGetSymbolAddress(&p, g_msg);  msg = (float*)p;
    cudaGetSymbolAddress(&p, g_msg2); msg2= (float*)p;
    cudaGetSymbolAddress(&p, g_h22);  h22 = (float*)p;
    cudaGetSymbolAddress(&p, g_Mq);   Mq  = (float*)p;
    cudaGetSymbolAddress(&p, g_Mqi);  Mqi = (float*)p;
    cudaGetSymbolAddress(&p, g_Mkv);  Mkv = (float*)p;
    cudaGetSymbolAddress(&p, g_xh);    xh    = (uint32_t*)p;
    cudaGetSymbolAddress(&p, g_xl);    xl    = (uint32_t*)p;
    cudaGetSymbolAddress(&p, g_xpreh); xpreh = (uint32_t*)p;
    cudaGetSymbolAddress(&p, g_xprel); xprel = (uint32_t*)p;
    cudaGetSymbolAddress(&p, g_omh);   omh   = (uint32_t*)p;
    cudaGetSymbolAddress(&p, g_oml);   oml   = (uint32_t*)p;
    cudaGetSymbolAddress(&p, g_cath);  cath  = (uint32_t*)p;
    cudaGetSymbolAddress(&p, g_catl);  catl  = (uint32_t*)p;
    cudaGetSymbolAddress(&p, g_hh);    hh    = (uint32_t*)p;
    cudaGetSymbolAddress(&p, g_hl);    hl    = (uint32_t*)p;
    cudaGetSymbolAddress(&p, g_wh);    wh    = (uint32_t*)p;
    cudaGetSymbolAddress(&p, g_wl);    wl    = (uint32_t*)p;

    const int ROWS = ROWS_;
    const int NEL  = ROWS * CC;
    const int NKV_SELF  = NAPP;
    const int NKV_CROSS = NVB*TKX*NH*16;

    k_cvt_all<<<WTOT/256, 256>>>(Wq, Wk, Wv, Wm, W1, W2, wh, wl);
    k_build_x<<<(XW+255)/256, 256>>>(feats, x, xh, xl, xpreh, xprel);
    k_prope_q<<<(ROWS+255)/256, 256>>>(vms, Ks, Mq, Mqi);
    k_prope_kv<<<(NVB*TKX+255)/256, 256>>>(vms, Ks, Mkv);

    for (int ly = 0; ly < 2; ly++) {
        // ---------- self attention ----------
        gemm128(xh, xl, xh, xl, 1<<30,
                wh + WQKV0 + (ly*2+0)*98304, wl + WQKV0 + (ly*2+0)*98304,
                qkv, ROWS, 768, CC);
        k_apply_all<<<(NAPP + 2*NKV_SELF)/256, 256>>>(
            qkv, 768, Mqi, Mq, qp, kph, kpl, vph, vpl, LTOK, 0, NKV_SELF);
        k_flash<<<dim3(LTOK/128, NVB*NH), 256>>>(qp, kph, kpl, vph, vpl, O, LTOK);
        k_apply_out<<<NAPP/256, 256>>>(O, Mqi, omh, oml);
        gemm64s(omh, oml, wh + WMO + (ly*2+0)*32768, wl + WMO + (ly*2+0)*32768,
                msg2, ROWS, CC, CC);
        k_ln<<<ROWS, 256>>>(x, msg2, msg2 + NEL, n1w + (ly*2+0)*CC, n1b + (ly*2+0)*CC, 1,
                            xh, xl, nullptr, nullptr);

        // ---------- cross attention ----------
        gemm128(xh, xl, xpreh, xprel, 256,
                wh + WQKV0 + (ly*2+1)*98304, wl + WQKV0 + (ly*2+1)*98304,
                qkv, ROWS, 768, CC);
        k_apply_all<<<(NAPP + 2*NKV_CROSS)/256, 256>>>(
            qkv, 768, Mqi, Mkv, qp, kph, kpl, vph, vpl, TKX, 1, NKV_CROSS);
        k_flash<<<dim3(LTOK/128, NVB*NH), 256>>>(qp, kph, kpl, vph, vpl, O, TKX);
        k_apply_out<<<NAPP/256, 256>>>(O, Mqi, omh, oml);
        gemm64s(omh, oml, wh + WMO + (ly*2+1)*32768, wl + WMO + (ly*2+1)*32768,
                msg2, ROWS, CC, CC);
        k_ln<<<ROWS, 256>>>(msg, msg2, msg2 + NEL, n1w + (ly*2+1)*CC, n1b + (ly*2+1)*CC, 0,
                            nullptr, nullptr, nullptr, nullptr);

        // ---------- FFN ----------
        k_cat<<<(ROWS*(FFNI/2))/256, 256>>>(x, msg, cath, catl);
        gemm_gelu_hl(cath, catl,
                     wh + W1O + (size_t)ly*524288, wl + W1O + (size_t)ly*524288,
                     hh, hl, ROWS, FFNH, FFNI);
        gemm64s(hh, hl, wh + W2O + (size_t)ly*262144, wl + W2O + (size_t)ly*262144,
                h22, ROWS, CC, FFNH);
        k_ln<<<ROWS, 256>>>(x, h22, h22 + NEL, n2w + ly*CC, n2b + ly*CC, 1,
                            xh, xl, xpreh, xprel);
    }

    k_final<<<(NEL+255)/256, 256>>>(x, (float*)d_out);
}

// round 13
// speedup vs baseline: 1.1200x; 1.0016x over previous
#include <cuda_runtime.h>
#include <cuda_bf16.h>
#include <math.h>
#include <stdint.h>

// ---------------- problem constants ----------------
#define NVB   6
#define VV    3
#define BB    2
#define CC    256
#define LTOK  1024
#define TKX   2048
#define NH    4
#define HD    64
#define FFNI  512
#define FFNH  2048

#define ROWS_ (NVB*LTOK)          // 6144
#define XW    (NVB*LTOK*CC/2)
#define NAPP  (NVB*LTOK*NH*16)    // 393216

// ---------------- device scratch ----------------
__device__ float g_x   [ROWS_*CC];
__device__ float g_qkv [ROWS_*768];
__device__ float g_qp  [NVB*NH*LTOK*HD];
__device__ uint32_t g_kph[NVB*NH*TKX*HD/2], g_kpl[NVB*NH*TKX*HD/2];
__device__ uint32_t g_vph[NVB*NH*TKX*HD/2], g_vpl[NVB*NH*TKX*HD/2];  // V^T packed
__device__ float g_O   [NVB*NH*LTOK*HD];
__device__ float g_msg [ROWS_*CC];
__device__ float g_msg2[2*ROWS_*CC];          // split-K partials (msg)
__device__ float g_h22 [4*ROWS_*CC];          // split-K partials (W2, x4)
__device__ float g_Mq  [NVB*LTOK*16];
__device__ float g_Mqi [NVB*LTOK*16];
__device__ float g_Mkv [NVB*TKX*16];

__device__ uint32_t g_xh   [XW],  g_xl   [XW];
__device__ uint32_t g_xpreh[XW],  g_xprel[XW];
__device__ uint32_t g_omh  [XW],  g_oml  [XW];
__device__ uint32_t g_cath [ROWS_*FFNI/2], g_catl[ROWS_*FFNI/2];
__device__ uint32_t g_hh   [ROWS_*FFNH/2], g_hl  [ROWS_*FFNH/2];
#define WQKV0 0
#define WMO   393216
#define W1O   524288
#define W2O   1572864
#define WTOT  2097152
__device__ uint32_t g_wh[WTOT], g_wl[WTOT];

// ---------------- helpers ----------------
__device__ __forceinline__ void cvt_hl(float x, float y, uint32_t& hi, uint32_t& lo) {
    __nv_bfloat162 h = __floats2bfloat162_rn(x, y);
    float rx = x - __bfloat162float(h.x);
    float ry = y - __bfloat162float(h.y);
    __nv_bfloat162 l = __floats2bfloat162_rn(rx, ry);
    hi = *reinterpret_cast<uint32_t*>(&h);
    lo = *reinterpret_cast<uint32_t*>(&l);
}

__device__ __forceinline__ void mma_bf16(float* c, const uint32_t* a, const uint32_t* b) {
    asm volatile(
        "mma.sync.aligned.m16n8k16.row.col.f32.bf16.bf16.f32 "
        "{%0,%1,%2,%3}, {%4,%5,%6,%7}, {%8,%9}, {%0,%1,%2,%3};"
        : "+f"(c[0]), "+f"(c[1]), "+f"(c[2]), "+f"(c[3])
        : "r"(a[0]), "r"(a[1]), "r"(a[2]), "r"(a[3]), "r"(b[0]), "r"(b[1]));
}

__device__ __forceinline__ void ldsm4(uint32_t* r, uint32_t addr) {
    asm volatile("ldmatrix.sync.aligned.m8n8.x4.shared.b16 {%0,%1,%2,%3}, [%4];"
        : "=r"(r[0]), "=r"(r[1]), "=r"(r[2]), "=r"(r[3]) : "r"(addr));
}

__device__ __forceinline__ uint32_t smem_u32(const void* p) {
    uint32_t a;
    asm("{ .reg .u64 t; cvta.to.shared.u64 t, %1; cvt.u32.u64 %0, t; }" : "=r"(a) : "l"(p));
    return a;
}

__device__ __forceinline__ void cp16(uint32_t smem, const void* g) {
    asm volatile("cp.async.cg.shared.global [%0], [%1], 16;" :: "r"(smem), "l"(g));
}
#define CP_COMMIT() asm volatile("cp.async.commit_group;")
#define CP_WAIT(N)  asm volatile("cp.async.wait_group %0;" :: "n"(N))

// ---------------- all-weight conversion + QKV repack ----------------
__global__ void k_cvt_all(const float* __restrict__ Wq, const float* __restrict__ Wk,
                          const float* __restrict__ Wv, const float* __restrict__ Wm,
                          const float* __restrict__ W1, const float* __restrict__ W2,
                          uint32_t* __restrict__ wh, uint32_t* __restrict__ wl) {
    int i = blockIdx.x * blockDim.x + threadIdx.x;
    if (i >= WTOT) return;
    const float* src;
    if (i < WMO) {
        int lyp  = i / 98304;
        int sub  = i % 98304;
        int which = sub / 32768;
        int woff  = sub % 32768;
        const float* base = (which == 0) ? Wq : (which == 1) ? Wk : Wv;
        src = base + (size_t)lyp * 65536 + (size_t)woff * 2;
    } else if (i < W1O) {
        src = Wm + (size_t)(i - WMO) * 2;
    } else if (i < W2O) {
        src = W1 + (size_t)(i - W1O) * 2;
    } else {
        src = W2 + (size_t)(i - W2O) * 2;
    }
    float2 v = *reinterpret_cast<const float2*>(src);
    uint32_t h, l;
    cvt_hl(v.x, v.y, h, l);
    wh[i] = h; wl[i] = l;
}

// ---------------- tensor-core bf16x3 GEMM (BN template, split-K via z) -------
template<int BN, int OUT>
__global__ __launch_bounds__(256)
void tc_gemm(const uint32_t* __restrict__ Ah, const uint32_t* __restrict__ Al,
             const uint32_t* __restrict__ A2h, const uint32_t* __restrict__ A2l,
             int nsplit,
             const uint32_t* __restrict__ Bh, const uint32_t* __restrict__ Bl,
             float* __restrict__ C, uint32_t* __restrict__ Oh, uint32_t* __restrict__ Ol,
             int M, int N, int K, int Krow)
{
    constexpr int WARPS_N = BN / 32;
    constexpr int WMX = 128 / (8 / WARPS_N);
    constexpr int MT = WMX / 16;
    constexpr int B_HI = BN * 48;
    constexpr int STAGE = 12288 + 2 * B_HI;

    extern __shared__ uint32_t smem[];
    const uint32_t sb0 = smem_u32(smem);

    const int m0 = blockIdx.y * 128;
    const int n0 = blockIdx.x * BN;
    const int kz = blockIdx.z;
    const int tid = threadIdx.x;
    const int wid = tid >> 5, lane = tid & 31;
    const int g = lane >> 2, tg = lane & 3;
    const int warp_m = wid / WARPS_N, warp_n = wid % WARPS_N;
    const int wm0 = warp_m * WMX, wn0 = warp_n * 32;
    const int Krow2 = Krow >> 1;
    const size_t kzoff = (size_t)kz * (K >> 1);

    const int rowa = tid >> 1, hw = (tid & 1) * 4;

    const int a_lrow = lane & 15;
    const int a_lcol = (lane >> 4) * 4;
    const int b_lrow = (lane & 7) + ((lane >> 4) << 3);
    const int b_lcol = ((lane >> 3) & 1) * 4;

    float acc[MT][4][4];
    #pragma unroll
    for (int i = 0; i < MT; i++)
        #pragma unroll
        for (int j = 0; j < 4; j++)
            #pragma unroll
            for (int r = 0; r < 4; r++) acc[i][j][r] = 0.f;

    const bool useA2 = (n0 >= nsplit);
    const uint32_t* Ab  = (useA2 ? A2h : Ah) + (size_t)(m0 + rowa) * Krow2 + hw + kzoff;
    const uint32_t* Alb = (useA2 ? A2l : Al) + (size_t)(m0 + rowa) * Krow2 + hw + kzoff;
    const uint32_t* Bb  = Bh + (size_t)(n0 + rowa) * Krow2 + hw + kzoff;
    const uint32_t* Blb = Bl + (size_t)(n0 + rowa) * Krow2 + hw + kzoff;
    C += (size_t)kz * M * N;

    const uint32_t dst_off = (uint32_t)(rowa * 12 + hw) * 4;
    const int nk = K >> 4;

    #define ISSUE(tile, stage) do {                                   \
        uint32_t sb = sb0 + (stage) * (uint32_t)STAGE;                \
        int ko = (tile) * 8;                                          \
        cp16(sb + dst_off,        Ab + ko);                           \
        cp16(sb + 6144 + dst_off, Alb + ko);                          \
        if (BN == 128 || tid < 128) {                                 \
            cp16(sb + 12288 + dst_off,        Bb + ko);               \
            cp16(sb + 12288 + B_HI + dst_off, Blb + ko);              \
        }                                                             \
    } while (0)

    #pragma unroll
    for (int s = 0; s < 3; s++) {
        if (s < nk) ISSUE(s, s);
        CP_COMMIT();
    }

    for (int kt = 0; kt < nk; kt++) {
        if (kt + 3 < nk) ISSUE(kt + 3, (kt + 3) & 3);
        CP_COMMIT();
        CP_WAIT(3);
        __syncthreads();

        const uint32_t sb = sb0 + (kt & 3) * (uint32_t)STAGE;
        uint32_t ah[MT][4], al[MT][4], bh2[4][2], bl2[4][2];
        #pragma unroll
        for (int mi = 0; mi < MT; mi++) {
            uint32_t woff = (uint32_t)((wm0 + mi*16 + a_lrow) * 12 + a_lcol) * 4;
            ldsm4(ah[mi], sb + woff);
            ldsm4(al[mi], sb + 6144 + woff);
        }
        #pragma unroll
        for (int p = 0; p < 2; p++) {
            uint32_t woff = (uint32_t)((wn0 + p*16 + b_lrow) * 12 + b_lcol) * 4;
            uint32_t r[4];
            ldsm4(r, sb + 12288 + woff);
            bh2[2*p][0] = r[0]; bh2[2*p][1] = r[1];
            bh2[2*p+1][0] = r[2]; bh2[2*p+1][1] = r[3];
            ldsm4(r, sb + 12288 + B_HI + woff);
            bl2[2*p][0] = r[0]; bl2[2*p][1] = r[1];
            bl2[2*p+1][0] = r[2]; bl2[2*p+1][1] = r[3];
        }
        #pragma unroll
        for (int mi = 0; mi < MT; mi++)
            #pragma unroll
            for (int ni = 0; ni < 4; ni++) {
                mma_bf16(acc[mi][ni], ah[mi], bh2[ni]);
                mma_bf16(acc[mi][ni], ah[mi], bl2[ni]);
                mma_bf16(acc[mi][ni], al[mi], bh2[ni]);
            }
        __syncthreads();
    }
    #undef ISSUE

    #pragma unroll
    for (int mi = 0; mi < MT; mi++) {
        #pragma unroll
        for (int ni = 0; ni < 4; ni++) {
            long long row0 = m0 + wm0 + mi * 16 + g;
            int col = n0 + wn0 + ni * 8 + tg * 2;
            if (OUT == 0) {
                *reinterpret_cast<float2*>(&C[row0 * N + col]) =
                    make_float2(acc[mi][ni][0], acc[mi][ni][1]);
                *reinterpret_cast<float2*>(&C[(row0 + 8) * N + col]) =
                    make_float2(acc[mi][ni][2], acc[mi][ni][3]);
            } else {
                float r[4];
                #pragma unroll
                for (int t = 0; t < 4; t++) {
                    float v = acc[mi][ni][t];
                    r[t] = 0.5f * v * (1.0f + erff(v * 0.70710678118654752f));
                }
                uint32_t h0, l0, h1, l1;
                cvt_hl(r[0], r[1], h0, l0);
                cvt_hl(r[2], r[3], h1, l1);
                size_t w0 = (size_t)(row0 * N + col) >> 1;
                size_t w1 = (size_t)((row0 + 8) * N + col) >> 1;
                Oh[w0] = h0; Ol[w0] = l0;
                Oh[w1] = h1; Ol[w1] = l1;
            }
        }
    }
}

// ---------------- fused flash attention (packed bf16 K/V, online softmax) ----
#define FA_SK 36
__global__ __launch_bounds__(256)
void k_flash(const float* __restrict__ qp,
             const uint32_t* __restrict__ kph, const uint32_t* __restrict__ kpl,
             const uint32_t* __restrict__ vph, const uint32_t* __restrict__ vpl,
             float* __restrict__ Og, int Tk)
{
    __shared__ uint32_t khw[64*FA_SK], klw[64*FA_SK];
    __shared__ uint32_t vhw[64*FA_SK], vlw[64*FA_SK];

    const int nh = blockIdx.y;
    const int q0 = blockIdx.x * 128;
    const int tid = threadIdx.x, wid = tid >> 5, lane = tid & 31;
    const int g = lane >> 2, tg = lane & 3;

    const float* Qb = qp + ((size_t)nh * LTOK + q0) * HD;
    const uint32_t* Kh = kph + (size_t)nh * Tk * 32;
    const uint32_t* Kl = kpl + (size_t)nh * Tk * 32;
    const uint32_t* Vh = vph + (size_t)nh * HD * (Tk >> 1);
    const uint32_t* Vl = vpl + (size_t)nh * HD * (Tk >> 1);

    const int row0 = wid * 16 + g;
    uint32_t qh[4][4], ql[4][4];
    #pragma unroll
    for (int kk = 0; kk < 4; kk++) {
        int col = kk * 16 + tg * 2;
        float2 q00 = *reinterpret_cast<const float2*>(&Qb[(size_t)row0 * HD + col]);
        float2 q01 = *reinterpret_cast<const float2*>(&Qb[(size_t)row0 * HD + col + 8]);
        float2 q10 = *reinterpret_cast<const float2*>(&Qb[(size_t)(row0 + 8) * HD + col]);
        float2 q11 = *reinterpret_cast<const float2*>(&Qb[(size_t)(row0 + 8) * HD + col + 8]);
        cvt_hl(q00.x * 0.125f, q00.y * 0.125f, qh[kk][0], ql[kk][0]);
        cvt_hl(q10.x * 0.125f, q10.y * 0.125f, qh[kk][1], ql[kk][1]);
        cvt_hl(q01.x * 0.125f, q01.y * 0.125f, qh[kk][2], ql[kk][2]);
        cvt_hl(q11.x * 0.125f, q11.y * 0.125f, qh[kk][3], ql[kk][3]);
    }

    float m0 = -1e30f, m1 = -1e30f, l0 = 0.f, l1 = 0.f;
    float oacc[8][4];
    #pragma unroll
    for (int i = 0; i < 8; i++)
        #pragma unroll
        for (int t = 0; t < 4; t++) oacc[i][t] = 0.f;

    const int r = tid >> 2, c2 = (tid & 3) * 8;
    uint4 kh0, kh1, kl0, kl1, vh0, vh1, vl0, vl1;
    {
        const uint32_t* sk = Kh + (size_t)r * 32 + c2;
        const uint32_t* sl = Kl + (size_t)r * 32 + c2;
        const uint32_t* tv = Vh + (size_t)r * (Tk >> 1) + c2;
        const uint32_t* tl = Vl + (size_t)r * (Tk >> 1) + c2;
        kh0 = *reinterpret_cast<const uint4*>(sk);
        kh1 = *reinterpret_cast<const uint4*>(sk + 4);
        kl0 = *reinterpret_cast<const uint4*>(sl);
        kl1 = *reinterpret_cast<const uint4*>(sl + 4);
        vh0 = *reinterpret_cast<const uint4*>(tv);
        vh1 = *reinterpret_cast<const uint4*>(tv + 4);
        vl0 = *reinterpret_cast<const uint4*>(tl);
        vl1 = *reinterpret_cast<const uint4*>(tl + 4);
    }

    for (int kv0 = 0; kv0 < Tk; kv0 += 64) {
        {
            int w = r * FA_SK + c2;
            *reinterpret_cast<uint4*>(&khw[w]) = kh0;
            *reinterpret_cast<uint4*>(&khw[w + 4]) = kh1;
            *reinterpret_cast<uint4*>(&klw[w]) = kl0;
            *reinterpret_cast<uint4*>(&klw[w + 4]) = kl1;
            *reinterpret_cast<uint4*>(&vhw[w]) = vh0;
            *reinterpret_cast<uint4*>(&vhw[w + 4]) = vh1;
            *reinterpret_cast<uint4*>(&vlw[w]) = vl0;
            *reinterpret_cast<uint4*>(&vlw[w + 4]) = vl1;
        }
        __syncthreads();

        if (kv0 + 64 < Tk) {
            const uint32_t* sk = Kh + (size_t)(kv0 + 64 + r) * 32 + c2;
            const uint32_t* sl = Kl + (size_t)(kv0 + 64 + r) * 32 + c2;
            const uint32_t* tv = Vh + (size_t)r * (Tk >> 1) + ((kv0 + 64) >> 1) + c2;
            const uint32_t* tl = Vl + (size_t)r * (Tk >> 1) + ((kv0 + 64) >> 1) + c2;
            kh0 = *reinterpret_cast<const uint4*>(sk);
            kh1 = *reinterpret_cast<const uint4*>(sk + 4);
            kl0 = *reinterpret_cast<const uint4*>(sl);
            kl1 = *reinterpret_cast<const uint4*>(sl + 4);
            vh0 = *reinterpret_cast<const uint4*>(tv);
            vh1 = *reinterpret_cast<const uint4*>(tv + 4);
            vl0 = *reinterpret_cast<const uint4*>(tl);
            vl1 = *reinterpret_cast<const uint4*>(tl + 4);
        }

        float sacc[8][4];
        #pragma unroll
        for (int i = 0; i < 8; i++)
            #pragma unroll
            for (int t = 0; t < 4; t++) sacc[i][t] = 0.f;
        #pragma unroll
        for (int kk = 0; kk < 4; kk++) {
            #pragma unroll
            for (int ni = 0; ni < 8; ni++) {
                uint32_t bh[2], bl[2];
                int off = (ni * 8 + g) * FA_SK + kk * 8 + tg;
                bh[0] = khw[off]; bh[1] = khw[off + 4];
                bl[0] = klw[off]; bl[1] = klw[off + 4];
                mma_bf16(sacc[ni], qh[kk], bh);
                mma_bf16(sacc[ni], qh[kk], bl);
                mma_bf16(sacc[ni], ql[kk], bh);
            }
        }

        float mx0 = -1e30f, mx1 = -1e30f;
        #pragma unroll
        for (int ni = 0; ni < 8; ni++) {
            mx0 = fmaxf(mx0, fmaxf(sacc[ni][0], sacc[ni][1]));
            mx1 = fmaxf(mx1, fmaxf(sacc[ni][2], sacc[ni][3]));
        }
        mx0 = fmaxf(mx0, __shfl_xor_sync(0xffffffff, mx0, 1));
        mx0 = fmaxf(mx0, __shfl_xor_sync(0xffffffff, mx0, 2));
        mx1 = fmaxf(mx1, __shfl_xor_sync(0xffffffff, mx1, 1));
        mx1 = fmaxf(mx1, __shfl_xor_sync(0xffffffff, mx1, 2));
        float nm0 = fmaxf(m0, mx0), nm1 = fmaxf(m1, mx1);
        float al0 = __expf(m0 - nm0), al1 = __expf(m1 - nm1);
        float rs0 = 0.f, rs1 = 0.f;
        #pragma unroll
        for (int ni = 0; ni < 8; ni++) {
            sacc[ni][0] = __expf(sacc[ni][0] - nm0);
            sacc[ni][1] = __expf(sacc[ni][1] - nm0);
            sacc[ni][2] = __expf(sacc[ni][2] - nm1);
            sacc[ni][3] = __expf(sacc[ni][3] - nm1);
            rs0 += sacc[ni][0] + sacc[ni][1];
            rs1 += sacc[ni][2] + sacc[ni][3];
        }
        rs0 += __shfl_xor_sync(0xffffffff, rs0, 1);
        rs0 += __shfl_xor_sync(0xffffffff, rs0, 2);
        rs1 += __shfl_xor_sync(0xffffffff, rs1, 1);
        rs1 += __shfl_xor_sync(0xffffffff, rs1, 2);
        l0 = l0 * al0 + rs0;  l1 = l1 * al1 + rs1;
        m0 = nm0;  m1 = nm1;
        #pragma unroll
        for (int nd = 0; nd < 8; nd++) {
            oacc[nd][0] *= al0; oacc[nd][1] *= al0;
            oacc[nd][2] *= al1; oacc[nd][3] *= al1;
        }

        #pragma unroll
        for (int kk = 0; kk < 4; kk++) {
            uint32_t ph[4], pl[4];
            cvt_hl(sacc[2*kk][0],   sacc[2*kk][1],   ph[0], pl[0]);
            cvt_hl(sacc[2*kk][2],   sacc[2*kk][3],   ph[1], pl[1]);
            cvt_hl(sacc[2*kk+1][0], sacc[2*kk+1][1], ph[2], pl[2]);
            cvt_hl(sacc[2*kk+1][2], sacc[2*kk+1][3], ph[3], pl[3]);
            #pragma unroll
            for (int nd = 0; nd < 8; nd++) {
                uint32_t vh[2], vl[2];
                int off = (nd * 8 + g) * FA_SK + kk * 8 + tg;
                vh[0] = vhw[off]; vh[1] = vhw[off + 4];
                vl[0] = vlw[off]; vl[1] = vlw[off + 4];
                mma_bf16(oacc[nd], ph, vh);
                mma_bf16(oacc[nd], ph, vl);
                mma_bf16(oacc[nd], pl, vh);
            }
        }
        __syncthreads();
    }

    float il0 = 1.0f / l0, il1 = 1.0f / l1;
    float* Ob = Og + ((size_t)nh * LTOK + q0) * HD;
    #pragma unroll
    for (int nd = 0; nd < 8; nd++) {
        int col = nd * 8 + tg * 2;
        *reinterpret_cast<float2*>(&Ob[(size_t)row0 * HD + col]) =
            make_float2(oacc[nd][0] * il0, oacc[nd][1] * il0);
        *reinterpret_cast<float2*>(&Ob[(size_t)(row0 + 8) * HD + col]) =
            make_float2(oacc[nd][2] * il1, oacc[nd][3] * il1);
    }
}

// ---------------- layout kernels ----------------
__global__ void k_build_x(const float* __restrict__ f, float* __restrict__ x,
                          uint32_t* __restrict__ xh, uint32_t* __restrict__ xl,
                          uint32_t* __restrict__ xph, uint32_t* __restrict__ xpl) {
    int idx = blockIdx.x * blockDim.x + threadIdx.x;
    if (idx >= XW) return;
    int c2 = idx & 127;
    int l  = (idx >> 7) & (LTOK-1);
    int n  = idx >> 17;
    int c  = c2 * 2;
    float a = f[((size_t)n*CC + c)*LTOK + l];
    float b = f[((size_t)n*CC + c + 1)*LTOK + l];
    reinterpret_cast<float2*>(x)[idx] = make_float2(a, b);
    uint32_t h, lw;
    cvt_hl(a, b, h, lw);
    xh[idx] = h; xl[idx] = lw;
    xph[idx] = h; xpl[idx] = lw;
}

__global__ void k_final(const float* __restrict__ x, float* __restrict__ o) {
    int idx = blockIdx.x * blockDim.x + threadIdx.x;
    if (idx >= ROWS_*CC) return;
    int l = idx & (LTOK-1);
    int c = (idx >> 10) & (CC-1);
    int n = idx >> 18;
    o[idx] = x[((size_t)n*LTOK + l)*CC + c];
}

// ---------------- PRoPE matrix build ----------------
__device__ __forceinline__ void prope_forward(const float* vm, const float* Kc,
                                              float u, float vyy, float* M) {
    float fx = Kc[0] * (1.0f/128.0f), fy = Kc[4] * (1.0f/128.0f);
    float cx = Kc[2] * (1.0f/128.0f), cy = Kc[5] * (1.0f/128.0f);
    float a = cx - u, b = cy - vyy;
    #pragma unroll
    for (int c = 0; c < 4; c++) {
        M[0*4+c] = fx*vm[0*4+c] + a*vm[2*4+c];
        M[1*4+c] = fy*vm[1*4+c] + b*vm[2*4+c];
        M[2*4+c] = vm[2*4+c];
        M[3*4+c] = vm[3*4+c];
    }
}

__global__ void k_prope_q(const float* __restrict__ vms, const float* __restrict__ Ks,
                          float* __restrict__ Mq, float* __restrict__ Mqi) {
    int idx = blockIdx.x * blockDim.x + threadIdx.x;
    if (idx >= NVB*LTOK) return;
    int n = idx >> 10, t = idx & (LTOK-1);
    int px = t & 31, py = t >> 5;
    float u  = (px + 0.5f) * (1.0f/32.0f);
    float vy = (py + 0.5f) * (1.0f/32.0f);
    const float* vm = vms + n*16;
    const float* Kc = Ks + n*9;
    float M[16];
    prope_forward(vm, Kc, u, vy, M);
    #pragma unroll
    for (int i = 0; i < 16; i++) Mq[idx*16+i] = M[i];

    float r00=vm[0],r01=vm[1],r02=vm[2],  t0=vm[3];
    float r10=vm[4],r11=vm[5],r12=vm[6],  t1=vm[7];
    float r20=vm[8],r21=vm[9],r22=vm[10], t2=vm[11];
    float det = r00*(r11*r22-r12*r21) - r01*(r10*r22-r12*r20) + r02*(r10*r21-r11*r20);
    float id = 1.0f/det;
    float Ri[9];
    Ri[0]=(r11*r22-r12*r21)*id; Ri[1]=(r02*r21-r01*r22)*id; Ri[2]=(r01*r12-r02*r11)*id;
    Ri[3]=(r12*r20-r10*r22)*id; Ri[4]=(r00*r22-r02*r20)*id; Ri[5]=(r02*r10-r00*r12)*id;
    Ri[6]=(r10*r21-r11*r20)*id; Ri[7]=(r01*r20-r00*r21)*id; Ri[8]=(r00*r11-r01*r10)*id;
    float ti0 = -(Ri[0]*t0 + Ri[1]*t1 + Ri[2]*t2);
    float ti1 = -(Ri[3]*t0 + Ri[4]*t1 + Ri[5]*t2);
    float ti2 = -(Ri[6]*t0 + Ri[7]*t1 + Ri[8]*t2);
    float fx = Kc[0]*(1.0f/128.0f), fy = Kc[4]*(1.0f/128.0f);
    float cx = Kc[2]*(1.0f/128.0f), cy = Kc[5]*(1.0f/128.0f);
    float a = cx - u, b = cy - vy;
    float ifx = 1.0f/fx, ify = 1.0f/fy;
    float Mi[16];
    float tv[3] = {ti0, ti1, ti2};
    #pragma unroll
    for (int i = 0; i < 3; i++) {
        Mi[i*4+0] = Ri[i*3+0]*ifx;
        Mi[i*4+1] = Ri[i*3+1]*ify;
        Mi[i*4+2] = -Ri[i*3+0]*a*ifx - Ri[i*3+1]*b*ify + Ri[i*3+2];
        Mi[i*4+3] = tv[i];
    }
    Mi[12]=0.f; Mi[13]=0.f; Mi[14]=0.f; Mi[15]=1.f;
    #pragma unroll
    for (int i = 0; i < 16; i++) Mqi[idx*16+i] = Mi[i];
}

__global__ void k_prope_kv(const float* __restrict__ vms, const float* __restrict__ Ks,
                           float* __restrict__ Mkv) {
    int idx = blockIdx.x * blockDim.x + threadIdx.x;
    if (idx >= NVB*TKX) return;
    int n = idx >> 11, tt = idx & (TKX-1);
    int m = tt >> 10, l = tt & (LTOK-1);
    int vvi = n >> 1, b = n & 1;
    int j = m + (m >= vvi ? 1 : 0);
    int cam = j*BB + b;
    int px = l & 31, py = l >> 5;
    float u  = (px + 0.5f)*(1.0f/32.0f);
    float vy = (py + 0.5f)*(1.0f/32.0f);
    float M[16];
    prope_forward(vms + cam*16, Ks + cam*9, u, vy, M);
    #pragma unroll
    for (int i = 0; i < 16; i++) Mkv[idx*16+i] = M[i];
}

// ---------------- fused per-token applies (packed K/V outputs) ---------------
__global__ void k_apply_all(const float* __restrict__ qkv, int stride,
                            const float* __restrict__ Mqi, const float* __restrict__ Mats,
                            float* __restrict__ qp,
                            uint32_t* __restrict__ kph, uint32_t* __restrict__ kpl,
                            uint32_t* __restrict__ vph, uint32_t* __restrict__ vpl,
                            int Tk, int gather, int nkv)
{
    int idx = blockIdx.x * blockDim.x + threadIdx.x;
    if (idx < NAPP) {
        int g = idx & 15, h = (idx >> 4) & 3, t = (idx >> 6) & (LTOK-1), n = idx >> 16;
        const float* M = Mqi + ((size_t)(n*LTOK + t))*16;
        const float* s = qkv + ((size_t)(n*LTOK + t))*stride + h*HD + g*4;
        float x0=s[0], x1=s[1], x2=s[2], x3=s[3];
        float* d = qp + (((size_t)(n*NH + h))*LTOK + t)*HD + g*4;
        #pragma unroll
        for (int i = 0; i < 4; i++)
            d[i] = M[0*4+i]*x0 + M[1*4+i]*x1 + M[2*4+i]*x2 + M[3*4+i]*x3;
    } else if (idx < NAPP + nkv) {
        int i2 = idx - NAPP;
        int g = i2 & 15, h = (i2 >> 4) & 3;
        int tt = (i2 >> 6) % Tk, n = (i2 >> 6) / Tk;
        size_t srcRow;
        if (gather) {
            int m = tt >> 10, l = tt & (LTOK-1);
            int vvi = n >> 1, b = n & 1;
            int j = m + (m >= vvi ? 1 : 0);
            srcRow = (size_t)(j*BB + b)*LTOK + l;
        } else {
            srcRow = (size_t)n*LTOK + tt;
        }
        const float* M = Mats + ((size_t)n*Tk + tt)*16;
        const float* s = qkv + srcRow*stride + 256 + h*HD + g*4;
        float x0=s[0], x1=s[1], x2=s[2], x3=s[3];
        float d[4];
        #pragma unroll
        for (int i = 0; i < 4; i++)
            d[i] = M[i*4+0]*x0 + M[i*4+1]*x1 + M[i*4+2]*x2 + M[i*4+3]*x3;
        size_t wb = (((size_t)(n*NH + h))*Tk + tt)*32 + g*2;
        uint32_t h0, l0, h1, l1;
        cvt_hl(d[0], d[1], h0, l0);
        cvt_hl(d[2], d[3], h1, l1);
        kph[wb] = h0;   kpl[wb] = l0;
        kph[wb+1] = h1; kpl[wb+1] = l1;
    } else if (idx < NAPP + 2*nkv) {
        int i2 = idx - NAPP - nkv;
        int tt = i2 % Tk;
        int rest = i2 / Tk;
        int g = rest & 15, h = (rest >> 4) & 3, n = rest >> 6;
        size_t srcRow;
        if (gather) {
            int m = tt >> 10, l = tt & (LTOK-1);
            int vvi = n >> 1, b = n & 1;
            int j = m + (m >= vvi ? 1 : 0);
            srcRow = (size_t)(j*BB + b)*LTOK + l;
        } else {
            srcRow = (size_t)n*LTOK + tt;
        }
        const float* M = Mats + ((size_t)n*Tk + tt)*16;
        const float* s = qkv + srcRow*stride + 512 + h*HD + g*4;
        float x0=s[0], x1=s[1], x2=s[2], x3=s[3];
        #pragma unroll
        for (int i = 0; i < 4; i++) {
            float v = M[i*4+0]*x0 + M[i*4+1]*x1 + M[i*4+2]*x2 + M[i*4+3]*x3;
            float vn = __shfl_down_sync(0xffffffff, v, 1);
            if ((tt & 1) == 0) {
                uint32_t hh2, ll2;
                cvt_hl(v, vn, hh2, ll2);
                size_t wb = ((size_t)(n*NH + h)*HD + g*4 + i)*(Tk >> 1) + (tt >> 1);
                vph[wb] = hh2; vpl[wb] = ll2;
            }
        }
    }
}

__global__ void k_apply_out(const float* __restrict__ O, const float* __restrict__ Mi,
                            uint32_t* __restrict__ omh, uint32_t* __restrict__ oml) {
    int idx = blockIdx.x * blockDim.x + threadIdx.x;
    if (idx >= NAPP) return;
    int g = idx & 15, h = (idx >> 4) & 3, t = (idx >> 6) & (LTOK-1), n = idx >> 16;
    const float* M = Mi + ((size_t)(n*LTOK + t))*16;
    const float* s = O + (((size_t)(n*NH + h))*LTOK + t)*HD + g*4;
    float x0=s[0], x1=s[1], x2=s[2], x3=s[3];
    float d[4];
    #pragma unroll
    for (int i = 0; i < 4; i++)
        d[i] = M[i*4+0]*x0 + M[i*4+1]*x1 + M[i*4+2]*x2 + M[i*4+3]*x3;
    size_t w = (((size_t)(n*LTOK + t))*CC + h*HD + g*4) >> 1;
    uint32_t h0, l0, h1, l1;
    cvt_hl(d[0], d[1], h0, l0);
    cvt_hl(d[2], d[3], h1, l1);
    omh[w] = h0;   oml[w] = l0;
    omh[w+1] = h1; oml[w+1] = l1;
}

// ---------------- layernorm: sums nparts partials, optional bf16 + cat writes --
__global__ void k_ln(float* __restrict__ dst, const float* __restrict__ parts, int nparts,
                     const float* __restrict__ w, const float* __restrict__ b, int add,
                     uint32_t* __restrict__ oh, uint32_t* __restrict__ ol,
                     uint32_t* __restrict__ oh2, uint32_t* __restrict__ ol2,
                     uint32_t* __restrict__ ch, uint32_t* __restrict__ cl, int catHalf) {
    __shared__ float red[256];
    int row = blockIdx.x, tid = threadIdx.x;
    float v = parts[(size_t)row*CC + tid];
    for (int p = 1; p < nparts; p++)
        v += parts[(size_t)p*ROWS_*CC + (size_t)row*CC + tid];
    red[tid] = v; __syncthreads();
    for (int s = 128; s > 0; s >>= 1) { if (tid < s) red[tid] += red[tid+s]; __syncthreads(); }
    float mu = red[0] * (1.0f/CC); __syncthreads();
    float d = v - mu;
    red[tid] = d * d; __syncthreads();
    for (int s = 128; s > 0; s >>= 1) { if (tid < s) red[tid] += red[tid+s]; __syncthreads(); }
    float var = red[0] * (1.0f/CC);
    float o = d * rsqrtf(var + 1e-5f) * w[tid] + b[tid];
    float fin;
    if (add) { fin = dst[(size_t)row*CC + tid] + o; dst[(size_t)row*CC + tid] = fin; }
    else     { fin = o; dst[(size_t)row*CC + tid] = fin; }
    if (oh || ch) {
        __syncthreads();
        red[tid] = fin;
        __syncthreads();
        if (tid < 128) {
            uint32_t h, l;
            cvt_hl(red[2*tid], red[2*tid+1], h, l);
            if (oh) {
                oh[(size_t)row*(CC/2) + tid] = h;
                ol[(size_t)row*(CC/2) + tid] = l;
                if (oh2) {
                    oh2[(size_t)row*(CC/2) + tid] = h;
                    ol2[(size_t)row*(CC/2) + tid] = l;
                }
            }
            if (ch) {
                size_t cw = (size_t)row*(FFNI/2) + catHalf*128 + tid;
                ch[cw] = h; cl[cw] = l;
            }
        }
    }
}

// ---------------- host driver ----------------
static const int GSMEM128 = 98304;
static const int GSMEM64  = 73728;

static void gemm128(const uint32_t* Ah, const uint32_t* Al,
                    const uint32_t* A2h, const uint32_t* A2l, int nsplit,
                    const uint32_t* Bh, const uint32_t* Bl,
                    float* C, int M, int N, int K) {
    dim3 g(N/128, M/128, 1);
    tc_gemm<128,0><<<g, 256, GSMEM128>>>(Ah, Al, A2h, A2l, nsplit, Bh, Bl,
                                         C, nullptr, nullptr, M, N, K, K);
}
// split-K xNZ: writes partials to C[z*M*N]
static void gemm64s(const uint32_t* Ah, const uint32_t* Al,
                    const uint32_t* Bh, const uint32_t* Bl,
                    float* C, int M, int N, int Ktot, int nz) {
    dim3 g(N/64, M/128, nz);
    tc_gemm<64,0><<<g, 256, GSMEM64>>>(Ah, Al, Ah, Al, 1<<30, Bh, Bl,
                                       C, nullptr, nullptr, M, N, Ktot/nz, Ktot);
}
static void gemm_gelu_hl(const uint32_t* Ah, const uint32_t* Al,
                         const uint32_t* Bh, const uint32_t* Bl,
                         uint32_t* Oh, uint32_t* Ol, int M, int N, int K) {
    dim3 g(N/128, M/128, 1);
    tc_gemm<128,1><<<g, 256, GSMEM128>>>(Ah, Al, Ah, Al, 1<<30, Bh, Bl,
                                         nullptr, Oh, Ol, M, N, K, K);
}

extern "C" void kernel_launch(void* const* d_in, const int* in_sizes, int n_in,
                              void* d_out, int out_size) {
    const float* feats = (const float*)d_in[0];
    const float* vms   = (const float*)d_in[1];
    const float* Ks    = (const float*)d_in[2];
    const float* Wq    = (const float*)d_in[3];
    const float* Wk    = (const float*)d_in[4];
    const float* Wv    = (const float*)d_in[5];
    const float* Wm    = (const float*)d_in[6];
    const float* n1w   = (const float*)d_in[7];
    const float* n1b   = (const float*)d_in[8];
    const float* W1    = (const float*)d_in[9];
    const float* W2    = (const float*)d_in[10];
    const float* n2w   = (const float*)d_in[11];
    const float* n2b   = (const float*)d_in[12];

    cudaFuncSetAttribute(tc_gemm<128,0>, cudaFuncAttributeMaxDynamicSharedMemorySize, GSMEM128);
    cudaFuncSetAttribute(tc_gemm<128,1>, cudaFuncAttributeMaxDynamicSharedMemorySize, GSMEM128);
    cudaFuncSetAttribute(tc_gemm<64,0>,  cudaFuncAttributeMaxDynamicSharedMemorySize, GSMEM64);

    void* p;
    float *x,*qkv,*qp,*O,*msg,*msg2,*h22,*Mq,*Mqi,*Mkv;
    uint32_t *kph,*kpl,*vph,*vpl;
    uint32_t *xh,*xl,*xpreh,*xprel,*omh,*oml,*cath,*catl,*hh,*hl,*wh,*wl;
    cudaGetSymbolAddress(&p, g_x);    x   = (float*)p;
    cudaGetSymbolAddress(&p, g_qkv);  qkv = (float*)p;
    cudaGetSymbolAddress(&p, g_qp);   qp  = (float*)p;
    cudaGetSymbolAddress(&p, g_kph);  kph = (uint32_t*)p;
    cudaGetSymbolAddress(&p, g_kpl);  kpl = (uint32_t*)p;
    cudaGetSymbolAddress(&p, g_vph);  vph = (uint32_t*)p;
    cudaGetSymbolAddress(&p, g_vpl);  vpl = (uint32_t*)p;
    cudaGetSymbolAddress(&p, g_O);    O   = (float*)p;
    cudaGetSymbolAddress(&p, g_msg);  msg = (float*)p;
    cudaGetSymbolAddress(&p, g_msg2); msg2= (float*)p;
    cudaGetSymbolAddress(&p, g_h22);  h22 = (float*)p;
    cudaGetSymbolAddress(&p, g_Mq);   Mq  = (float*)p;
    cudaGetSymbolAddress(&p, g_Mqi);  Mqi = (float*)p;
    cudaGetSymbolAddress(&p, g_Mkv);  Mkv = (float*)p;
    cudaGetSymbolAddress(&p, g_xh);    xh    = (uint32_t*)p;
    cudaGetSymbolAddress(&p, g_xl);    xl    = (uint32_t*)p;
    cudaGetSymbolAddress(&p, g_xpreh); xpreh = (uint32_t*)p;
    cudaGetSymbolAddress(&p, g_xprel); xprel = (uint32_t*)p;
    cudaGetSymbolAddress(&p, g_omh);   omh   = (uint32_t*)p;
    cudaGetSymbolAddress(&p, g_oml);   oml   = (uint32_t*)p;
    cudaGetSymbolAddress(&p, g_cath);  cath  = (uint32_t*)p;
    cudaGetSymbolAddress(&p, g_catl);  catl  = (uint32_t*)p;
    cudaGetSymbolAddress(&p, g_hh);    hh    = (uint32_t*)p;
    cudaGetSymbolAddress(&p, g_hl);    hl    = (uint32_t*)p;
    cudaGetSymbolAddress(&p, g_wh);    wh    = (uint32_t*)p;
    cudaGetSymbolAddress(&p, g_wl);    wl    = (uint32_t*)p;

    const int ROWS = ROWS_;
    const int NEL  = ROWS * CC;
    const int NKV_SELF  = NAPP;
    const int NKV_CROSS = NVB*TKX*NH*16;

    k_cvt_all<<<WTOT/256, 256>>>(Wq, Wk, Wv, Wm, W1, W2, wh, wl);
    k_build_x<<<(XW+255)/256, 256>>>(feats, x, xh, xl, xpreh, xprel);
    k_prope_q<<<(ROWS+255)/256, 256>>>(vms, Ks, Mq, Mqi);
    k_prope_kv<<<(NVB*TKX+255)/256, 256>>>(vms, Ks, Mkv);

    for (int ly = 0; ly < 2; ly++) {
        // ---------- self attention ----------
        gemm128(xh, xl, xh, xl, 1<<30,
                wh + WQKV0 + (ly*2+0)*98304, wl + WQKV0 + (ly*2+0)*98304,
                qkv, ROWS, 768, CC);
        k_apply_all<<<(NAPP + 2*NKV_SELF)/256, 256>>>(
            qkv, 768, Mqi, Mq, qp, kph, kpl, vph, vpl, LTOK, 0, NKV_SELF);
        k_flash<<<dim3(LTOK/128, NVB*NH), 256>>>(qp, kph, kpl, vph, vpl, O, LTOK);
        k_apply_out<<<NAPP/256, 256>>>(O, Mqi, omh, oml);
        gemm64s(omh, oml, wh + WMO + (ly*2+0)*32768, wl + WMO + (ly*2+0)*32768,
                msg2, ROWS, CC, CC, 2);
        // writes x, xh/xl, and cat[:,0:256)
        k_ln<<<ROWS, 256>>>(x, msg2, 2, n1w + (ly*2+0)*CC, n1b + (ly*2+0)*CC, 1,
                            xh, xl, nullptr, nullptr, cath, catl, 0);

        // ---------- cross attention ----------
        gemm128(xh, xl, xpreh, xprel, 256,
                wh + WQKV0 + (ly*2+1)*98304, wl + WQKV0 + (ly*2+1)*98304,
                qkv, ROWS, 768, CC);
        k_apply_all<<<(NAPP + 2*NKV_CROSS)/256, 256>>>(
            qkv, 768, Mqi, Mkv, qp, kph, kpl, vph, vpl, TKX, 1, NKV_CROSS);
        k_flash<<<dim3(LTOK/128, NVB*NH), 256>>>(qp, kph, kpl, vph, vpl, O, TKX);
        k_apply_out<<<NAPP/256, 256>>>(O, Mqi, omh, oml);
        gemm64s(omh, oml, wh + WMO + (ly*2+1)*32768, wl + WMO + (ly*2+1)*32768,
                msg2, ROWS, CC, CC, 2);
        // writes msg and cat[:,256:512)
        k_ln<<<ROWS, 256>>>(msg, msg2, 2, n1w + (ly*2+1)*CC, n1b + (ly*2+1)*CC, 0,
                            nullptr, nullptr, nullptr, nullptr, cath, catl, 1);

        // ---------- FFN ----------
        gemm_gelu_hl(cath, catl,
                     wh + W1O + (size_t)ly*524288, wl + W1O + (size_t)ly*524288,
                     hh, hl, ROWS, FFNH, FFNI);
        gemm64s(hh, hl, wh + W2O + (size_t)ly*262144, wl + W2O + (size_t)ly*262144,
                h22, ROWS, CC, FFNH, 4);
        k_ln<<<ROWS, 256>>>(x, h22, 4, n2w + ly*CC, n2b + ly*CC, 1,
                            xh, xl, xpreh, xprel, nullptr, nullptr, 0);
    }

    k_final<<<(NEL+255)/256, 256>>>(x, (float*)d_out);
}